// round 2
// baseline (speedup 1.0000x reference)
#include <cuda_runtime.h>
#include <math.h>

#define HH 256
#define WW 256
#define NPIX 65536          // H*W
#define CIN 512
#define HALF 256
#define PSZ 32
#define NH 8
#define NUM 64              // patches
#define EPS 1e-5f

// ---------------- static scratch (no allocations allowed) ----------------
__device__ float g_q[HALF * NPIX];            // q projection, image layout [c][pix]
__device__ float g_pf[HALF * NPIX];           // reused: kf -> vf -> attention output image
__device__ float g_attn[(size_t)NUM * 1024 * 64];   // attn per patch [b][n][m]
__device__ float g_kp[HALF * NUM];            // pooled k, [c][patch]
__device__ float g_vp[NUM * HALF];            // pooled v, [patch][c]

// ---------------- fused 1x1conv + BN + ReLU GEMM ----------------
// C[o][pix] = relu((sum_c W[o][c]*X[c][pix] - m[o])*g[o]/sqrt(v[o]+eps) + b[o]) * postscale (+ resid)
// 128x128 tile, BK=8, 256 threads, 8x8 per thread.
template <int KDIM>
__global__ void __launch_bounds__(256)
sgemm_bn_relu(const float* __restrict__ Wt, const float* __restrict__ X,
              const float* __restrict__ gg, const float* __restrict__ bb,
              const float* __restrict__ mm, const float* __restrict__ vv,
              float* __restrict__ C, float postscale,
              const float* __restrict__ resid)
{
    __shared__ float As[8][128];
    __shared__ float Bs[8][128];
    const int bn = blockIdx.x;            // pixel tile
    const int bm = blockIdx.y;            // out-channel tile
    const int tid = threadIdx.x;
    const int tx = tid & 15;
    const int ty = tid >> 4;

    float acc[8][8];
    #pragma unroll
    for (int i = 0; i < 8; i++)
        #pragma unroll
        for (int j = 0; j < 8; j++) acc[i][j] = 0.f;

    const int arow = tid >> 1;
    const int acol = (tid & 1) * 4;
    const int brow = tid >> 5;
    const int bcol = (tid & 31) * 4;
    const float* Ab = Wt + (size_t)(bm * 128 + arow) * KDIM + acol;
    const float* Bb = X + (size_t)brow * NPIX + bn * 128 + bcol;

    for (int kt = 0; kt < KDIM / 8; kt++) {
        float4 a4 = *(const float4*)(Ab + kt * 8);
        As[acol + 0][arow] = a4.x;
        As[acol + 1][arow] = a4.y;
        As[acol + 2][arow] = a4.z;
        As[acol + 3][arow] = a4.w;
        float4 b4 = *(const float4*)(Bb + (size_t)kt * 8 * NPIX);
        *(float4*)&Bs[brow][bcol] = b4;
        __syncthreads();
        #pragma unroll
        for (int k = 0; k < 8; k++) {
            float a[8], bvv[8];
            *(float4*)(a)     = *(const float4*)&As[k][ty * 8];
            *(float4*)(a + 4) = *(const float4*)&As[k][ty * 8 + 4];
            *(float4*)(bvv)     = *(const float4*)&Bs[k][tx * 8];
            *(float4*)(bvv + 4) = *(const float4*)&Bs[k][tx * 8 + 4];
            #pragma unroll
            for (int i = 0; i < 8; i++)
                #pragma unroll
                for (int j = 0; j < 8; j++) acc[i][j] += a[i] * bvv[j];
        }
        __syncthreads();
    }

    #pragma unroll
    for (int i = 0; i < 8; i++) {
        const int o = bm * 128 + ty * 8 + i;
        const float sc = gg[o] * rsqrtf(vv[o] + EPS);
        const float mo = mm[o];
        const float bo = bb[o];
        const size_t rowoff = (size_t)o * NPIX + bn * 128 + tx * 8;
        float out[8];
        #pragma unroll
        for (int j = 0; j < 8; j++) {
            float y = (acc[i][j] - mo) * sc + bo;
            y = fmaxf(y, 0.f) * postscale;
            out[j] = y;
        }
        if (resid) {
            #pragma unroll
            for (int j = 0; j < 8; j++) out[j] += resid[rowoff + j];
        }
        *(float4*)(C + rowoff)     = *(float4*)(out);
        *(float4*)(C + rowoff + 4) = *(float4*)(out + 4);
    }
}

// ---------------- 32x32 patch average pooling ----------------
// src: [HALF][NPIX] image.  dst: cmajor? [c][patch] : [patch][c]
__global__ void pool_kernel(const float* __restrict__ src, float* __restrict__ dst, int cmajor)
{
    const int c = blockIdx.x;        // 0..255
    const int ph = blockIdx.y;       // 0..7
    const int w = threadIdx.x >> 5;  // warp = pw, 0..7
    const int lane = threadIdx.x & 31;
    const float* base = src + (size_t)c * NPIX + (ph * 32) * WW + w * 32 + lane;
    float s = 0.f;
    #pragma unroll
    for (int r = 0; r < 32; r++) s += base[r * WW];
    #pragma unroll
    for (int o = 16; o > 0; o >>= 1) s += __shfl_xor_sync(0xffffffffu, s, o);
    if (lane == 0) {
        const float mean = s * (1.f / 1024.f);
        const int patch = ph * 8 + w;
        if (cmajor) dst[c * NUM + patch] = mean;
        else        dst[patch * HALF + c] = mean;
    }
}

// ---------------- attn = q_b^T (1024x256) x kp (256x64), per patch ----------------
__global__ void __launch_bounds__(256)
attn_kernel(const float* __restrict__ q, const float* __restrict__ kp, float* __restrict__ attn)
{
    __shared__ float Qs[8][128];
    __shared__ float Ks[8][64];
    const int blk = blockIdx.x;   // 0..7 n-row block
    const int b = blockIdx.y;     // patch 0..63
    const int ph = b >> 3, pw = b & 7;
    const int tid = threadIdx.x;
    const int tx = tid & 15;      // m cols, 4 each
    const int ty = tid >> 4;      // n rows, 8 each

    float acc[8][4];
    #pragma unroll
    for (int i = 0; i < 8; i++)
        #pragma unroll
        for (int j = 0; j < 4; j++) acc[i][j] = 0.f;

    const int pixbase = ph * 32 * WW + pw * 32;
    const int n_l = tid & 127;
    const int c0 = tid >> 7;      // 0 or 1
    const int n = blk * 128 + n_l;
    const int pix = pixbase + (n >> 5) * WW + (n & 31);

    for (int kt = 0; kt < HALF / 8; kt++) {
        #pragma unroll
        for (int i = 0; i < 4; i++) {
            const int cl = c0 + i * 2;
            Qs[cl][n_l] = q[(size_t)(kt * 8 + cl) * NPIX + pix];
        }
        #pragma unroll
        for (int i = 0; i < 2; i++) {
            const int e = tid + i * 256;
            Ks[e >> 6][e & 63] = kp[(kt * 8 + (e >> 6)) * NUM + (e & 63)];
        }
        __syncthreads();
        #pragma unroll
        for (int k = 0; k < 8; k++) {
            float a[8], bm4[4];
            *(float4*)(a)     = *(const float4*)&Qs[k][ty * 8];
            *(float4*)(a + 4) = *(const float4*)&Qs[k][ty * 8 + 4];
            *(float4*)(bm4)   = *(const float4*)&Ks[k][tx * 4];
            #pragma unroll
            for (int i = 0; i < 8; i++)
                #pragma unroll
                for (int j = 0; j < 4; j++) acc[i][j] += a[i] * bm4[j];
        }
        __syncthreads();
    }
    #pragma unroll
    for (int i = 0; i < 8; i++) {
        const size_t off = ((size_t)b * 1024 + blk * 128 + ty * 8 + i) * 64 + tx * 4;
        *(float4*)&attn[off] = *(float4*)acc[i];
    }
}

// ---------------- flash: corr softmax + corr_map + final softmax + out GEMM ----------------
// Per patch b: A = attn[b] (1024x64).  corr_map = softmax(A A^T) A.
// final = softmax(A + corr_map, over m).  out = final x vp (64x256).
// Writes out into image layout mid[c][pix] (patch-recover fused).
__global__ void __launch_bounds__(128)
flash_kernel(const float* __restrict__ attn, const float* __restrict__ vp, float* __restrict__ mid)
{
    extern __shared__ float sm[];
    float* vps = sm;                        // 64*256  = 16384 floats
    float* Kt  = sm + 64 * 256;             // 64*64   = 4096 floats
    float* stage = Kt + 64 * 64;            // 128*65  = 8320 floats

    const int blk = blockIdx.x;             // 0..7  (128 rows each)
    const int b = blockIdx.y;               // patch
    const int tid = threadIdx.x;            // 0..127, one n-row each

    // load vp (used only at the end, loaded once)
    for (int i = tid * 4; i < 64 * 256; i += 128 * 4)
        *(float4*)&vps[i] = *(const float4*)&vp[i];

    // this thread's attn row (Q role)
    const float* arow = attn + ((size_t)b * 1024 + blk * 128 + tid) * 64;
    float Q[64];
    #pragma unroll
    for (int i = 0; i < 64; i += 4) *(float4*)&Q[i] = *(const float4*)&arow[i];

    float O[64];
    #pragma unroll
    for (int i = 0; i < 64; i++) O[i] = 0.f;
    float mi = -1e30f, l = 0.f;

    for (int t = 0; t < 16; t++) {          // 16 tiles of 64 K/V rows
        __syncthreads();
        const float* kb = attn + ((size_t)b * 1024 + t * 64) * 64;
        for (int i = tid * 4; i < 64 * 64; i += 128 * 4)
            *(float4*)&Kt[i] = *(const float4*)&kb[i];
        __syncthreads();

        for (int st = 0; st < 8; st++) {    // subtiles of 8 p-rows (keeps S in regs)
            const float* kp_ = &Kt[st * 8 * 64];
            float S[8];
            float mt = -1e30f;
            #pragma unroll
            for (int p = 0; p < 8; p++) {
                float s = 0.f;
                #pragma unroll
                for (int c = 0; c < 64; c += 4) {
                    float4 kv = *(const float4*)&kp_[p * 64 + c];
                    s += Q[c] * kv.x + Q[c + 1] * kv.y + Q[c + 2] * kv.z + Q[c + 3] * kv.w;
                }
                S[p] = s;
                mt = fmaxf(mt, s);
            }
            const float mnew = fmaxf(mi, mt);
            const float corrf = __expf(mi - mnew);
            l *= corrf;
            #pragma unroll
            for (int c = 0; c < 64; c++) O[c] *= corrf;
            #pragma unroll
            for (int p = 0; p < 8; p++) {
                const float wv = __expf(S[p] - mnew);
                l += wv;
                #pragma unroll
                for (int c = 0; c < 64; c += 4) {
                    float4 kv = *(const float4*)&kp_[p * 64 + c];
                    O[c]     += wv * kv.x;
                    O[c + 1] += wv * kv.y;
                    O[c + 2] += wv * kv.z;
                    O[c + 3] += wv * kv.w;
                }
            }
            mi = mnew;
        }
    }

    // final row: softmax(Q + O/l) over 64
    const float invl = 1.f / l;
    float fv[64];
    float fm = -1e30f;
    #pragma unroll
    for (int j = 0; j < 64; j++) {
        fv[j] = Q[j] + O[j] * invl;
        fm = fmaxf(fm, fv[j]);
    }
    float fs = 0.f;
    #pragma unroll
    for (int j = 0; j < 64; j++) {
        fv[j] = __expf(fv[j] - fm);
        fs += fv[j];
    }
    const float invs = 1.f / fs;
    #pragma unroll
    for (int j = 0; j < 64; j++) fv[j] *= invs;

    // out row = fv (64) x vps (64x256), staged through smem for coalesced writes
    const int ph = b >> 3, pw = b & 7;
    const int pixbase = ph * 32 * WW + pw * 32;
    for (int ch = 0; ch < 4; ch++) {        // 4 chunks of 64 channels
        float acc[64];
        #pragma unroll
        for (int c = 0; c < 64; c++) acc[c] = 0.f;
        #pragma unroll 8
        for (int m = 0; m < 64; m++) {
            const float wm = fv[m];
            #pragma unroll
            for (int c = 0; c < 64; c += 4) {
                float4 v4 = *(const float4*)&vps[m * 256 + ch * 64 + c];
                acc[c]     += wm * v4.x;
                acc[c + 1] += wm * v4.y;
                acc[c + 2] += wm * v4.z;
                acc[c + 3] += wm * v4.w;
            }
        }
        __syncthreads();
        #pragma unroll
        for (int c = 0; c < 64; c++) stage[tid * 65 + c] = acc[c];
        __syncthreads();
        for (int i = tid; i < 128 * 64; i += 128) {
            const int cl = i >> 7;          // 0..63 (== iteration index)
            const int nl = i & 127;         // == tid
            const int n = blk * 128 + nl;
            const int pix = pixbase + (n >> 5) * WW + (n & 31);
            mid[(size_t)(ch * 64 + cl) * NPIX + pix] = stage[nl * 65 + cl];
        }
    }
}

// ---------------- launch ----------------
extern "C" void kernel_launch(void* const* d_in, const int* in_sizes, int n_in,
                              void* d_out, int out_size)
{
    const float* x   = (const float*)d_in[0];
    const float* q_w = (const float*)d_in[1];
    const float* q_g = (const float*)d_in[2];
    const float* q_b = (const float*)d_in[3];
    const float* q_m = (const float*)d_in[4];
    const float* q_v = (const float*)d_in[5];
    const float* k_w = (const float*)d_in[6];
    const float* k_g = (const float*)d_in[7];
    const float* k_b = (const float*)d_in[8];
    const float* k_m = (const float*)d_in[9];
    const float* k_v = (const float*)d_in[10];
    const float* v_w = (const float*)d_in[11];
    const float* v_g = (const float*)d_in[12];
    const float* v_b = (const float*)d_in[13];
    const float* v_m = (const float*)d_in[14];
    const float* v_v = (const float*)d_in[15];
    const float* o_w = (const float*)d_in[16];
    const float* o_g = (const float*)d_in[17];
    const float* o_b = (const float*)d_in[18];
    const float* o_m = (const float*)d_in[19];
    const float* o_v = (const float*)d_in[20];
    float* out = (float*)d_out;

    float *gq, *gpf, *gattn, *gkp, *gvp;
    cudaGetSymbolAddress((void**)&gq, g_q);
    cudaGetSymbolAddress((void**)&gpf, g_pf);
    cudaGetSymbolAddress((void**)&gattn, g_attn);
    cudaGetSymbolAddress((void**)&gkp, g_kp);
    cudaGetSymbolAddress((void**)&gvp, g_vp);

    const float qscale = 0.044194173824159216f;   // 512^-0.5

    // 1. q projection -> g_q  (postscale folds the c^-0.5)
    sgemm_bn_relu<CIN><<<dim3(NPIX / 128, HALF / 128), 256>>>(
        q_w, x, q_g, q_b, q_m, q_v, gq, qscale, nullptr);

    // 2. k projection -> g_pf, pool -> g_kp [c][patch]
    sgemm_bn_relu<CIN><<<dim3(NPIX / 128, HALF / 128), 256>>>(
        k_w, x, k_g, k_b, k_m, k_v, gpf, 1.f, nullptr);
    pool_kernel<<<dim3(HALF, NH), 256>>>(gpf, gkp, 1);

    // 3. v projection -> g_pf, pool -> g_vp [patch][c]
    sgemm_bn_relu<CIN><<<dim3(NPIX / 128, HALF / 128), 256>>>(
        v_w, x, v_g, v_b, v_m, v_v, gpf, 1.f, nullptr);
    pool_kernel<<<dim3(HALF, NH), 256>>>(gpf, gvp, 0);

    // 4. attn = q x kp per patch
    attn_kernel<<<dim3(8, NUM), 256>>>(gq, gkp, gattn);

    // 5. flash (nested softmax attention) -> g_pf reused as output image
    const int smem_bytes = (64 * 256 + 64 * 64 + 128 * 65) * (int)sizeof(float);
    cudaFuncSetAttribute(flash_kernel, cudaFuncAttributeMaxDynamicSharedMemorySize, smem_bytes);
    flash_kernel<<<dim3(8, NUM), 128, smem_bytes>>>(gattn, gvp, gpf);

    // 6. o projection + residual -> d_out
    sgemm_bn_relu<HALF><<<dim3(NPIX / 128, CIN / 128), 256>>>(
        o_w, gpf, o_g, o_b, o_m, o_v, out, 1.f, x);
}

// round 4
// speedup vs baseline: 10.5737x; 10.5737x over previous
#include <cuda_runtime.h>
#include <math.h>

#define HH 256
#define WW 256
#define NPIX 65536          // H*W
#define CIN 512
#define HALF 256
#define PSZ 32
#define NH 8
#define NUM 64              // patches
#define EPS 1e-5f

// ---------------- static scratch (no allocations allowed) ----------------
__device__ float g_q[HALF * NPIX];            // q projection, image layout [c][pix]
__device__ float g_pf[HALF * NPIX];           // reused: kf -> vf -> attention output image
__device__ float g_attn[(size_t)NUM * 1024 * 64];   // attn per patch [b][n][m]
__device__ float g_kp[HALF * NUM];            // pooled k, [c][patch]
__device__ float g_vp[NUM * HALF];            // pooled v, [patch][c]

// ---------------- fused 1x1conv + BN + ReLU GEMM ----------------
template <int KDIM>
__global__ void __launch_bounds__(256)
sgemm_bn_relu(const float* __restrict__ Wt, const float* __restrict__ X,
              const float* __restrict__ gg, const float* __restrict__ bb,
              const float* __restrict__ mm, const float* __restrict__ vv,
              float* __restrict__ C, float postscale,
              const float* __restrict__ resid)
{
    __shared__ float As[8][128];
    __shared__ float Bs[8][128];
    const int bn = blockIdx.x;            // pixel tile
    const int bm = blockIdx.y;            // out-channel tile
    const int tid = threadIdx.x;
    const int tx = tid & 15;
    const int ty = tid >> 4;

    float acc[8][8];
    #pragma unroll
    for (int i = 0; i < 8; i++)
        #pragma unroll
        for (int j = 0; j < 8; j++) acc[i][j] = 0.f;

    const int arow = tid >> 1;
    const int acol = (tid & 1) * 4;
    const int brow = tid >> 5;
    const int bcol = (tid & 31) * 4;
    const float* Ab = Wt + (size_t)(bm * 128 + arow) * KDIM + acol;
    const float* Bb = X + (size_t)brow * NPIX + bn * 128 + bcol;

    for (int kt = 0; kt < KDIM / 8; kt++) {
        float4 a4 = *(const float4*)(Ab + kt * 8);
        As[acol + 0][arow] = a4.x;
        As[acol + 1][arow] = a4.y;
        As[acol + 2][arow] = a4.z;
        As[acol + 3][arow] = a4.w;
        float4 b4 = *(const float4*)(Bb + (size_t)kt * 8 * NPIX);
        *(float4*)&Bs[brow][bcol] = b4;
        __syncthreads();
        #pragma unroll
        for (int k = 0; k < 8; k++) {
            float a[8], bvv[8];
            *(float4*)(a)     = *(const float4*)&As[k][ty * 8];
            *(float4*)(a + 4) = *(const float4*)&As[k][ty * 8 + 4];
            *(float4*)(bvv)     = *(const float4*)&Bs[k][tx * 8];
            *(float4*)(bvv + 4) = *(const float4*)&Bs[k][tx * 8 + 4];
            #pragma unroll
            for (int i = 0; i < 8; i++)
                #pragma unroll
                for (int j = 0; j < 8; j++) acc[i][j] += a[i] * bvv[j];
        }
        __syncthreads();
    }

    #pragma unroll
    for (int i = 0; i < 8; i++) {
        const int o = bm * 128 + ty * 8 + i;
        const float sc = gg[o] * rsqrtf(vv[o] + EPS);
        const float mo = mm[o];
        const float bo = bb[o];
        const size_t rowoff = (size_t)o * NPIX + bn * 128 + tx * 8;
        float out[8];
        #pragma unroll
        for (int j = 0; j < 8; j++) {
            float y = (acc[i][j] - mo) * sc + bo;
            y = fmaxf(y, 0.f) * postscale;
            out[j] = y;
        }
        if (resid) {
            #pragma unroll
            for (int j = 0; j < 8; j++) out[j] += resid[rowoff + j];
        }
        *(float4*)(C + rowoff)     = *(float4*)(out);
        *(float4*)(C + rowoff + 4) = *(float4*)(out + 4);
    }
}

// ---------------- 32x32 patch average pooling ----------------
__global__ void pool_kernel(const float* __restrict__ src, float* __restrict__ dst, int cmajor)
{
    const int c = blockIdx.x;        // 0..255
    const int ph = blockIdx.y;       // 0..7
    const int w = threadIdx.x >> 5;  // warp = pw, 0..7
    const int lane = threadIdx.x & 31;
    const float* base = src + (size_t)c * NPIX + (ph * 32) * WW + w * 32 + lane;
    float s = 0.f;
    #pragma unroll
    for (int r = 0; r < 32; r++) s += base[r * WW];
    #pragma unroll
    for (int o = 16; o > 0; o >>= 1) s += __shfl_xor_sync(0xffffffffu, s, o);
    if (lane == 0) {
        const float mean = s * (1.f / 1024.f);
        const int patch = ph * 8 + w;
        if (cmajor) dst[c * NUM + patch] = mean;
        else        dst[patch * HALF + c] = mean;
    }
}

// ---------------- attn = q_b^T (1024x256) x kp (256x64), per patch ----------------
__global__ void __launch_bounds__(256)
attn_kernel(const float* __restrict__ q, const float* __restrict__ kp, float* __restrict__ attn)
{
    __shared__ float Qs[8][128];
    __shared__ float Ks[8][64];
    const int blk = blockIdx.x;   // 0..7 n-row block
    const int b = blockIdx.y;     // patch 0..63
    const int ph = b >> 3, pw = b & 7;
    const int tid = threadIdx.x;
    const int tx = tid & 15;      // m cols, 4 each
    const int ty = tid >> 4;      // n rows, 8 each

    float acc[8][4];
    #pragma unroll
    for (int i = 0; i < 8; i++)
        #pragma unroll
        for (int j = 0; j < 4; j++) acc[i][j] = 0.f;

    const int pixbase = ph * 32 * WW + pw * 32;
    const int n_l = tid & 127;
    const int c0 = tid >> 7;      // 0 or 1
    const int n = blk * 128 + n_l;
    const int pix = pixbase + (n >> 5) * WW + (n & 31);

    for (int kt = 0; kt < HALF / 8; kt++) {
        #pragma unroll
        for (int i = 0; i < 4; i++) {
            const int cl = c0 + i * 2;
            Qs[cl][n_l] = q[(size_t)(kt * 8 + cl) * NPIX + pix];
        }
        #pragma unroll
        for (int i = 0; i < 2; i++) {
            const int e = tid + i * 256;
            Ks[e >> 6][e & 63] = kp[(kt * 8 + (e >> 6)) * NUM + (e & 63)];
        }
        __syncthreads();
        #pragma unroll
        for (int k = 0; k < 8; k++) {
            float a[8], bm4[4];
            *(float4*)(a)     = *(const float4*)&Qs[k][ty * 8];
            *(float4*)(a + 4) = *(const float4*)&Qs[k][ty * 8 + 4];
            *(float4*)(bm4)   = *(const float4*)&Ks[k][tx * 4];
            #pragma unroll
            for (int i = 0; i < 8; i++)
                #pragma unroll
                for (int j = 0; j < 4; j++) acc[i][j] += a[i] * bm4[j];
        }
        __syncthreads();
    }
    #pragma unroll
    for (int i = 0; i < 8; i++) {
        const size_t off = ((size_t)b * 1024 + blk * 128 + ty * 8 + i) * 64 + tx * 4;
        *(float4*)&attn[off] = *(float4*)acc[i];
    }
}

// ---------------- flash v2: register-tiled two-GEMM nested-softmax attention ----------------
// Block = (row-chunk rblk of 64 rows, patch b). 256 threads, 4x4 micro-tiles.
// corr_map = softmax(A A^T) A  (online), final = softmax(A + corr_map) over 64,
// out = final x vp, written to image layout mid[c][pix].
#define QTS 68          // padded row stride for k-major tiles
__global__ void __launch_bounds__(256, 2)
flash2_kernel(const float* __restrict__ attn, const float* __restrict__ vp, float* __restrict__ mid)
{
    extern __shared__ float sm[];
    float* Qt = sm;                 // [64][QTS] k-major Q tile
    float* Kt = Qt + 64 * QTS;      // [64][QTS] k-major K tile  (reused as stage buffer at end)
    float* Vs = Kt + 64 * QTS;      // [64][QTS] natural A tile
    float* Ps = Vs + 64 * QTS;      // [64][QTS] natural P tile (reused as final weights)
    float* red = Ps + 64 * QTS;     // [64][16]
    float* m_s = red + 64 * 16;     // [64]
    float* l_s = m_s + 64;
    float* sc_s = l_s + 64;
    float* mn_s = sc_s + 64;

    const int rblk = blockIdx.x;    // 0..15
    const int b = blockIdx.y;       // patch
    const int tid = threadIdx.x;
    const int tx = tid & 15;
    const int ty = tid >> 4;
    const int r0 = rblk * 64;
    const float* Ab = attn + (size_t)b * 1024 * 64;

    if (tid < 64) { m_s[tid] = -1e30f; l_s[tid] = 0.f; }

    // load Q tile (k-major, transposed write, conflict-free mapping)
    {
        const int r = tid & 63;
        const int dc = (tid >> 6) * 16;
        const float* src = Ab + (size_t)(r0 + r) * 64 + dc;
        float tmp[16];
        #pragma unroll
        for (int i = 0; i < 4; i++) *(float4*)&tmp[i * 4] = ((const float4*)src)[i];
        #pragma unroll
        for (int i = 0; i < 16; i++) Qt[(dc + i) * QTS + r] = tmp[i];
    }
    __syncthreads();

    float O[4][4];
    #pragma unroll
    for (int i = 0; i < 4; i++)
        #pragma unroll
        for (int j = 0; j < 4; j++) O[i][j] = 0.f;

    for (int t = 0; t < 16; t++) {
        // ---- load K/V tile (same data, two layouts) ----
        {
            const float* srcb = Ab + (size_t)(t * 64) * 64;
            const int r = tid & 63;
            const int dc = (tid >> 6) * 16;
            float tmp[16];
            #pragma unroll
            for (int i = 0; i < 4; i++)
                *(float4*)&tmp[i * 4] = ((const float4*)(srcb + (size_t)r * 64 + dc))[i];
            #pragma unroll
            for (int i = 0; i < 16; i++) Kt[(dc + i) * QTS + r] = tmp[i];

            const int r2 = tid >> 2;
            const int dc2 = (tid & 3) * 16;
            #pragma unroll
            for (int i = 0; i < 4; i++) {
                float4 v4 = ((const float4*)(srcb + (size_t)r2 * 64 + dc2))[i];
                *(float4*)&Vs[r2 * QTS + dc2 + i * 4] = v4;
            }
        }
        __syncthreads();

        // ---- GEMM1: S = Q K^T ----
        float S[4][4];
        #pragma unroll
        for (int i = 0; i < 4; i++)
            #pragma unroll
            for (int j = 0; j < 4; j++) S[i][j] = 0.f;
        #pragma unroll 8
        for (int k = 0; k < 64; k++) {
            float4 a = *(const float4*)&Qt[k * QTS + ty * 4];
            float4 bv = *(const float4*)&Kt[k * QTS + tx * 4];
            const float av[4] = {a.x, a.y, a.z, a.w};
            const float bw[4] = {bv.x, bv.y, bv.z, bv.w};
            #pragma unroll
            for (int i = 0; i < 4; i++)
                #pragma unroll
                for (int j = 0; j < 4; j++) S[i][j] += av[i] * bw[j];
        }

        // ---- local row max -> reduce ----
        #pragma unroll
        for (int i = 0; i < 4; i++) {
            float lm = fmaxf(fmaxf(S[i][0], S[i][1]), fmaxf(S[i][2], S[i][3]));
            red[(ty * 4 + i) * 16 + tx] = lm;
        }
        __syncthreads();
        if (tid < 64) {
            float mt = red[tid * 16];
            #pragma unroll
            for (int j = 1; j < 16; j++) mt = fmaxf(mt, red[tid * 16 + j]);
            const float mo = m_s[tid];
            const float mn = fmaxf(mo, mt);
            sc_s[tid] = __expf(mo - mn);
            m_s[tid] = mn;
            mn_s[tid] = mn;
        }
        __syncthreads();

        // ---- P = exp(S - m), write natural, accumulate row sums, rescale O ----
        #pragma unroll
        for (int i = 0; i < 4; i++) {
            const int r = ty * 4 + i;
            const float mn = mn_s[r];
            const float sc = sc_s[r];
            float p[4], rs = 0.f;
            #pragma unroll
            for (int j = 0; j < 4; j++) { p[j] = __expf(S[i][j] - mn); rs += p[j]; }
            *(float4*)&Ps[r * QTS + tx * 4] = make_float4(p[0], p[1], p[2], p[3]);
            red[r * 16 + tx] = rs;
            #pragma unroll
            for (int j = 0; j < 4; j++) O[i][j] *= sc;
        }
        __syncthreads();
        if (tid < 64) {
            float su = red[tid * 16];
            #pragma unroll
            for (int j = 1; j < 16; j++) su += red[tid * 16 + j];
            l_s[tid] = l_s[tid] * sc_s[tid] + su;
        }

        // ---- GEMM2: O += P V ----
        #pragma unroll 8
        for (int c = 0; c < 64; c++) {
            float pr[4];
            #pragma unroll
            for (int i = 0; i < 4; i++) pr[i] = Ps[(ty * 4 + i) * QTS + c];
            float4 v4 = *(const float4*)&Vs[c * QTS + tx * 4];
            const float vw[4] = {v4.x, v4.y, v4.z, v4.w};
            #pragma unroll
            for (int i = 0; i < 4; i++)
                #pragma unroll
                for (int j = 0; j < 4; j++) O[i][j] += pr[i] * vw[j];
        }
        __syncthreads();
    }

    // ---- final: fv = Q + O/l, softmax over 64 cols ----
    float fv[4][4];
    #pragma unroll
    for (int i = 0; i < 4; i++) {
        const int r = ty * 4 + i;
        const float linv = 1.f / l_s[r];
        #pragma unroll
        for (int j = 0; j < 4; j++)
            fv[i][j] = Qt[(tx * 4 + j) * QTS + r] + O[i][j] * linv;
    }
    #pragma unroll
    for (int i = 0; i < 4; i++) {
        float lm = fmaxf(fmaxf(fv[i][0], fv[i][1]), fmaxf(fv[i][2], fv[i][3]));
        red[(ty * 4 + i) * 16 + tx] = lm;
    }
    __syncthreads();
    if (tid < 64) {
        float mt = red[tid * 16];
        #pragma unroll
        for (int j = 1; j < 16; j++) mt = fmaxf(mt, red[tid * 16 + j]);
        mn_s[tid] = mt;
    }
    __syncthreads();
    #pragma unroll
    for (int i = 0; i < 4; i++) {
        const int r = ty * 4 + i;
        const float mn = mn_s[r];
        float rs = 0.f;
        #pragma unroll
        for (int j = 0; j < 4; j++) { fv[i][j] = __expf(fv[i][j] - mn); rs += fv[i][j]; }
        red[r * 16 + tx] = rs;
    }
    __syncthreads();
    if (tid < 64) {
        float su = red[tid * 16];
        #pragma unroll
        for (int j = 1; j < 16; j++) su += red[tid * 16 + j];
        l_s[tid] = 1.f / su;
    }
    __syncthreads();
    #pragma unroll
    for (int i = 0; i < 4; i++) {
        const int r = ty * 4 + i;
        const float inv = l_s[r];
        *(float4*)&Ps[r * QTS + tx * 4] =
            make_float4(fv[i][0] * inv, fv[i][1] * inv, fv[i][2] * inv, fv[i][3] * inv);
    }
    __syncthreads();

    // ---- out GEMM: out[64][256] = P_final[64][64] x vp[64][256] ----
    // thread tile: rows ty*4..+3, channels tx*16..+15; vp via L1 (hot, 64KB)
    float acc[4][16];
    #pragma unroll
    for (int i = 0; i < 4; i++)
        #pragma unroll
        for (int j = 0; j < 16; j++) acc[i][j] = 0.f;
    #pragma unroll 2
    for (int m = 0; m < 64; m++) {
        float pr[4];
        #pragma unroll
        for (int i = 0; i < 4; i++) pr[i] = Ps[(ty * 4 + i) * QTS + m];
        const float4* vr = (const float4*)(vp + m * 256 + tx * 16);
        float4 v0 = vr[0], v1 = vr[1], v2 = vr[2], v3 = vr[3];
        const float vw[16] = {v0.x, v0.y, v0.z, v0.w, v1.x, v1.y, v1.z, v1.w,
                              v2.x, v2.y, v2.z, v2.w, v3.x, v3.y, v3.z, v3.w};
        #pragma unroll
        for (int i = 0; i < 4; i++)
            #pragma unroll
            for (int j = 0; j < 16; j++) acc[i][j] += pr[i] * vw[j];
    }

    // ---- staged, coalesced store to image layout ----
    const int ph = b >> 3, pw = b & 7;
    const int pixbase = ph * 32 * WW + pw * 32;
    float* stg = Kt;   // 64x65 <= 64*QTS
    #pragma unroll 1
    for (int g = 0; g < 4; g++) {
        __syncthreads();
        if ((tx >> 2) == g) {
            const int txl = tx & 3;
            #pragma unroll
            for (int i = 0; i < 4; i++)
                #pragma unroll
                for (int j = 0; j < 16; j++)
                    stg[(ty * 4 + i) * 65 + txl * 16 + j] = acc[i][j];
        }
        __syncthreads();
        const int rl = tid & 63;
        const int cl0 = tid >> 6;
        const int n = r0 + rl;
        const int pix = pixbase + (n >> 5) * WW + (n & 31);
        #pragma unroll
        for (int k = 0; k < 16; k++) {
            const int cl = cl0 + k * 4;
            mid[(size_t)(g * 64 + cl) * NPIX + pix] = stg[rl * 65 + cl];
        }
    }
}

// ---------------- launch ----------------
extern "C" void kernel_launch(void* const* d_in, const int* in_sizes, int n_in,
                              void* d_out, int out_size)
{
    const float* x   = (const float*)d_in[0];
    const float* q_w = (const float*)d_in[1];
    const float* q_g = (const float*)d_in[2];
    const float* q_b = (const float*)d_in[3];
    const float* q_m = (const float*)d_in[4];
    const float* q_v = (const float*)d_in[5];
    const float* k_w = (const float*)d_in[6];
    const float* k_g = (const float*)d_in[7];
    const float* k_b = (const float*)d_in[8];
    const float* k_m = (const float*)d_in[9];
    const float* k_v = (const float*)d_in[10];
    const float* v_w = (const float*)d_in[11];
    const float* v_g = (const float*)d_in[12];
    const float* v_b = (const float*)d_in[13];
    const float* v_m = (const float*)d_in[14];
    const float* v_v = (const float*)d_in[15];
    const float* o_w = (const float*)d_in[16];
    const float* o_g = (const float*)d_in[17];
    const float* o_b = (const float*)d_in[18];
    const float* o_m = (const float*)d_in[19];
    const float* o_v = (const float*)d_in[20];
    float* out = (float*)d_out;

    float *gq, *gpf, *gattn, *gkp, *gvp;
    cudaGetSymbolAddress((void**)&gq, g_q);
    cudaGetSymbolAddress((void**)&gpf, g_pf);
    cudaGetSymbolAddress((void**)&gattn, g_attn);
    cudaGetSymbolAddress((void**)&gkp, g_kp);
    cudaGetSymbolAddress((void**)&gvp, g_vp);

    const float qscale = 0.044194173824159216f;   // 512^-0.5

    // 1. q projection -> g_q  (postscale folds the c^-0.5)
    sgemm_bn_relu<CIN><<<dim3(NPIX / 128, HALF / 128), 256>>>(
        q_w, x, q_g, q_b, q_m, q_v, gq, qscale, nullptr);

    // 2. k projection -> g_pf, pool -> g_kp [c][patch]
    sgemm_bn_relu<CIN><<<dim3(NPIX / 128, HALF / 128), 256>>>(
        k_w, x, k_g, k_b, k_m, k_v, gpf, 1.f, nullptr);
    pool_kernel<<<dim3(HALF, NH), 256>>>(gpf, gkp, 1);

    // 3. v projection -> g_pf, pool -> g_vp [patch][c]
    sgemm_bn_relu<CIN><<<dim3(NPIX / 128, HALF / 128), 256>>>(
        v_w, x, v_g, v_b, v_m, v_v, gpf, 1.f, nullptr);
    pool_kernel<<<dim3(HALF, NH), 256>>>(gpf, gvp, 0);

    // 4. attn = q x kp per patch
    attn_kernel<<<dim3(8, NUM), 256>>>(gq, gkp, gattn);

    // 5. flash v2 (nested softmax attention) -> g_pf reused as output image
    const int smem_bytes = (4 * 64 * QTS + 64 * 16 + 4 * 64) * (int)sizeof(float);
    cudaFuncSetAttribute(flash2_kernel, cudaFuncAttributeMaxDynamicSharedMemorySize, smem_bytes);
    flash2_kernel<<<dim3(16, NUM), 256, smem_bytes>>>(gattn, gvp, gpf);

    // 6. o projection + residual -> d_out
    sgemm_bn_relu<HALF><<<dim3(NPIX / 128, CIN / 128), 256>>>(
        o_w, gpf, o_g, o_b, o_m, o_v, out, 1.f, x);
}

// round 8
// speedup vs baseline: 17.3493x; 1.6408x over previous
#include <cuda_runtime.h>
#include <cuda_bf16.h>
#include <cstdint>
#include <math.h>

#define HH 256
#define WW 256
#define NPIX 65536          // H*W
#define CIN 512
#define HALF 256
#define PSZ 32
#define NH 8
#define NUM 64              // patches
#define EPS 1e-5f

// ==================== mma.sync / ldmatrix helpers (plain sm_80+ PTX) ====================
__device__ __forceinline__ uint32_t smem_to_u32(const void* smem_ptr) {
    uint32_t addr;
    asm("{ .reg .u64 tmp; cvta.to.shared.u64 tmp, %1; cvt.u32.u64 %0, tmp; }"
        : "=r"(addr) : "l"(smem_ptr));
    return addr;
}
__device__ __forceinline__ void ldsm4(uint32_t* r, uint32_t addr) {
    asm volatile("ldmatrix.sync.aligned.m8n8.x4.shared.b16 {%0,%1,%2,%3}, [%4];"
        : "=r"(r[0]), "=r"(r[1]), "=r"(r[2]), "=r"(r[3]) : "r"(addr));
}
__device__ __forceinline__ void mma16816(float* c, const uint32_t* a, const uint32_t* b) {
    asm volatile(
        "mma.sync.aligned.m16n8k16.row.col.f32.bf16.bf16.f32 "
        "{%0,%1,%2,%3}, {%4,%5,%6,%7}, {%8,%9}, {%0,%1,%2,%3};"
        : "+f"(c[0]), "+f"(c[1]), "+f"(c[2]), "+f"(c[3])
        : "r"(a[0]), "r"(a[1]), "r"(a[2]), "r"(a[3]), "r"(b[0]), "r"(b[1]));
}

// ==================== static scratch ====================
__device__ __nv_bfloat16 g_xthi[(size_t)NPIX * CIN];   // x transposed hi, [pix][512]
__device__ __nv_bfloat16 g_xtlo[(size_t)NPIX * CIN];   // x transposed lo
__device__ __nv_bfloat16 g_pthi[(size_t)NPIX * HALF];  // attn-out transposed hi, [pix][256]
__device__ __nv_bfloat16 g_ptlo[(size_t)NPIX * HALF];
__device__ __nv_bfloat16 g_whi[4][CIN * HALF];         // q,k,v,o weights hi
__device__ __nv_bfloat16 g_wlo[4][CIN * HALF];
__device__ float g_q[(size_t)HALF * NPIX];             // q projection image [c][pix]
__device__ float g_attn[(size_t)NUM * 1024 * 64];      // attn per patch
__device__ float g_kp[HALF * NUM];                     // pooled k [c][patch]
__device__ float g_vp[NUM * HALF];                     // pooled v [patch][c]

// ==================== conversion kernels ====================
__global__ void conv_w_kernel(const float* __restrict__ w,
                              __nv_bfloat16* __restrict__ hi,
                              __nv_bfloat16* __restrict__ lo, int n)
{
    int i = blockIdx.x * 256 + threadIdx.x;
    if (i < n) {
        float v = w[i];
        __nv_bfloat16 h = __float2bfloat16(v);
        hi[i] = h;
        lo[i] = __float2bfloat16(v - __bfloat162float(h));
    }
}

// x [512][NPIX] fp32 -> XT [NPIX][512] bf16 hi/lo  (32x32 tile transpose)
__global__ void conv_x_kernel(const float* __restrict__ x,
                              __nv_bfloat16* __restrict__ hi,
                              __nv_bfloat16* __restrict__ lo)
{
    __shared__ float t[32][33];
    const int p0 = blockIdx.x * 32;
    const int k0 = blockIdx.y * 32;
    const int tx = threadIdx.x, ty = threadIdx.y;   // (32, 8)
    #pragma unroll
    for (int i = 0; i < 4; i++) {
        int kl = ty + i * 8;
        t[kl][tx] = x[(size_t)(k0 + kl) * NPIX + p0 + tx];
    }
    __syncthreads();
    #pragma unroll
    for (int i = 0; i < 4; i++) {
        int pl = ty + i * 8;
        float v = t[tx][pl];
        __nv_bfloat16 h = __float2bfloat16(v);
        size_t off = (size_t)(p0 + pl) * CIN + k0 + tx;
        hi[off] = h;
        lo[off] = __float2bfloat16(v - __bfloat162float(h));
    }
}

__global__ void zero_pool_kernel(float* kp, float* vp)
{
    int i = blockIdx.x * 256 + threadIdx.x;   // grid 64 -> 16384
    kp[i] = 0.f;
    vp[i] = 0.f;
}

// ==================== HMMA (mma.sync) projection GEMM ====================
// C[M tile of out-ch][N=128 pixels] = W(hi+lo) x X(hi+lo), K = KDIM, split-bf16.
// MODE 0: image fp32 out (with postscale)      [q]
// MODE 1: pooled atomic out, [c][patch]        [k]
// MODE 2: pooled atomic out, [patch][c]        [v]
// MODE 3: image fp32 out + residual            [o]
#define LDKB 144                    // smem row stride in bytes (72 bf16)
#define TILE_BYTES (128 * LDKB)     // 18432 per tensor tile
#define PROJ_SMEM (4 * TILE_BYTES)  // 73728
template <int KDIM, int MODE>
__global__ void __launch_bounds__(256, 2)
proj_mma(const __nv_bfloat16* __restrict__ Ahi, const __nv_bfloat16* __restrict__ Alo,
         const __nv_bfloat16* __restrict__ Bhi, const __nv_bfloat16* __restrict__ Blo,
         const float* __restrict__ gg, const float* __restrict__ bb,
         const float* __restrict__ mm, const float* __restrict__ vv,
         float postscale, float* __restrict__ outp, const float* __restrict__ resid)
{
    extern __shared__ char smc[];
    const uint32_t sb = smem_to_u32(smc);
    const uint32_t baseA[2] = { sb, sb + TILE_BYTES };                 // Ahi, Alo
    const uint32_t baseB[2] = { sb + 2 * TILE_BYTES, sb + 3 * TILE_BYTES }; // Bhi, Blo

    const int tid = threadIdx.x;
    const int wid = tid >> 5;
    const int lane = tid & 31;
    const int wm = wid & 1;          // 0..1 -> 64 rows each
    const int wn = wid >> 1;         // 0..3 -> 32 cols each
    const int bm = blockIdx.y;
    const int pixbase = blockIdx.x * 128;

    float acc[4][4][4];
    #pragma unroll
    for (int mt = 0; mt < 4; mt++)
        #pragma unroll
        for (int nt = 0; nt < 4; nt++)
            #pragma unroll
            for (int e = 0; e < 4; e++) acc[mt][nt][e] = 0.f;

    // ldmatrix lane-address components
    const int am_ = lane & 15;                 // A row offset within 16
    const int ak_ = (lane >> 4) * 8;           // A k offset
    const int bn_ = (lane & 7) + ((lane >> 4) << 3);   // B n offset within 16
    const int bk_ = ((lane >> 3) & 1) * 8;     // B k offset

    // loader indices: 1024 16B-chunks per tensor tile, 4 per thread per tensor
    const int lr[4] = { (tid + 0) >> 3, (tid + 256) >> 3, (tid + 512) >> 3, (tid + 768) >> 3 };
    const int lc = tid & 7;

    const int NCH = KDIM / 64;
    for (int ch = 0; ch < NCH; ch++) {
        const int kc0 = ch * 64;
        // ---- load 4 tensor tiles (Ahi, Alo, Bhi, Blo), 64 k-cols each ----
        #pragma unroll
        for (int j = 0; j < 4; j++) {
            const int r = lr[j];
            const size_t arow = (size_t)(bm * 128 + r) * KDIM + kc0 + lc * 8;
            const size_t brow = (size_t)(pixbase + r) * KDIM + kc0 + lc * 8;
            *(uint4*)(smc + 0 * TILE_BYTES + r * LDKB + lc * 16) = *(const uint4*)(Ahi + arow);
            *(uint4*)(smc + 1 * TILE_BYTES + r * LDKB + lc * 16) = *(const uint4*)(Alo + arow);
            *(uint4*)(smc + 2 * TILE_BYTES + r * LDKB + lc * 16) = *(const uint4*)(Bhi + brow);
            *(uint4*)(smc + 3 * TILE_BYTES + r * LDKB + lc * 16) = *(const uint4*)(Blo + brow);
        }
        __syncthreads();

        #pragma unroll
        for (int ks = 0; ks < 4; ks++) {
            const int kc = ks * 16;
            uint32_t a[4][4], bh[4][2], bl[4][2];
            // A hi fragments
            #pragma unroll
            for (int mt = 0; mt < 4; mt++)
                ldsm4(a[mt], baseA[0] + (wm * 64 + mt * 16 + am_) * LDKB + (kc + ak_) * 2);
            // B hi fragments (two x4, each covers 2 n-tiles)
            #pragma unroll
            for (int pr = 0; pr < 2; pr++) {
                uint32_t r4[4];
                ldsm4(r4, baseB[0] + (wn * 32 + pr * 16 + bn_) * LDKB + (kc + bk_) * 2);
                bh[2 * pr][0] = r4[0]; bh[2 * pr][1] = r4[1];
                bh[2 * pr + 1][0] = r4[2]; bh[2 * pr + 1][1] = r4[3];
            }
            #pragma unroll
            for (int mt = 0; mt < 4; mt++)
                #pragma unroll
                for (int nt = 0; nt < 4; nt++) mma16816(acc[mt][nt], a[mt], bh[nt]);
            // B lo fragments
            #pragma unroll
            for (int pr = 0; pr < 2; pr++) {
                uint32_t r4[4];
                ldsm4(r4, baseB[1] + (wn * 32 + pr * 16 + bn_) * LDKB + (kc + bk_) * 2);
                bl[2 * pr][0] = r4[0]; bl[2 * pr][1] = r4[1];
                bl[2 * pr + 1][0] = r4[2]; bl[2 * pr + 1][1] = r4[3];
            }
            #pragma unroll
            for (int mt = 0; mt < 4; mt++)
                #pragma unroll
                for (int nt = 0; nt < 4; nt++) mma16816(acc[mt][nt], a[mt], bl[nt]);
            // A lo fragments (reuse a regs)
            #pragma unroll
            for (int mt = 0; mt < 4; mt++)
                ldsm4(a[mt], baseA[1] + (wm * 64 + mt * 16 + am_) * LDKB + (kc + ak_) * 2);
            #pragma unroll
            for (int mt = 0; mt < 4; mt++)
                #pragma unroll
                for (int nt = 0; nt < 4; nt++) mma16816(acc[mt][nt], a[mt], bh[nt]);
        }
        __syncthreads();
    }

    // ==================== epilogue ====================
    if (MODE == 1 || MODE == 2) {
        // fused BN + ReLU + 32-pixel pooling; each warp's 32 cols = one patch
        const int x0 = (pixbase & 255) + wn * 32;
        const int y0 = pixbase >> 8;
        const int p = ((y0 >> 5) << 3) + (x0 >> 5);
        const float inv = 1.f / 1024.f;
        #pragma unroll
        for (int mt = 0; mt < 4; mt++) {
            #pragma unroll
            for (int hf = 0; hf < 2; hf++) {
                const int o = bm * 128 + wm * 64 + mt * 16 + (lane >> 2) + hf * 8;
                const float s_r = gg[o] * rsqrtf(vv[o] + EPS);
                const float t_r = bb[o] - mm[o] * s_r;
                float s = 0.f;
                #pragma unroll
                for (int nt = 0; nt < 4; nt++) {
                    s += fmaxf(acc[mt][nt][2 * hf + 0] * s_r + t_r, 0.f);
                    s += fmaxf(acc[mt][nt][2 * hf + 1] * s_r + t_r, 0.f);
                }
                s += __shfl_xor_sync(0xffffffffu, s, 1);
                s += __shfl_xor_sync(0xffffffffu, s, 2);
                if ((lane & 3) == 0) {
                    if (MODE == 1) atomicAdd(outp + o * NUM + p, s * inv);
                    else           atomicAdd(outp + p * HALF + o, s * inv);
                }
            }
        }
    } else {
        // BN params per row into smem (region beyond stage)
        float* stage = (float*)smc;                   // 128 x 130 fp32 = 66560B
        float* scb = (float*)(smc + 68608);           // 128 floats
        float* bob = (float*)(smc + 69632);           // 128 floats
        if (tid < 128) {
            const int o = bm * 128 + tid;
            const float s_r = gg[o] * rsqrtf(vv[o] + EPS);
            scb[tid] = s_r;
            bob[tid] = bb[o] - mm[o] * s_r;
        }
        __syncthreads();
        #pragma unroll
        for (int mt = 0; mt < 4; mt++) {
            const int r_lo = wm * 64 + mt * 16 + (lane >> 2);
            #pragma unroll
            for (int nt = 0; nt < 4; nt++) {
                const int c = wn * 32 + nt * 8 + (lane & 3) * 2;
                stage[r_lo * 130 + c]     = fmaxf(acc[mt][nt][0] * scb[r_lo] + bob[r_lo], 0.f) * postscale;
                stage[r_lo * 130 + c + 1] = fmaxf(acc[mt][nt][1] * scb[r_lo] + bob[r_lo], 0.f) * postscale;
                stage[(r_lo + 8) * 130 + c]     = fmaxf(acc[mt][nt][2] * scb[r_lo + 8] + bob[r_lo + 8], 0.f) * postscale;
                stage[(r_lo + 8) * 130 + c + 1] = fmaxf(acc[mt][nt][3] * scb[r_lo + 8] + bob[r_lo + 8], 0.f) * postscale;
            }
        }
        __syncthreads();
        for (int i = tid; i < 128 * 128; i += 256) {
            const int r = i >> 7;
            const int c = i & 127;
            float v = stage[r * 130 + c];
            const size_t go = (size_t)(bm * 128 + r) * NPIX + pixbase + c;
            if (MODE == 3) v += resid[go];
            outp[go] = v;
        }
    }
}

// ---------------- attn = q_b^T (1024x256) x kp (256x64), per patch ----------------
__global__ void __launch_bounds__(256)
attn_kernel(const float* __restrict__ q, const float* __restrict__ kp, float* __restrict__ attn)
{
    __shared__ float Qs[8][128];
    __shared__ float Ks[8][64];
    const int blk = blockIdx.x;
    const int b = blockIdx.y;
    const int ph = b >> 3, pw = b & 7;
    const int tid = threadIdx.x;
    const int tx = tid & 15;
    const int ty = tid >> 4;

    float acc[8][4];
    #pragma unroll
    for (int i = 0; i < 8; i++)
        #pragma unroll
        for (int j = 0; j < 4; j++) acc[i][j] = 0.f;

    const int pixbase = ph * 32 * WW + pw * 32;
    const int n_l = tid & 127;
    const int c0 = tid >> 7;
    const int n = blk * 128 + n_l;
    const int pix = pixbase + (n >> 5) * WW + (n & 31);

    for (int kt = 0; kt < HALF / 8; kt++) {
        #pragma unroll
        for (int i = 0; i < 4; i++) {
            const int cl = c0 + i * 2;
            Qs[cl][n_l] = q[(size_t)(kt * 8 + cl) * NPIX + pix];
        }
        #pragma unroll
        for (int i = 0; i < 2; i++) {
            const int e = tid + i * 256;
            Ks[e >> 6][e & 63] = kp[(kt * 8 + (e >> 6)) * NUM + (e & 63)];
        }
        __syncthreads();
        #pragma unroll
        for (int k = 0; k < 8; k++) {
            float a[8], bm4[4];
            *(float4*)(a)     = *(const float4*)&Qs[k][ty * 8];
            *(float4*)(a + 4) = *(const float4*)&Qs[k][ty * 8 + 4];
            *(float4*)(bm4)   = *(const float4*)&Ks[k][tx * 4];
            #pragma unroll
            for (int i = 0; i < 8; i++)
                #pragma unroll
                for (int j = 0; j < 4; j++) acc[i][j] += a[i] * bm4[j];
        }
        __syncthreads();
    }
    #pragma unroll
    for (int i = 0; i < 8; i++) {
        const size_t off = ((size_t)b * 1024 + blk * 128 + ty * 8 + i) * 64 + tx * 4;
        *(float4*)&attn[off] = *(float4*)acc[i];
    }
}

// ---------------- flash v2 (register-tiled nested-softmax attention) ----------------
// Output: bf16 hi/lo, transposed [pix][256] (feeds o-projection directly).
#define QTS 68
__global__ void __launch_bounds__(256, 2)
flash2_kernel(const float* __restrict__ attn, const float* __restrict__ vp,
              __nv_bfloat16* __restrict__ pthi, __nv_bfloat16* __restrict__ ptlo)
{
    extern __shared__ float sm[];
    float* Qt = sm;                 // [64][QTS] k-major Q tile
    float* Kt = Qt + 64 * QTS;      // [64][QTS] k-major K tile  (reused as stage)
    float* Vs = Kt + 64 * QTS;      // [64][QTS] natural A tile
    float* Ps = Vs + 64 * QTS;      // [64][QTS] natural P tile
    float* red = Ps + 64 * QTS;     // [64][16]
    float* m_s = red + 64 * 16;
    float* l_s = m_s + 64;
    float* sc_s = l_s + 64;
    float* mn_s = sc_s + 64;

    const int rblk = blockIdx.x;    // 0..15
    const int b = blockIdx.y;       // patch
    const int tid = threadIdx.x;
    const int tx = tid & 15;
    const int ty = tid >> 4;
    const int r0 = rblk * 64;
    const float* Ab = attn + (size_t)b * 1024 * 64;

    if (tid < 64) { m_s[tid] = -1e30f; l_s[tid] = 0.f; }

    {
        const int r = tid & 63;
        const int dc = (tid >> 6) * 16;
        const float* src = Ab + (size_t)(r0 + r) * 64 + dc;
        float tmp[16];
        #pragma unroll
        for (int i = 0; i < 4; i++) *(float4*)&tmp[i * 4] = ((const float4*)src)[i];
        #pragma unroll
        for (int i = 0; i < 16; i++) Qt[(dc + i) * QTS + r] = tmp[i];
    }
    __syncthreads();

    float O[4][4];
    #pragma unroll
    for (int i = 0; i < 4; i++)
        #pragma unroll
        for (int j = 0; j < 4; j++) O[i][j] = 0.f;

    for (int t = 0; t < 16; t++) {
        {
            const float* srcb = Ab + (size_t)(t * 64) * 64;
            const int r = tid & 63;
            const int dc = (tid >> 6) * 16;
            float tmp[16];
            #pragma unroll
            for (int i = 0; i < 4; i++)
                *(float4*)&tmp[i * 4] = ((const float4*)(srcb + (size_t)r * 64 + dc))[i];
            #pragma unroll
            for (int i = 0; i < 16; i++) Kt[(dc + i) * QTS + r] = tmp[i];

            const int r2 = tid >> 2;
            const int dc2 = (tid & 3) * 16;
            #pragma unroll
            for (int i = 0; i < 4; i++) {
                float4 v4 = ((const float4*)(srcb + (size_t)r2 * 64 + dc2))[i];
                *(float4*)&Vs[r2 * QTS + dc2 + i * 4] = v4;
            }
        }
        __syncthreads();

        float S[4][4];
        #pragma unroll
        for (int i = 0; i < 4; i++)
            #pragma unroll
            for (int j = 0; j < 4; j++) S[i][j] = 0.f;
        #pragma unroll 8
        for (int k = 0; k < 64; k++) {
            float4 a = *(const float4*)&Qt[k * QTS + ty * 4];
            float4 bv = *(const float4*)&Kt[k * QTS + tx * 4];
            const float av[4] = {a.x, a.y, a.z, a.w};
            const float bw[4] = {bv.x, bv.y, bv.z, bv.w};
            #pragma unroll
            for (int i = 0; i < 4; i++)
                #pragma unroll
                for (int j = 0; j < 4; j++) S[i][j] += av[i] * bw[j];
        }

        #pragma unroll
        for (int i = 0; i < 4; i++) {
            float lm = fmaxf(fmaxf(S[i][0], S[i][1]), fmaxf(S[i][2], S[i][3]));
            red[(ty * 4 + i) * 16 + tx] = lm;
        }
        __syncthreads();
        if (tid < 64) {
            float mt = red[tid * 16];
            #pragma unroll
            for (int j = 1; j < 16; j++) mt = fmaxf(mt, red[tid * 16 + j]);
            const float mo = m_s[tid];
            const float mn = fmaxf(mo, mt);
            sc_s[tid] = __expf(mo - mn);
            m_s[tid] = mn;
            mn_s[tid] = mn;
        }
        __syncthreads();

        #pragma unroll
        for (int i = 0; i < 4; i++) {
            const int r = ty * 4 + i;
            const float mn = mn_s[r];
            const float scx = sc_s[r];
            float p[4], rs = 0.f;
            #pragma unroll
            for (int j = 0; j < 4; j++) { p[j] = __expf(S[i][j] - mn); rs += p[j]; }
            *(float4*)&Ps[r * QTS + tx * 4] = make_float4(p[0], p[1], p[2], p[3]);
            red[r * 16 + tx] = rs;
            #pragma unroll
            for (int j = 0; j < 4; j++) O[i][j] *= scx;
        }
        __syncthreads();
        if (tid < 64) {
            float su = red[tid * 16];
            #pragma unroll
            for (int j = 1; j < 16; j++) su += red[tid * 16 + j];
            l_s[tid] = l_s[tid] * sc_s[tid] + su;
        }

        #pragma unroll 8
        for (int c = 0; c < 64; c++) {
            float pr[4];
            #pragma unroll
            for (int i = 0; i < 4; i++) pr[i] = Ps[(ty * 4 + i) * QTS + c];
            float4 v4 = *(const float4*)&Vs[c * QTS + tx * 4];
            const float vw[4] = {v4.x, v4.y, v4.z, v4.w};
            #pragma unroll
            for (int i = 0; i < 4; i++)
                #pragma unroll
                for (int j = 0; j < 4; j++) O[i][j] += pr[i] * vw[j];
        }
        __syncthreads();
    }

    float fv[4][4];
    #pragma unroll
    for (int i = 0; i < 4; i++) {
        const int r = ty * 4 + i;
        const float linv = 1.f / l_s[r];
        #pragma unroll
        for (int j = 0; j < 4; j++)
            fv[i][j] = Qt[(tx * 4 + j) * QTS + r] + O[i][j] * linv;
    }
    #pragma unroll
    for (int i = 0; i < 4; i++) {
        float lm = fmaxf(fmaxf(fv[i][0], fv[i][1]), fmaxf(fv[i][2], fv[i][3]));
        red[(ty * 4 + i) * 16 + tx] = lm;
    }
    __syncthreads();
    if (tid < 64) {
        float mt = red[tid * 16];
        #pragma unroll
        for (int j = 1; j < 16; j++) mt = fmaxf(mt, red[tid * 16 + j]);
        mn_s[tid] = mt;
    }
    __syncthreads();
    #pragma unroll
    for (int i = 0; i < 4; i++) {
        const int r = ty * 4 + i;
        const float mn = mn_s[r];
        float rs = 0.f;
        #pragma unroll
        for (int j = 0; j < 4; j++) { fv[i][j] = __expf(fv[i][j] - mn); rs += fv[i][j]; }
        red[r * 16 + tx] = rs;
    }
    __syncthreads();
    if (tid < 64) {
        float su = red[tid * 16];
        #pragma unroll
        for (int j = 1; j < 16; j++) su += red[tid * 16 + j];
        l_s[tid] = 1.f / su;
    }
    __syncthreads();
    #pragma unroll
    for (int i = 0; i < 4; i++) {
        const int r = ty * 4 + i;
        const float inv = l_s[r];
        *(float4*)&Ps[r * QTS + tx * 4] =
            make_float4(fv[i][0] * inv, fv[i][1] * inv, fv[i][2] * inv, fv[i][3] * inv);
    }
    __syncthreads();

    // out GEMM: out[64][256] = P_final[64][64] x vp[64][256]
    float acc[4][16];
    #pragma unroll
    for (int i = 0; i < 4; i++)
        #pragma unroll
        for (int j = 0; j < 16; j++) acc[i][j] = 0.f;
    #pragma unroll 2
    for (int m = 0; m < 64; m++) {
        float pr[4];
        #pragma unroll
        for (int i = 0; i < 4; i++) pr[i] = Ps[(ty * 4 + i) * QTS + m];
        const float4* vr = (const float4*)(vp + m * 256 + tx * 16);
        float4 v0 = vr[0], v1 = vr[1], v2 = vr[2], v3 = vr[3];
        const float vw[16] = {v0.x, v0.y, v0.z, v0.w, v1.x, v1.y, v1.z, v1.w,
                              v2.x, v2.y, v2.z, v2.w, v3.x, v3.y, v3.z, v3.w};
        #pragma unroll
        for (int i = 0; i < 4; i++)
            #pragma unroll
            for (int j = 0; j < 16; j++) acc[i][j] += pr[i] * vw[j];
    }

    // staged store -> transposed bf16 hi/lo [pix][256]
    const int ph = b >> 3, pw = b & 7;
    const int pixbase = ph * 32 * WW + pw * 32;
    float* stg = Kt;
    #pragma unroll 1
    for (int g = 0; g < 4; g++) {
        __syncthreads();
        if ((tx >> 2) == g) {
            const int txl = tx & 3;
            #pragma unroll
            for (int i = 0; i < 4; i++)
                #pragma unroll
                for (int j = 0; j < 16; j++)
                    stg[(ty * 4 + i) * 65 + txl * 16 + j] = acc[i][j];
        }
        __syncthreads();
        const int rl = tid >> 2;           // 0..63
        const int cc0 = (tid & 3) * 16;    // 0,16,32,48
        const int n = r0 + rl;
        const int pix = pixbase + (n >> 5) * WW + (n & 31);
        #pragma unroll
        for (int k2 = 0; k2 < 16; k2++) {
            float v = stg[rl * 65 + cc0 + k2];
            __nv_bfloat16 h = __float2bfloat16(v);
            const size_t off = (size_t)pix * HALF + g * 64 + cc0 + k2;
            pthi[off] = h;
            ptlo[off] = __float2bfloat16(v - __bfloat162float(h));
        }
    }
}

// ==================== launch ====================
extern "C" void kernel_launch(void* const* d_in, const int* in_sizes, int n_in,
                              void* d_out, int out_size)
{
    const float* x   = (const float*)d_in[0];
    const float* q_w = (const float*)d_in[1];
    const float* q_g = (const float*)d_in[2];
    const float* q_b = (const float*)d_in[3];
    const float* q_m = (const float*)d_in[4];
    const float* q_v = (const float*)d_in[5];
    const float* k_w = (const float*)d_in[6];
    const float* k_g = (const float*)d_in[7];
    const float* k_b = (const float*)d_in[8];
    const float* k_m = (const float*)d_in[9];
    const float* k_v = (const float*)d_in[10];
    const float* v_w = (const float*)d_in[11];
    const float* v_g = (const float*)d_in[12];
    const float* v_b = (const float*)d_in[13];
    const float* v_m = (const float*)d_in[14];
    const float* v_v = (const float*)d_in[15];
    const float* o_w = (const float*)d_in[16];
    const float* o_g = (const float*)d_in[17];
    const float* o_b = (const float*)d_in[18];
    const float* o_m = (const float*)d_in[19];
    const float* o_v = (const float*)d_in[20];
    float* out = (float*)d_out;

    __nv_bfloat16 *xthi, *xtlo, *pthi, *ptlo;
    __nv_bfloat16 (*whi)[CIN * HALF], (*wlo)[CIN * HALF];
    float *gq, *gattn, *gkp, *gvp;
    cudaGetSymbolAddress((void**)&xthi, g_xthi);
    cudaGetSymbolAddress((void**)&xtlo, g_xtlo);
    cudaGetSymbolAddress((void**)&pthi, g_pthi);
    cudaGetSymbolAddress((void**)&ptlo, g_ptlo);
    cudaGetSymbolAddress((void**)&whi, g_whi);
    cudaGetSymbolAddress((void**)&wlo, g_wlo);
    cudaGetSymbolAddress((void**)&gq, g_q);
    cudaGetSymbolAddress((void**)&gattn, g_attn);
    cudaGetSymbolAddress((void**)&gkp, g_kp);
    cudaGetSymbolAddress((void**)&gvp, g_vp);

    const float qscale = 0.044194173824159216f;   // 512^-0.5

    // conversions
    conv_w_kernel<<<512, 256>>>(q_w, whi[0], wlo[0], HALF * CIN);
    conv_w_kernel<<<512, 256>>>(k_w, whi[1], wlo[1], HALF * CIN);
    conv_w_kernel<<<512, 256>>>(v_w, whi[2], wlo[2], HALF * CIN);
    conv_w_kernel<<<512, 256>>>(o_w, whi[3], wlo[3], CIN * HALF);
    conv_x_kernel<<<dim3(NPIX / 32, CIN / 32), dim3(32, 8)>>>(x, xthi, xtlo);
    zero_pool_kernel<<<64, 256>>>(gkp, gvp);

    // projections on HMMA (mma.sync)
    cudaFuncSetAttribute(proj_mma<CIN, 0>, cudaFuncAttributeMaxDynamicSharedMemorySize, PROJ_SMEM);
    cudaFuncSetAttribute(proj_mma<CIN, 1>, cudaFuncAttributeMaxDynamicSharedMemorySize, PROJ_SMEM);
    cudaFuncSetAttribute(proj_mma<CIN, 2>, cudaFuncAttributeMaxDynamicSharedMemorySize, PROJ_SMEM);
    cudaFuncSetAttribute(proj_mma<HALF, 3>, cudaFuncAttributeMaxDynamicSharedMemorySize, PROJ_SMEM);

    proj_mma<CIN, 0><<<dim3(NPIX / 128, HALF / 128), 256, PROJ_SMEM>>>(
        whi[0], wlo[0], xthi, xtlo, q_g, q_b, q_m, q_v, qscale, gq, nullptr);
    proj_mma<CIN, 1><<<dim3(NPIX / 128, HALF / 128), 256, PROJ_SMEM>>>(
        whi[1], wlo[1], xthi, xtlo, k_g, k_b, k_m, k_v, 1.f, gkp, nullptr);
    proj_mma<CIN, 2><<<dim3(NPIX / 128, HALF / 128), 256, PROJ_SMEM>>>(
        whi[2], wlo[2], xthi, xtlo, v_g, v_b, v_m, v_v, 1.f, gvp, nullptr);

    // attn = q x kp per patch
    attn_kernel<<<dim3(8, NUM), 256>>>(gq, gkp, gattn);

    // flash (nested softmax attention) -> bf16 hi/lo transposed
    const int fl_smem = (4 * 64 * QTS + 64 * 16 + 4 * 64) * (int)sizeof(float);
    cudaFuncSetAttribute(flash2_kernel, cudaFuncAttributeMaxDynamicSharedMemorySize, fl_smem);
    flash2_kernel<<<dim3(16, NUM), 256, fl_smem>>>(gattn, gvp, pthi, ptlo);

    // o projection + residual -> d_out
    proj_mma<HALF, 3><<<dim3(NPIX / 128, CIN / 128), 256, PROJ_SMEM>>>(
        whi[3], wlo[3], pthi, ptlo, o_g, o_b, o_m, o_v, 1.f, out, x);
}

// round 10
// speedup vs baseline: 22.1497x; 1.2767x over previous
#include <cuda_runtime.h>
#include <cuda_bf16.h>
#include <cstdint>
#include <math.h>

#define HH 256
#define WW 256
#define NPIX 65536          // H*W
#define CIN 512
#define HALF 256
#define PSZ 32
#define NH 8
#define NUM 64              // patches
#define EPS 1e-5f

// ==================== mma.sync / ldmatrix helpers (plain sm_80+ PTX) ====================
__device__ __forceinline__ uint32_t smem_to_u32(const void* smem_ptr) {
    uint32_t addr;
    asm("{ .reg .u64 tmp; cvta.to.shared.u64 tmp, %1; cvt.u32.u64 %0, tmp; }"
        : "=r"(addr) : "l"(smem_ptr));
    return addr;
}
__device__ __forceinline__ void ldsm4(uint32_t* r, uint32_t addr) {
    asm volatile("ldmatrix.sync.aligned.m8n8.x4.shared.b16 {%0,%1,%2,%3}, [%4];"
        : "=r"(r[0]), "=r"(r[1]), "=r"(r[2]), "=r"(r[3]) : "r"(addr));
}
__device__ __forceinline__ void ldsm4t(uint32_t* r, uint32_t addr) {
    asm volatile("ldmatrix.sync.aligned.m8n8.x4.trans.shared.b16 {%0,%1,%2,%3}, [%4];"
        : "=r"(r[0]), "=r"(r[1]), "=r"(r[2]), "=r"(r[3]) : "r"(addr));
}
__device__ __forceinline__ void mma16816(float* c, const uint32_t* a, const uint32_t* b) {
    asm volatile(
        "mma.sync.aligned.m16n8k16.row.col.f32.bf16.bf16.f32 "
        "{%0,%1,%2,%3}, {%4,%5,%6,%7}, {%8,%9}, {%0,%1,%2,%3};"
        : "+f"(c[0]), "+f"(c[1]), "+f"(c[2]), "+f"(c[3])
        : "r"(a[0]), "r"(a[1]), "r"(a[2]), "r"(a[3]), "r"(b[0]), "r"(b[1]));
}
__device__ __forceinline__ uint32_t packbf2(float lo, float hi) {
    __nv_bfloat162 h = __floats2bfloat162_rn(lo, hi);
    return *(uint32_t*)&h;
}

// ==================== static scratch ====================
__device__ __nv_bfloat16 g_xthi[(size_t)NPIX * CIN];   // x transposed hi, [pix][512]
__device__ __nv_bfloat16 g_xtlo[(size_t)NPIX * CIN];   // x transposed lo
__device__ __nv_bfloat16 g_pthi[(size_t)NPIX * HALF];  // attn-out transposed hi, [pix][256]
__device__ __nv_bfloat16 g_ptlo[(size_t)NPIX * HALF];
__device__ __nv_bfloat16 g_whi[4][CIN * HALF];         // q,k,v,o weights hi
__device__ __nv_bfloat16 g_wlo[4][CIN * HALF];
__device__ float g_q[(size_t)HALF * NPIX];             // q projection image [c][pix]
__device__ float g_attn[(size_t)NUM * 1024 * 64];      // attn per patch (fp32)
__device__ __nv_bfloat16 g_ahi[(size_t)NUM * 1024 * 64];   // attn bf16 hi
__device__ __nv_bfloat16 g_alo[(size_t)NUM * 1024 * 64];   // attn bf16 lo
__device__ float g_kp[HALF * NUM];                     // pooled k [c][patch]
__device__ float g_vp[NUM * HALF];                     // pooled v [patch][c]

// ==================== conversion kernels ====================
__global__ void conv_w_kernel(const float* __restrict__ w,
                              __nv_bfloat16* __restrict__ hi,
                              __nv_bfloat16* __restrict__ lo, int n)
{
    int i = blockIdx.x * 256 + threadIdx.x;
    if (i < n) {
        float v = w[i];
        __nv_bfloat16 h = __float2bfloat16(v);
        hi[i] = h;
        lo[i] = __float2bfloat16(v - __bfloat162float(h));
    }
}

// x [512][NPIX] fp32 -> XT [NPIX][512] bf16 hi/lo  (32x32 tile transpose)
__global__ void conv_x_kernel(const float* __restrict__ x,
                              __nv_bfloat16* __restrict__ hi,
                              __nv_bfloat16* __restrict__ lo)
{
    __shared__ float t[32][33];
    const int p0 = blockIdx.x * 32;
    const int k0 = blockIdx.y * 32;
    const int tx = threadIdx.x, ty = threadIdx.y;   // (32, 8)
    #pragma unroll
    for (int i = 0; i < 4; i++) {
        int kl = ty + i * 8;
        t[kl][tx] = x[(size_t)(k0 + kl) * NPIX + p0 + tx];
    }
    __syncthreads();
    #pragma unroll
    for (int i = 0; i < 4; i++) {
        int pl = ty + i * 8;
        float v = t[tx][pl];
        __nv_bfloat16 h = __float2bfloat16(v);
        size_t off = (size_t)(p0 + pl) * CIN + k0 + tx;
        hi[off] = h;
        lo[off] = __float2bfloat16(v - __bfloat162float(h));
    }
}

__global__ void zero_pool_kernel(float* kp, float* vp)
{
    int i = blockIdx.x * 256 + threadIdx.x;   // grid 64 -> 16384
    kp[i] = 0.f;
    vp[i] = 0.f;
}

// ==================== HMMA (mma.sync) projection GEMM ====================
#define LDKB 144                    // smem row stride in bytes (72 bf16)
#define TILE_BYTES (128 * LDKB)     // 18432 per tensor tile
#define PROJ_SMEM (4 * TILE_BYTES)  // 73728
template <int KDIM, int MODE>
__global__ void __launch_bounds__(256, 2)
proj_mma(const __nv_bfloat16* __restrict__ Ahi, const __nv_bfloat16* __restrict__ Alo,
         const __nv_bfloat16* __restrict__ Bhi, const __nv_bfloat16* __restrict__ Blo,
         const float* __restrict__ gg, const float* __restrict__ bb,
         const float* __restrict__ mm, const float* __restrict__ vv,
         float postscale, float* __restrict__ outp, const float* __restrict__ resid)
{
    extern __shared__ char smc[];
    const uint32_t sb = smem_to_u32(smc);
    const uint32_t baseA[2] = { sb, sb + TILE_BYTES };
    const uint32_t baseB[2] = { sb + 2 * TILE_BYTES, sb + 3 * TILE_BYTES };

    const int tid = threadIdx.x;
    const int wid = tid >> 5;
    const int lane = tid & 31;
    const int wm = wid & 1;
    const int wn = wid >> 1;
    const int bm = blockIdx.y;
    const int pixbase = blockIdx.x * 128;

    float acc[4][4][4];
    #pragma unroll
    for (int mt = 0; mt < 4; mt++)
        #pragma unroll
        for (int nt = 0; nt < 4; nt++)
            #pragma unroll
            for (int e = 0; e < 4; e++) acc[mt][nt][e] = 0.f;

    const int am_ = lane & 15;
    const int ak_ = (lane >> 4) * 8;
    const int bn_ = (lane & 7) + ((lane >> 4) << 3);
    const int bk_ = ((lane >> 3) & 1) * 8;

    const int lr[4] = { (tid + 0) >> 3, (tid + 256) >> 3, (tid + 512) >> 3, (tid + 768) >> 3 };
    const int lc = tid & 7;

    const int NCH = KDIM / 64;
    for (int ch = 0; ch < NCH; ch++) {
        const int kc0 = ch * 64;
        #pragma unroll
        for (int j = 0; j < 4; j++) {
            const int r = lr[j];
            const size_t arow = (size_t)(bm * 128 + r) * KDIM + kc0 + lc * 8;
            const size_t brow = (size_t)(pixbase + r) * KDIM + kc0 + lc * 8;
            *(uint4*)(smc + 0 * TILE_BYTES + r * LDKB + lc * 16) = *(const uint4*)(Ahi + arow);
            *(uint4*)(smc + 1 * TILE_BYTES + r * LDKB + lc * 16) = *(const uint4*)(Alo + arow);
            *(uint4*)(smc + 2 * TILE_BYTES + r * LDKB + lc * 16) = *(const uint4*)(Bhi + brow);
            *(uint4*)(smc + 3 * TILE_BYTES + r * LDKB + lc * 16) = *(const uint4*)(Blo + brow);
        }
        __syncthreads();

        #pragma unroll
        for (int ks = 0; ks < 4; ks++) {
            const int kc = ks * 16;
            uint32_t a[4][4], bh[4][2], bl[4][2];
            #pragma unroll
            for (int mt = 0; mt < 4; mt++)
                ldsm4(a[mt], baseA[0] + (wm * 64 + mt * 16 + am_) * LDKB + (kc + ak_) * 2);
            #pragma unroll
            for (int pr = 0; pr < 2; pr++) {
                uint32_t r4[4];
                ldsm4(r4, baseB[0] + (wn * 32 + pr * 16 + bn_) * LDKB + (kc + bk_) * 2);
                bh[2 * pr][0] = r4[0]; bh[2 * pr][1] = r4[1];
                bh[2 * pr + 1][0] = r4[2]; bh[2 * pr + 1][1] = r4[3];
            }
            #pragma unroll
            for (int mt = 0; mt < 4; mt++)
                #pragma unroll
                for (int nt = 0; nt < 4; nt++) mma16816(acc[mt][nt], a[mt], bh[nt]);
            #pragma unroll
            for (int pr = 0; pr < 2; pr++) {
                uint32_t r4[4];
                ldsm4(r4, baseB[1] + (wn * 32 + pr * 16 + bn_) * LDKB + (kc + bk_) * 2);
                bl[2 * pr][0] = r4[0]; bl[2 * pr][1] = r4[1];
                bl[2 * pr + 1][0] = r4[2]; bl[2 * pr + 1][1] = r4[3];
            }
            #pragma unroll
            for (int mt = 0; mt < 4; mt++)
                #pragma unroll
                for (int nt = 0; nt < 4; nt++) mma16816(acc[mt][nt], a[mt], bl[nt]);
            #pragma unroll
            for (int mt = 0; mt < 4; mt++)
                ldsm4(a[mt], baseA[1] + (wm * 64 + mt * 16 + am_) * LDKB + (kc + ak_) * 2);
            #pragma unroll
            for (int mt = 0; mt < 4; mt++)
                #pragma unroll
                for (int nt = 0; nt < 4; nt++) mma16816(acc[mt][nt], a[mt], bh[nt]);
        }
        __syncthreads();
    }

    if (MODE == 1 || MODE == 2) {
        const int x0 = (pixbase & 255) + wn * 32;
        const int y0 = pixbase >> 8;
        const int p = ((y0 >> 5) << 3) + (x0 >> 5);
        const float inv = 1.f / 1024.f;
        #pragma unroll
        for (int mt = 0; mt < 4; mt++) {
            #pragma unroll
            for (int hf = 0; hf < 2; hf++) {
                const int o = bm * 128 + wm * 64 + mt * 16 + (lane >> 2) + hf * 8;
                const float s_r = gg[o] * rsqrtf(vv[o] + EPS);
                const float t_r = bb[o] - mm[o] * s_r;
                float s = 0.f;
                #pragma unroll
                for (int nt = 0; nt < 4; nt++) {
                    s += fmaxf(acc[mt][nt][2 * hf + 0] * s_r + t_r, 0.f);
                    s += fmaxf(acc[mt][nt][2 * hf + 1] * s_r + t_r, 0.f);
                }
                s += __shfl_xor_sync(0xffffffffu, s, 1);
                s += __shfl_xor_sync(0xffffffffu, s, 2);
                if ((lane & 3) == 0) {
                    if (MODE == 1) atomicAdd(outp + o * NUM + p, s * inv);
                    else           atomicAdd(outp + p * HALF + o, s * inv);
                }
            }
        }
    } else {
        float* stage = (float*)smc;
        float* scb = (float*)(smc + 68608);
        float* bob = (float*)(smc + 69632);
        if (tid < 128) {
            const int o = bm * 128 + tid;
            const float s_r = gg[o] * rsqrtf(vv[o] + EPS);
            scb[tid] = s_r;
            bob[tid] = bb[o] - mm[o] * s_r;
        }
        __syncthreads();
        #pragma unroll
        for (int mt = 0; mt < 4; mt++) {
            const int r_lo = wm * 64 + mt * 16 + (lane >> 2);
            #pragma unroll
            for (int nt = 0; nt < 4; nt++) {
                const int c = wn * 32 + nt * 8 + (lane & 3) * 2;
                stage[r_lo * 130 + c]     = fmaxf(acc[mt][nt][0] * scb[r_lo] + bob[r_lo], 0.f) * postscale;
                stage[r_lo * 130 + c + 1] = fmaxf(acc[mt][nt][1] * scb[r_lo] + bob[r_lo], 0.f) * postscale;
                stage[(r_lo + 8) * 130 + c]     = fmaxf(acc[mt][nt][2] * scb[r_lo + 8] + bob[r_lo + 8], 0.f) * postscale;
                stage[(r_lo + 8) * 130 + c + 1] = fmaxf(acc[mt][nt][3] * scb[r_lo + 8] + bob[r_lo + 8], 0.f) * postscale;
            }
        }
        __syncthreads();
        for (int i = tid; i < 128 * 128; i += 256) {
            const int r = i >> 7;
            const int c = i & 127;
            float v = stage[r * 130 + c];
            const size_t go = (size_t)(bm * 128 + r) * NPIX + pixbase + c;
            if (MODE == 3) v += resid[go];
            outp[go] = v;
        }
    }
}

// ---------------- attn = q_b^T (1024x256) x kp (256x64), per patch ----------------
// Emits fp32 + bf16 hi/lo versions of A (flash3 consumes hi/lo via mma).
__global__ void __launch_bounds__(256)
attn_kernel(const float* __restrict__ q, const float* __restrict__ kp,
            float* __restrict__ attn,
            __nv_bfloat16* __restrict__ ahi, __nv_bfloat16* __restrict__ alo)
{
    __shared__ float Qs[8][128];
    __shared__ float Ks[8][64];
    const int blk = blockIdx.x;
    const int b = blockIdx.y;
    const int ph = b >> 3, pw = b & 7;
    const int tid = threadIdx.x;
    const int tx = tid & 15;
    const int ty = tid >> 4;

    float acc[8][4];
    #pragma unroll
    for (int i = 0; i < 8; i++)
        #pragma unroll
        for (int j = 0; j < 4; j++) acc[i][j] = 0.f;

    const int pixbase = ph * 32 * WW + pw * 32;
    const int n_l = tid & 127;
    const int c0 = tid >> 7;
    const int n = blk * 128 + n_l;
    const int pix = pixbase + (n >> 5) * WW + (n & 31);

    for (int kt = 0; kt < HALF / 8; kt++) {
        #pragma unroll
        for (int i = 0; i < 4; i++) {
            const int cl = c0 + i * 2;
            Qs[cl][n_l] = q[(size_t)(kt * 8 + cl) * NPIX + pix];
        }
        #pragma unroll
        for (int i = 0; i < 2; i++) {
            const int e = tid + i * 256;
            Ks[e >> 6][e & 63] = kp[(kt * 8 + (e >> 6)) * NUM + (e & 63)];
        }
        __syncthreads();
        #pragma unroll
        for (int k = 0; k < 8; k++) {
            float a[8], bm4[4];
            *(float4*)(a)     = *(const float4*)&Qs[k][ty * 8];
            *(float4*)(a + 4) = *(const float4*)&Qs[k][ty * 8 + 4];
            *(float4*)(bm4)   = *(const float4*)&Ks[k][tx * 4];
            #pragma unroll
            for (int i = 0; i < 8; i++)
                #pragma unroll
                for (int j = 0; j < 4; j++) acc[i][j] += a[i] * bm4[j];
        }
        __syncthreads();
    }
    #pragma unroll
    for (int i = 0; i < 8; i++) {
        const size_t off = ((size_t)b * 1024 + blk * 128 + ty * 8 + i) * 64 + tx * 4;
        *(float4*)&attn[off] = *(float4*)acc[i];
        uint2 uh, ul;
        float h0 = __bfloat162float(__float2bfloat16(acc[i][0]));
        float h1 = __bfloat162float(__float2bfloat16(acc[i][1]));
        float h2 = __bfloat162float(__float2bfloat16(acc[i][2]));
        float h3 = __bfloat162float(__float2bfloat16(acc[i][3]));
        uh.x = packbf2(acc[i][0], acc[i][1]);
        uh.y = packbf2(acc[i][2], acc[i][3]);
        ul.x = packbf2(acc[i][0] - h0, acc[i][1] - h1);
        ul.y = packbf2(acc[i][2] - h2, acc[i][3] - h3);
        *(uint2*)(ahi + off) = uh;
        *(uint2*)(alo + off) = ul;
    }
}

// ==================== flash v3: mma.sync nested-softmax attention ====================
// Block = (64-row chunk, patch). 8 warps: wm (2) x wn (4).
// GEMM1: S(64x64) = Q·K^T (split bf16, 3 passes). Online softmax.
// GEMM2: O += P·V with P register-resident (C-frag -> A-frag reinterpret), split P/V.
// Final: fv = A + O/l, softmax over 64, out = fv x vp, bf16 hi/lo transposed store.
#define FLDB 144                 // bf16 tile stride bytes
#define F_QHI 0
#define F_QLO 9216
#define F_KHI 18432
#define F_KLO 27648
#define F_REDM 36864             // float[64][4]
#define F_REDS 37888             // float[64][4]
#define F_MS   38912             // float[64]
#define F_LS   39168
#define F_SCS  39424
#define F_MNS  39680
#define F_REDF 39936             // float[64][16]
#define F_TOTAL 44032
// overlays: OSUM (stride 66 f32) at 0; PS (stride 68 f32) at 18432; STG (stride 65) at 0
__global__ void __launch_bounds__(256, 2)
flash3_kernel(const float* __restrict__ attn,
              const __nv_bfloat16* __restrict__ ahi, const __nv_bfloat16* __restrict__ alo,
              const float* __restrict__ vp,
              __nv_bfloat16* __restrict__ pthi, __nv_bfloat16* __restrict__ ptlo)
{
    extern __shared__ char smc[];
    const uint32_t sb = smem_to_u32(smc);
    float* REDM = (float*)(smc + F_REDM);
    float* REDS = (float*)(smc + F_REDS);
    float* m_s  = (float*)(smc + F_MS);
    float* l_s  = (float*)(smc + F_LS);
    float* sc_s = (float*)(smc + F_SCS);
    float* mn_s = (float*)(smc + F_MNS);
    float* REDF = (float*)(smc + F_REDF);

    const int rblk = blockIdx.x;    // 0..15
    const int b = blockIdx.y;       // patch
    const int tid = threadIdx.x;
    const int lane = tid & 31;
    const int wid = tid >> 5;
    const int wm = wid >> 2;        // 0..1
    const int wn = wid & 3;         // 0..3
    const int r0 = rblk * 64;
    const size_t abase = (size_t)b * 1024 * 64;

    if (tid < 64) { m_s[tid] = -1e30f; l_s[tid] = 0.f; }

    // load Q tile (rows r0..r0+63) bf16 hi/lo into smem
    {
        #pragma unroll
        for (int i = 0; i < 2; i++) {
            const int idx = tid + i * 256;
            const int r = idx >> 3;
            const int c = idx & 7;
            const size_t g = abase + (size_t)(r0 + r) * 64 + c * 8;
            *(uint4*)(smc + F_QHI + r * FLDB + c * 16) = *(const uint4*)(ahi + g);
            *(uint4*)(smc + F_QLO + r * FLDB + c * 16) = *(const uint4*)(alo + g);
        }
    }

    // ldmatrix lane address components
    const int am_ = lane & 15;
    const int ak_ = (lane >> 4) * 8;
    const int bn_ = (lane & 7) + ((lane >> 4) << 3);
    const int bk_ = ((lane >> 3) & 1) * 8;
    const int vk_ = lane & 15;
    const int vn_ = (lane >> 4) << 3;
    const int grp = lane >> 2;       // fragment row group
    const int qd  = lane & 3;        // fragment col quad

    float O[2][8][4];
    #pragma unroll
    for (int mt = 0; mt < 2; mt++)
        #pragma unroll
        for (int n8 = 0; n8 < 8; n8++)
            #pragma unroll
            for (int e = 0; e < 4; e++) O[mt][n8][e] = 0.f;

    for (int t = 0; t < 16; t++) {
        __syncthreads();   // K region free, REDS(t-1) complete
        if (t > 0 && tid < 64) {
            l_s[tid] = l_s[tid] * sc_s[tid]
                     + REDS[tid * 4 + 0] + REDS[tid * 4 + 1]
                     + REDS[tid * 4 + 2] + REDS[tid * 4 + 3];
        }
        // load K/V tile t
        #pragma unroll
        for (int i = 0; i < 2; i++) {
            const int idx = tid + i * 256;
            const int r = idx >> 3;
            const int c = idx & 7;
            const size_t g = abase + (size_t)(t * 64 + r) * 64 + c * 8;
            *(uint4*)(smc + F_KHI + r * FLDB + c * 16) = *(const uint4*)(ahi + g);
            *(uint4*)(smc + F_KLO + r * FLDB + c * 16) = *(const uint4*)(alo + g);
        }
        __syncthreads();

        // ---- GEMM1: S = Q K^T (3-term split) ----
        float S[2][2][4];
        #pragma unroll
        for (int mt = 0; mt < 2; mt++)
            #pragma unroll
            for (int nt = 0; nt < 2; nt++)
                #pragma unroll
                for (int e = 0; e < 4; e++) S[mt][nt][e] = 0.f;
        #pragma unroll
        for (int ks = 0; ks < 4; ks++) {
            const int kc = ks * 16;
            uint32_t a[2][4], bh[2][2], bl[2][2];
            #pragma unroll
            for (int mt = 0; mt < 2; mt++)
                ldsm4(a[mt], sb + F_QHI + (wm * 32 + mt * 16 + am_) * FLDB + (kc + ak_) * 2);
            {
                uint32_t r4[4];
                ldsm4(r4, sb + F_KHI + (wn * 16 + bn_) * FLDB + (kc + bk_) * 2);
                bh[0][0] = r4[0]; bh[0][1] = r4[1]; bh[1][0] = r4[2]; bh[1][1] = r4[3];
            }
            #pragma unroll
            for (int mt = 0; mt < 2; mt++)
                #pragma unroll
                for (int nt = 0; nt < 2; nt++) mma16816(S[mt][nt], a[mt], bh[nt]);
            {
                uint32_t r4[4];
                ldsm4(r4, sb + F_KLO + (wn * 16 + bn_) * FLDB + (kc + bk_) * 2);
                bl[0][0] = r4[0]; bl[0][1] = r4[1]; bl[1][0] = r4[2]; bl[1][1] = r4[3];
            }
            #pragma unroll
            for (int mt = 0; mt < 2; mt++)
                #pragma unroll
                for (int nt = 0; nt < 2; nt++) mma16816(S[mt][nt], a[mt], bl[nt]);
            #pragma unroll
            for (int mt = 0; mt < 2; mt++)
                ldsm4(a[mt], sb + F_QLO + (wm * 32 + mt * 16 + am_) * FLDB + (kc + ak_) * 2);
            #pragma unroll
            for (int mt = 0; mt < 2; mt++)
                #pragma unroll
                for (int nt = 0; nt < 2; nt++) mma16816(S[mt][nt], a[mt], bh[nt]);
        }

        // ---- local row max -> cross-warp reduce ----
        #pragma unroll
        for (int mt = 0; mt < 2; mt++) {
            float la = fmaxf(fmaxf(S[mt][0][0], S[mt][0][1]), fmaxf(S[mt][1][0], S[mt][1][1]));
            float lb = fmaxf(fmaxf(S[mt][0][2], S[mt][0][3]), fmaxf(S[mt][1][2], S[mt][1][3]));
            la = fmaxf(la, __shfl_xor_sync(0xffffffffu, la, 1));
            la = fmaxf(la, __shfl_xor_sync(0xffffffffu, la, 2));
            lb = fmaxf(lb, __shfl_xor_sync(0xffffffffu, lb, 1));
            lb = fmaxf(lb, __shfl_xor_sync(0xffffffffu, lb, 2));
            if (qd == 0) {
                const int r1 = wm * 32 + mt * 16 + grp;
                REDM[r1 * 4 + wn] = la;
                REDM[(r1 + 8) * 4 + wn] = lb;
            }
        }
        __syncthreads();
        if (tid < 64) {
            float mt_ = fmaxf(fmaxf(REDM[tid * 4], REDM[tid * 4 + 1]),
                              fmaxf(REDM[tid * 4 + 2], REDM[tid * 4 + 3]));
            const float mo = m_s[tid];
            const float mn = fmaxf(mo, mt_);
            sc_s[tid] = __expf(mo - mn);
            mn_s[tid] = mn;
            m_s[tid] = mn;
        }
        __syncthreads();

        // ---- P = exp(S-m), row sums, pack A-frags, rescale O ----
        uint32_t aPh[2][4], aPl[2][4];
        #pragma unroll
        for (int mt = 0; mt < 2; mt++) {
            const int r1 = wm * 32 + mt * 16 + grp;
            const float mna = mn_s[r1];
            const float mnb = mn_s[r1 + 8];
            float P[2][4];
            #pragma unroll
            for (int nt = 0; nt < 2; nt++) {
                P[nt][0] = __expf(S[mt][nt][0] - mna);
                P[nt][1] = __expf(S[mt][nt][1] - mna);
                P[nt][2] = __expf(S[mt][nt][2] - mnb);
                P[nt][3] = __expf(S[mt][nt][3] - mnb);
            }
            float ra = P[0][0] + P[0][1] + P[1][0] + P[1][1];
            float rb = P[0][2] + P[0][3] + P[1][2] + P[1][3];
            ra += __shfl_xor_sync(0xffffffffu, ra, 1);
            ra += __shfl_xor_sync(0xffffffffu, ra, 2);
            rb += __shfl_xor_sync(0xffffffffu, rb, 1);
            rb += __shfl_xor_sync(0xffffffffu, rb, 2);
            if (qd == 0) {
                REDS[r1 * 4 + wn] = ra;
                REDS[(r1 + 8) * 4 + wn] = rb;
            }
            // pack A fragments: a0,a1 from nt=0 (k 0-7), a2,a3 from nt=1 (k 8-15)
            aPh[mt][0] = packbf2(P[0][0], P[0][1]);
            aPh[mt][1] = packbf2(P[0][2], P[0][3]);
            aPh[mt][2] = packbf2(P[1][0], P[1][1]);
            aPh[mt][3] = packbf2(P[1][2], P[1][3]);
            float l00 = P[0][0] - __bfloat162float(__float2bfloat16(P[0][0]));
            float l01 = P[0][1] - __bfloat162float(__float2bfloat16(P[0][1]));
            float l02 = P[0][2] - __bfloat162float(__float2bfloat16(P[0][2]));
            float l03 = P[0][3] - __bfloat162float(__float2bfloat16(P[0][3]));
            float l10 = P[1][0] - __bfloat162float(__float2bfloat16(P[1][0]));
            float l11 = P[1][1] - __bfloat162float(__float2bfloat16(P[1][1]));
            float l12 = P[1][2] - __bfloat162float(__float2bfloat16(P[1][2]));
            float l13 = P[1][3] - __bfloat162float(__float2bfloat16(P[1][3]));
            aPl[mt][0] = packbf2(l00, l01);
            aPl[mt][1] = packbf2(l02, l03);
            aPl[mt][2] = packbf2(l10, l11);
            aPl[mt][3] = packbf2(l12, l13);
            // rescale O rows
            const float sa = sc_s[r1];
            const float sbx = sc_s[r1 + 8];
            #pragma unroll
            for (int n8 = 0; n8 < 8; n8++) {
                O[mt][n8][0] *= sa; O[mt][n8][1] *= sa;
                O[mt][n8][2] *= sbx; O[mt][n8][3] *= sbx;
            }
        }

        // ---- GEMM2: O += P V (3-term split); V via trans-ldsm, k-slice = wn*16 ----
        #pragma unroll
        for (int g = 0; g < 4; g++) {
            const int n0 = g * 16;
            uint32_t vh[4], vl[4];
            ldsm4t(vh, sb + F_KHI + (wn * 16 + vk_) * FLDB + (n0 + vn_) * 2);
            ldsm4t(vl, sb + F_KLO + (wn * 16 + vk_) * FLDB + (n0 + vn_) * 2);
            uint32_t b0h[2] = { vh[0], vh[1] }, b1h[2] = { vh[2], vh[3] };
            uint32_t b0l[2] = { vl[0], vl[1] }, b1l[2] = { vl[2], vl[3] };
            #pragma unroll
            for (int mt = 0; mt < 2; mt++) {
                mma16816(O[mt][2 * g + 0], aPh[mt], b0h);
                mma16816(O[mt][2 * g + 1], aPh[mt], b1h);
                mma16816(O[mt][2 * g + 0], aPh[mt], b0l);
                mma16816(O[mt][2 * g + 1], aPh[mt], b1l);
                mma16816(O[mt][2 * g + 0], aPl[mt], b0h);
                mma16816(O[mt][2 * g + 1], aPl[mt], b1h);
            }
        }
    }
    __syncthreads();
    if (tid < 64) {
        l_s[tid] = l_s[tid] * sc_s[tid]
                 + REDS[tid * 4 + 0] + REDS[tid * 4 + 1]
                 + REDS[tid * 4 + 2] + REDS[tid * 4 + 3];
    }

    // ---- reduce O across wn warps into OSUM (overlay on Q region) ----
    float* Os = (float*)(smc + 0);          // [64][66]
    for (int i = tid; i < 64 * 66; i += 256) Os[i] = 0.f;
    __syncthreads();
    #pragma unroll 1
    for (int p = 0; p < 4; p++) {
        if (wn == p) {
            #pragma unroll
            for (int mt = 0; mt < 2; mt++) {
                const int r1 = wm * 32 + mt * 16 + grp;
                #pragma unroll
                for (int n8 = 0; n8 < 8; n8++) {
                    const int c = n8 * 8 + qd * 2;
                    Os[r1 * 66 + c]       += O[mt][n8][0];
                    Os[r1 * 66 + c + 1]   += O[mt][n8][1];
                    Os[(r1 + 8) * 66 + c]     += O[mt][n8][2];
                    Os[(r1 + 8) * 66 + c + 1] += O[mt][n8][3];
                }
            }
        }
        __syncthreads();
    }

    // ---- final: fv = A + O/l, softmax over 64 (old-style thread layout) ----
    const int txx = tid & 15;
    const int tyy = tid >> 4;
    float fv[4][4];
    #pragma unroll
    for (int i = 0; i < 4; i++) {
        const int rr = tyy * 4 + i;
        const float linv = 1.f / l_s[rr];
        float4 qv = *(const float4*)(attn + abase + (size_t)(r0 + rr) * 64 + txx * 4);
        fv[i][0] = qv.x + Os[rr * 66 + txx * 4 + 0] * linv;
        fv[i][1] = qv.y + Os[rr * 66 + txx * 4 + 1] * linv;
        fv[i][2] = qv.z + Os[rr * 66 + txx * 4 + 2] * linv;
        fv[i][3] = qv.w + Os[rr * 66 + txx * 4 + 3] * linv;
    }
    #pragma unroll
    for (int i = 0; i < 4; i++) {
        float lm = fmaxf(fmaxf(fv[i][0], fv[i][1]), fmaxf(fv[i][2], fv[i][3]));
        REDF[(tyy * 4 + i) * 16 + txx] = lm;
    }
    __syncthreads();
    if (tid < 64) {
        float mt_ = REDF[tid * 16];
        #pragma unroll
        for (int j = 1; j < 16; j++) mt_ = fmaxf(mt_, REDF[tid * 16 + j]);
        mn_s[tid] = mt_;
    }
    __syncthreads();
    #pragma unroll
    for (int i = 0; i < 4; i++) {
        const int rr = tyy * 4 + i;
        const float mn = mn_s[rr];
        float rs = 0.f;
        #pragma unroll
        for (int j = 0; j < 4; j++) { fv[i][j] = __expf(fv[i][j] - mn); rs += fv[i][j]; }
        REDF[rr * 16 + txx] = rs;
    }
    __syncthreads();
    if (tid < 64) {
        float su = REDF[tid * 16];
        #pragma unroll
        for (int j = 1; j < 16; j++) su += REDF[tid * 16 + j];
        l_s[tid] = 1.f / su;
    }
    __syncthreads();
    float* Ps = (float*)(smc + F_KHI);      // [64][68] overlay on K region
    #pragma unroll
    for (int i = 0; i < 4; i++) {
        const int rr = tyy * 4 + i;
        const float inv = l_s[rr];
        *(float4*)&Ps[rr * 68 + txx * 4] =
            make_float4(fv[i][0] * inv, fv[i][1] * inv, fv[i][2] * inv, fv[i][3] * inv);
    }
    __syncthreads();

    // ---- out GEMM: out[64][256] = P_final[64][64] x vp[64][256] ----
    float acc[4][16];
    #pragma unroll
    for (int i = 0; i < 4; i++)
        #pragma unroll
        for (int j = 0; j < 16; j++) acc[i][j] = 0.f;
    #pragma unroll 2
    for (int m = 0; m < 64; m++) {
        float pr[4];
        #pragma unroll
        for (int i = 0; i < 4; i++) pr[i] = Ps[(tyy * 4 + i) * 68 + m];
        const float4* vr = (const float4*)(vp + m * 256 + txx * 16);
        float4 v0 = vr[0], v1 = vr[1], v2 = vr[2], v3 = vr[3];
        const float vw[16] = {v0.x, v0.y, v0.z, v0.w, v1.x, v1.y, v1.z, v1.w,
                              v2.x, v2.y, v2.z, v2.w, v3.x, v3.y, v3.z, v3.w};
        #pragma unroll
        for (int i = 0; i < 4; i++)
            #pragma unroll
            for (int j = 0; j < 16; j++) acc[i][j] += pr[i] * vw[j];
    }

    // ---- staged transposed bf16 hi/lo store ----
    const int ph = b >> 3, pw = b & 7;
    const int pixbase = ph * 32 * WW + pw * 32;
    float* stg = (float*)(smc + 0);         // [64][65] overlay (Os dead)
    #pragma unroll 1
    for (int g = 0; g < 4; g++) {
        __syncthreads();
        if ((txx >> 2) == g) {
            const int txl = txx & 3;
            #pragma unroll
            for (int i = 0; i < 4; i++)
                #pragma unroll
                for (int j = 0; j < 16; j++)
                    stg[(tyy * 4 + i) * 65 + txl * 16 + j] = acc[i][j];
        }
        __syncthreads();
        const int rl = tid >> 2;
        const int cc0 = (tid & 3) * 16;
        const int n = r0 + rl;
        const int pix = pixbase + (n >> 5) * WW + (n & 31);
        #pragma unroll
        for (int k2 = 0; k2 < 16; k2++) {
            float v = stg[rl * 65 + cc0 + k2];
            __nv_bfloat16 h = __float2bfloat16(v);
            const size_t off = (size_t)pix * HALF + g * 64 + cc0 + k2;
            pthi[off] = h;
            ptlo[off] = __float2bfloat16(v - __bfloat162float(h));
        }
    }
}

// ==================== launch ====================
extern "C" void kernel_launch(void* const* d_in, const int* in_sizes, int n_in,
                              void* d_out, int out_size)
{
    const float* x   = (const float*)d_in[0];
    const float* q_w = (const float*)d_in[1];
    const float* q_g = (const float*)d_in[2];
    const float* q_b = (const float*)d_in[3];
    const float* q_m = (const float*)d_in[4];
    const float* q_v = (const float*)d_in[5];
    const float* k_w = (const float*)d_in[6];
    const float* k_g = (const float*)d_in[7];
    const float* k_b = (const float*)d_in[8];
    const float* k_m = (const float*)d_in[9];
    const float* k_v = (const float*)d_in[10];
    const float* v_w = (const float*)d_in[11];
    const float* v_g = (const float*)d_in[12];
    const float* v_b = (const float*)d_in[13];
    const float* v_m = (const float*)d_in[14];
    const float* v_v = (const float*)d_in[15];
    const float* o_w = (const float*)d_in[16];
    const float* o_g = (const float*)d_in[17];
    const float* o_b = (const float*)d_in[18];
    const float* o_m = (const float*)d_in[19];
    const float* o_v = (const float*)d_in[20];
    float* out = (float*)d_out;

    __nv_bfloat16 *xthi, *xtlo, *pthi, *ptlo, *ahi, *alo;
    __nv_bfloat16 (*whi)[CIN * HALF], (*wlo)[CIN * HALF];
    float *gq, *gattn, *gkp, *gvp;
    cudaGetSymbolAddress((void**)&xthi, g_xthi);
    cudaGetSymbolAddress((void**)&xtlo, g_xtlo);
    cudaGetSymbolAddress((void**)&pthi, g_pthi);
    cudaGetSymbolAddress((void**)&ptlo, g_ptlo);
    cudaGetSymbolAddress((void**)&ahi, g_ahi);
    cudaGetSymbolAddress((void**)&alo, g_alo);
    cudaGetSymbolAddress((void**)&whi, g_whi);
    cudaGetSymbolAddress((void**)&wlo, g_wlo);
    cudaGetSymbolAddress((void**)&gq, g_q);
    cudaGetSymbolAddress((void**)&gattn, g_attn);
    cudaGetSymbolAddress((void**)&gkp, g_kp);
    cudaGetSymbolAddress((void**)&gvp, g_vp);

    const float qscale = 0.044194173824159216f;   // 512^-0.5

    // conversions
    conv_w_kernel<<<512, 256>>>(q_w, whi[0], wlo[0], HALF * CIN);
    conv_w_kernel<<<512, 256>>>(k_w, whi[1], wlo[1], HALF * CIN);
    conv_w_kernel<<<512, 256>>>(v_w, whi[2], wlo[2], HALF * CIN);
    conv_w_kernel<<<512, 256>>>(o_w, whi[3], wlo[3], CIN * HALF);
    conv_x_kernel<<<dim3(NPIX / 32, CIN / 32), dim3(32, 8)>>>(x, xthi, xtlo);
    zero_pool_kernel<<<64, 256>>>(gkp, gvp);

    // projections on HMMA (mma.sync)
    cudaFuncSetAttribute(proj_mma<CIN, 0>, cudaFuncAttributeMaxDynamicSharedMemorySize, PROJ_SMEM);
    cudaFuncSetAttribute(proj_mma<CIN, 1>, cudaFuncAttributeMaxDynamicSharedMemorySize, PROJ_SMEM);
    cudaFuncSetAttribute(proj_mma<CIN, 2>, cudaFuncAttributeMaxDynamicSharedMemorySize, PROJ_SMEM);
    cudaFuncSetAttribute(proj_mma<HALF, 3>, cudaFuncAttributeMaxDynamicSharedMemorySize, PROJ_SMEM);

    proj_mma<CIN, 0><<<dim3(NPIX / 128, HALF / 128), 256, PROJ_SMEM>>>(
        whi[0], wlo[0], xthi, xtlo, q_g, q_b, q_m, q_v, qscale, gq, nullptr);
    proj_mma<CIN, 1><<<dim3(NPIX / 128, HALF / 128), 256, PROJ_SMEM>>>(
        whi[1], wlo[1], xthi, xtlo, k_g, k_b, k_m, k_v, 1.f, gkp, nullptr);
    proj_mma<CIN, 2><<<dim3(NPIX / 128, HALF / 128), 256, PROJ_SMEM>>>(
        whi[2], wlo[2], xthi, xtlo, v_g, v_b, v_m, v_v, 1.f, gvp, nullptr);

    // attn = q x kp per patch (fp32 + bf16 hi/lo)
    attn_kernel<<<dim3(8, NUM), 256>>>(gq, gkp, gattn, ahi, alo);

    // flash v3 (mma.sync nested softmax attention) -> bf16 hi/lo transposed
    cudaFuncSetAttribute(flash3_kernel, cudaFuncAttributeMaxDynamicSharedMemorySize, F_TOTAL);
    flash3_kernel<<<dim3(16, NUM), 256, F_TOTAL>>>(gattn, ahi, alo, gvp, pthi, ptlo);

    // o projection + residual -> d_out
    proj_mma<HALF, 3><<<dim3(NPIX / 128, CIN / 128), 256, PROJ_SMEM>>>(
        whi[3], wlo[3], pthi, ptlo, o_g, o_b, o_m, o_v, 1.f, out, x);
}

// round 11
// speedup vs baseline: 22.6344x; 1.0219x over previous
#include <cuda_runtime.h>
#include <cuda_bf16.h>
#include <cstdint>
#include <math.h>

#define HH 256
#define WW 256
#define NPIX 65536          // H*W
#define CIN 512
#define HALF 256
#define PSZ 32
#define NH 8
#define NUM 64              // patches
#define EPS 1e-5f

// ==================== mma.sync / ldmatrix / cp.async helpers ====================
__device__ __forceinline__ uint32_t smem_to_u32(const void* smem_ptr) {
    uint32_t addr;
    asm("{ .reg .u64 tmp; cvta.to.shared.u64 tmp, %1; cvt.u32.u64 %0, tmp; }"
        : "=r"(addr) : "l"(smem_ptr));
    return addr;
}
__device__ __forceinline__ void ldsm4(uint32_t* r, uint32_t addr) {
    asm volatile("ldmatrix.sync.aligned.m8n8.x4.shared.b16 {%0,%1,%2,%3}, [%4];"
        : "=r"(r[0]), "=r"(r[1]), "=r"(r[2]), "=r"(r[3]) : "r"(addr));
}
__device__ __forceinline__ void ldsm4t(uint32_t* r, uint32_t addr) {
    asm volatile("ldmatrix.sync.aligned.m8n8.x4.trans.shared.b16 {%0,%1,%2,%3}, [%4];"
        : "=r"(r[0]), "=r"(r[1]), "=r"(r[2]), "=r"(r[3]) : "r"(addr));
}
__device__ __forceinline__ void mma16816(float* c, const uint32_t* a, const uint32_t* b) {
    asm volatile(
        "mma.sync.aligned.m16n8k16.row.col.f32.bf16.bf16.f32 "
        "{%0,%1,%2,%3}, {%4,%5,%6,%7}, {%8,%9}, {%0,%1,%2,%3};"
        : "+f"(c[0]), "+f"(c[1]), "+f"(c[2]), "+f"(c[3])
        : "r"(a[0]), "r"(a[1]), "r"(a[2]), "r"(a[3]), "r"(b[0]), "r"(b[1]));
}
__device__ __forceinline__ uint32_t packbf2(float lo, float hi) {
    __nv_bfloat162 h = __floats2bfloat162_rn(lo, hi);
    return *(uint32_t*)&h;
}
__device__ __forceinline__ void cpasync16(uint32_t s, const void* g) {
    asm volatile("cp.async.cg.shared.global [%0], [%1], 16;" :: "r"(s), "l"(g) : "memory");
}
__device__ __forceinline__ void cpasync_commit() {
    asm volatile("cp.async.commit_group;" ::: "memory");
}
template <int N>
__device__ __forceinline__ void cpasync_wait() {
    asm volatile("cp.async.wait_group %0;" :: "n"(N) : "memory");
}

// ==================== static scratch ====================
__device__ __nv_bfloat16 g_xthi[(size_t)NPIX * CIN];   // x transposed hi, [pix][512]
__device__ __nv_bfloat16 g_xtlo[(size_t)NPIX * CIN];   // x transposed lo
__device__ __nv_bfloat16 g_pthi[(size_t)NPIX * HALF];  // attn-out transposed hi, [pix][256]
__device__ __nv_bfloat16 g_ptlo[(size_t)NPIX * HALF];
__device__ __nv_bfloat16 g_whi[4][CIN * HALF];         // q,k,v,o weights hi
__device__ __nv_bfloat16 g_wlo[4][CIN * HALF];
__device__ float g_q[(size_t)HALF * NPIX];             // q projection image [c][pix]
__device__ __nv_bfloat16 g_ahi[(size_t)NUM * 1024 * 64];   // attn bf16 hi
__device__ __nv_bfloat16 g_alo[(size_t)NUM * 1024 * 64];   // attn bf16 lo
__device__ float g_kp[HALF * NUM];                     // pooled k [c][patch]
__device__ float g_vp[NUM * HALF];                     // pooled v [patch][c]

// ==================== conversion kernels ====================
// all 4 weight matrices in one launch: grid (512, 4)
__global__ void conv_w4_kernel(const float* __restrict__ w0, const float* __restrict__ w1,
                               const float* __restrict__ w2, const float* __restrict__ w3,
                               __nv_bfloat16* __restrict__ hi, __nv_bfloat16* __restrict__ lo)
{
    const int wsel = blockIdx.y;
    const float* w = (wsel == 0) ? w0 : (wsel == 1) ? w1 : (wsel == 2) ? w2 : w3;
    int i = blockIdx.x * 256 + threadIdx.x;
    float v = w[i];
    __nv_bfloat16 h = __float2bfloat16(v);
    const size_t off = (size_t)wsel * (CIN * HALF) + i;
    hi[off] = h;
    lo[off] = __float2bfloat16(v - __bfloat162float(h));
}

// x [512][NPIX] fp32 -> XT [NPIX][512] bf16 hi/lo  (32x32 tile transpose)
__global__ void conv_x_kernel(const float* __restrict__ x,
                              __nv_bfloat16* __restrict__ hi,
                              __nv_bfloat16* __restrict__ lo)
{
    __shared__ float t[32][33];
    const int p0 = blockIdx.x * 32;
    const int k0 = blockIdx.y * 32;
    const int tx = threadIdx.x, ty = threadIdx.y;   // (32, 8)
    #pragma unroll
    for (int i = 0; i < 4; i++) {
        int kl = ty + i * 8;
        t[kl][tx] = x[(size_t)(k0 + kl) * NPIX + p0 + tx];
    }
    __syncthreads();
    #pragma unroll
    for (int i = 0; i < 4; i++) {
        int pl = ty + i * 8;
        float v = t[tx][pl];
        __nv_bfloat16 h = __float2bfloat16(v);
        size_t off = (size_t)(p0 + pl) * CIN + k0 + tx;
        hi[off] = h;
        lo[off] = __float2bfloat16(v - __bfloat162float(h));
    }
}

__global__ void zero_pool_kernel(float* kp, float* vp)
{
    int i = blockIdx.x * 256 + threadIdx.x;   // grid 64 -> 16384
    kp[i] = 0.f;
    vp[i] = 0.f;
}

// ==================== HMMA projection GEMM, cp.async double-buffered ====================
// K-chunk = 32 cols. Two buffer sets of 4 tensor tiles (Ahi,Alo,Bhi,Blo).
#define LDKB2 80                      // 32 bf16 = 64B + 16B pad
#define TILE2 (128 * LDKB2)           // 10240
#define BUFSET (4 * TILE2)            // 40960
#define PROJ_SMEM (2 * BUFSET)        // 81920
template <int KDIM, int MODE>
__global__ void __launch_bounds__(256, 2)
proj_mma(const __nv_bfloat16* __restrict__ Ahi, const __nv_bfloat16* __restrict__ Alo,
         const __nv_bfloat16* __restrict__ Bhi, const __nv_bfloat16* __restrict__ Blo,
         const float* __restrict__ gg, const float* __restrict__ bb,
         const float* __restrict__ mm, const float* __restrict__ vv,
         float postscale, float* __restrict__ outp, const float* __restrict__ resid)
{
    extern __shared__ char smc[];
    const uint32_t sb = smem_to_u32(smc);

    const int tid = threadIdx.x;
    const int wid = tid >> 5;
    const int lane = tid & 31;
    const int wm = wid & 1;
    const int wn = wid >> 1;
    const int bm = blockIdx.y;
    const int pixbase = blockIdx.x * 128;

    float acc[4][4][4];
    #pragma unroll
    for (int mt = 0; mt < 4; mt++)
        #pragma unroll
        for (int nt = 0; nt < 4; nt++)
            #pragma unroll
            for (int e = 0; e < 4; e++) acc[mt][nt][e] = 0.f;

    const int am_ = lane & 15;
    const int ak_ = (lane >> 4) * 8;
    const int bn_ = (lane & 7) + ((lane >> 4) << 3);
    const int bk_ = ((lane >> 3) & 1) * 8;

    // loader: per tensor 512 16B chunks; 2 per thread
    const int lr[2] = { (tid + 0) >> 2, (tid + 256) >> 2 };
    const int lc = tid & 3;

    const int NCH = KDIM / 32;

    // prologue: issue chunk 0 into buf 0
    {
        const uint32_t bufb = sb;
        #pragma unroll
        for (int j = 0; j < 2; j++) {
            const int r = lr[j];
            const size_t arow = (size_t)(bm * 128 + r) * KDIM + lc * 8;
            const size_t brow = (size_t)(pixbase + r) * KDIM + lc * 8;
            cpasync16(bufb + 0 * TILE2 + r * LDKB2 + lc * 16, Ahi + arow);
            cpasync16(bufb + 1 * TILE2 + r * LDKB2 + lc * 16, Alo + arow);
            cpasync16(bufb + 2 * TILE2 + r * LDKB2 + lc * 16, Bhi + brow);
            cpasync16(bufb + 3 * TILE2 + r * LDKB2 + lc * 16, Blo + brow);
        }
        cpasync_commit();
    }

    for (int ch = 0; ch < NCH; ch++) {
        // issue next chunk into the other buffer (previous compute done: bar at loop end)
        if (ch + 1 < NCH) {
            const uint32_t bufb = sb + ((ch + 1) & 1) * BUFSET;
            const int kc1 = (ch + 1) * 32;
            #pragma unroll
            for (int j = 0; j < 2; j++) {
                const int r = lr[j];
                const size_t arow = (size_t)(bm * 128 + r) * KDIM + kc1 + lc * 8;
                const size_t brow = (size_t)(pixbase + r) * KDIM + kc1 + lc * 8;
                cpasync16(bufb + 0 * TILE2 + r * LDKB2 + lc * 16, Ahi + arow);
                cpasync16(bufb + 1 * TILE2 + r * LDKB2 + lc * 16, Alo + arow);
                cpasync16(bufb + 2 * TILE2 + r * LDKB2 + lc * 16, Bhi + brow);
                cpasync16(bufb + 3 * TILE2 + r * LDKB2 + lc * 16, Blo + brow);
            }
            cpasync_commit();
            cpasync_wait<1>();
        } else {
            cpasync_wait<0>();
        }
        __syncthreads();   // chunk ch visible to all warps

        const uint32_t cb = sb + (ch & 1) * BUFSET;
        const uint32_t bAh = cb, bAl = cb + TILE2, bBh = cb + 2 * TILE2, bBl = cb + 3 * TILE2;
        #pragma unroll
        for (int ks = 0; ks < 2; ks++) {
            const int kc = ks * 16;
            uint32_t a[4][4], bh[4][2], bl[4][2];
            #pragma unroll
            for (int mt = 0; mt < 4; mt++)
                ldsm4(a[mt], bAh + (wm * 64 + mt * 16 + am_) * LDKB2 + (kc + ak_) * 2);
            #pragma unroll
            for (int pr = 0; pr < 2; pr++) {
                uint32_t r4[4];
                ldsm4(r4, bBh + (wn * 32 + pr * 16 + bn_) * LDKB2 + (kc + bk_) * 2);
                bh[2 * pr][0] = r4[0]; bh[2 * pr][1] = r4[1];
                bh[2 * pr + 1][0] = r4[2]; bh[2 * pr + 1][1] = r4[3];
            }
            #pragma unroll
            for (int mt = 0; mt < 4; mt++)
                #pragma unroll
                for (int nt = 0; nt < 4; nt++) mma16816(acc[mt][nt], a[mt], bh[nt]);
            #pragma unroll
            for (int pr = 0; pr < 2; pr++) {
                uint32_t r4[4];
                ldsm4(r4, bBl + (wn * 32 + pr * 16 + bn_) * LDKB2 + (kc + bk_) * 2);
                bl[2 * pr][0] = r4[0]; bl[2 * pr][1] = r4[1];
                bl[2 * pr + 1][0] = r4[2]; bl[2 * pr + 1][1] = r4[3];
            }
            #pragma unroll
            for (int mt = 0; mt < 4; mt++)
                #pragma unroll
                for (int nt = 0; nt < 4; nt++) mma16816(acc[mt][nt], a[mt], bl[nt]);
            #pragma unroll
            for (int mt = 0; mt < 4; mt++)
                ldsm4(a[mt], bAl + (wm * 64 + mt * 16 + am_) * LDKB2 + (kc + ak_) * 2);
            #pragma unroll
            for (int mt = 0; mt < 4; mt++)
                #pragma unroll
                for (int nt = 0; nt < 4; nt++) mma16816(acc[mt][nt], a[mt], bh[nt]);
        }
        __syncthreads();   // compute done -> safe to overwrite this buffer next iter
    }

    // ==================== epilogue ====================
    if (MODE == 1 || MODE == 2) {
        const int x0 = (pixbase & 255) + wn * 32;
        const int y0 = pixbase >> 8;
        const int p = ((y0 >> 5) << 3) + (x0 >> 5);
        const float inv = 1.f / 1024.f;
        #pragma unroll
        for (int mt = 0; mt < 4; mt++) {
            #pragma unroll
            for (int hf = 0; hf < 2; hf++) {
                const int o = bm * 128 + wm * 64 + mt * 16 + (lane >> 2) + hf * 8;
                const float s_r = gg[o] * rsqrtf(vv[o] + EPS);
                const float t_r = bb[o] - mm[o] * s_r;
                float s = 0.f;
                #pragma unroll
                for (int nt = 0; nt < 4; nt++) {
                    s += fmaxf(acc[mt][nt][2 * hf + 0] * s_r + t_r, 0.f);
                    s += fmaxf(acc[mt][nt][2 * hf + 1] * s_r + t_r, 0.f);
                }
                s += __shfl_xor_sync(0xffffffffu, s, 1);
                s += __shfl_xor_sync(0xffffffffu, s, 2);
                if ((lane & 3) == 0) {
                    if (MODE == 1) atomicAdd(outp + o * NUM + p, s * inv);
                    else           atomicAdd(outp + p * HALF + o, s * inv);
                }
            }
        }
    } else {
        float* stage = (float*)smc;                  // 128x130 f32 = 66560
        float* scb = (float*)(smc + 68608);
        float* bob = (float*)(smc + 69632);
        if (tid < 128) {
            const int o = bm * 128 + tid;
            const float s_r = gg[o] * rsqrtf(vv[o] + EPS);
            scb[tid] = s_r;
            bob[tid] = bb[o] - mm[o] * s_r;
        }
        __syncthreads();
        #pragma unroll
        for (int mt = 0; mt < 4; mt++) {
            const int r_lo = wm * 64 + mt * 16 + (lane >> 2);
            #pragma unroll
            for (int nt = 0; nt < 4; nt++) {
                const int c = wn * 32 + nt * 8 + (lane & 3) * 2;
                stage[r_lo * 130 + c]     = fmaxf(acc[mt][nt][0] * scb[r_lo] + bob[r_lo], 0.f) * postscale;
                stage[r_lo * 130 + c + 1] = fmaxf(acc[mt][nt][1] * scb[r_lo] + bob[r_lo], 0.f) * postscale;
                stage[(r_lo + 8) * 130 + c]     = fmaxf(acc[mt][nt][2] * scb[r_lo + 8] + bob[r_lo + 8], 0.f) * postscale;
                stage[(r_lo + 8) * 130 + c + 1] = fmaxf(acc[mt][nt][3] * scb[r_lo + 8] + bob[r_lo + 8], 0.f) * postscale;
            }
        }
        __syncthreads();
        for (int i = tid; i < 128 * 128; i += 256) {
            const int r = i >> 7;
            const int c = i & 127;
            float v = stage[r * 130 + c];
            const size_t go = (size_t)(bm * 128 + r) * NPIX + pixbase + c;
            if (MODE == 3) v += resid[go];
            outp[go] = v;
        }
    }
}

// ---------------- attn = q_b^T (1024x256) x kp (256x64), per patch ----------------
// Emits bf16 hi/lo only (flash3 reconstructs fp32 as hi+lo).
__global__ void __launch_bounds__(256)
attn_kernel(const float* __restrict__ q, const float* __restrict__ kp,
            __nv_bfloat16* __restrict__ ahi, __nv_bfloat16* __restrict__ alo)
{
    __shared__ float Qs[8][128];
    __shared__ float Ks[8][64];
    const int blk = blockIdx.x;
    const int b = blockIdx.y;
    const int ph = b >> 3, pw = b & 7;
    const int tid = threadIdx.x;
    const int tx = tid & 15;
    const int ty = tid >> 4;

    float acc[8][4];
    #pragma unroll
    for (int i = 0; i < 8; i++)
        #pragma unroll
        for (int j = 0; j < 4; j++) acc[i][j] = 0.f;

    const int pixbase = ph * 32 * WW + pw * 32;
    const int n_l = tid & 127;
    const int c0 = tid >> 7;
    const int n = blk * 128 + n_l;
    const int pix = pixbase + (n >> 5) * WW + (n & 31);

    for (int kt = 0; kt < HALF / 8; kt++) {
        #pragma unroll
        for (int i = 0; i < 4; i++) {
            const int cl = c0 + i * 2;
            Qs[cl][n_l] = q[(size_t)(kt * 8 + cl) * NPIX + pix];
        }
        #pragma unroll
        for (int i = 0; i < 2; i++) {
            const int e = tid + i * 256;
            Ks[e >> 6][e & 63] = kp[(kt * 8 + (e >> 6)) * NUM + (e & 63)];
        }
        __syncthreads();
        #pragma unroll
        for (int k = 0; k < 8; k++) {
            float a[8], bm4[4];
            *(float4*)(a)     = *(const float4*)&Qs[k][ty * 8];
            *(float4*)(a + 4) = *(const float4*)&Qs[k][ty * 8 + 4];
            *(float4*)(bm4)   = *(const float4*)&Ks[k][tx * 4];
            #pragma unroll
            for (int i = 0; i < 8; i++)
                #pragma unroll
                for (int j = 0; j < 4; j++) acc[i][j] += a[i] * bm4[j];
        }
        __syncthreads();
    }
    #pragma unroll
    for (int i = 0; i < 8; i++) {
        const size_t off = ((size_t)b * 1024 + blk * 128 + ty * 8 + i) * 64 + tx * 4;
        uint2 uh, ul;
        float h0 = __bfloat162float(__float2bfloat16(acc[i][0]));
        float h1 = __bfloat162float(__float2bfloat16(acc[i][1]));
        float h2 = __bfloat162float(__float2bfloat16(acc[i][2]));
        float h3 = __bfloat162float(__float2bfloat16(acc[i][3]));
        uh.x = packbf2(acc[i][0], acc[i][1]);
        uh.y = packbf2(acc[i][2], acc[i][3]);
        ul.x = packbf2(acc[i][0] - h0, acc[i][1] - h1);
        ul.y = packbf2(acc[i][2] - h2, acc[i][3] - h3);
        *(uint2*)(ahi + off) = uh;
        *(uint2*)(alo + off) = ul;
    }
}

// ==================== flash v3: mma.sync nested-softmax attention ====================
// cp.async double-buffered K/V tiles.
#define FLDB 144                 // bf16 tile stride bytes
#define F_QHI 0
#define F_QLO 9216
#define F_KB   18432             // K buffers: base + buf*18432; KHI at +0, KLO at +9216
#define F_REDM 55296             // float[64][4]
#define F_REDS 56320             // float[64][4]
#define F_MS   57344             // float[64]
#define F_LS   57600
#define F_SCS  57856
#define F_MNS  58112
#define F_REDF 58368             // float[64][16]
#define F_TOTAL 62464
__global__ void __launch_bounds__(256, 2)
flash3_kernel(const __nv_bfloat16* __restrict__ ahi, const __nv_bfloat16* __restrict__ alo,
              const float* __restrict__ vp,
              __nv_bfloat16* __restrict__ pthi, __nv_bfloat16* __restrict__ ptlo)
{
    extern __shared__ char smc[];
    const uint32_t sb = smem_to_u32(smc);
    float* REDM = (float*)(smc + F_REDM);
    float* REDS = (float*)(smc + F_REDS);
    float* m_s  = (float*)(smc + F_MS);
    float* l_s  = (float*)(smc + F_LS);
    float* sc_s = (float*)(smc + F_SCS);
    float* mn_s = (float*)(smc + F_MNS);
    float* REDF = (float*)(smc + F_REDF);

    const int rblk = blockIdx.x;    // 0..15
    const int b = blockIdx.y;       // patch
    const int tid = threadIdx.x;
    const int lane = tid & 31;
    const int wid = tid >> 5;
    const int wm = wid >> 2;        // 0..1
    const int wn = wid & 3;         // 0..3
    const int r0 = rblk * 64;
    const size_t abase = (size_t)b * 1024 * 64;

    if (tid < 64) { m_s[tid] = -1e30f; l_s[tid] = 0.f; }

    // K/V tile loader indices: per tensor 512 16B chunks, 2 per thread
    const int kr[2] = { (tid + 0) >> 3, (tid + 256) >> 3 };
    const int kc_ = tid & 7;

    // issue K tile 0
    {
        const uint32_t kb = sb + F_KB;
        #pragma unroll
        for (int j = 0; j < 2; j++) {
            const int r = kr[j];
            const size_t g = abase + (size_t)r * 64 + kc_ * 8;
            cpasync16(kb + r * FLDB + kc_ * 16, ahi + g);
            cpasync16(kb + 9216 + r * FLDB + kc_ * 16, alo + g);
        }
        cpasync_commit();
    }

    // load Q tile (plain; overlaps with K tile0 cp.async)
    {
        #pragma unroll
        for (int i = 0; i < 2; i++) {
            const int idx = tid + i * 256;
            const int r = idx >> 3;
            const int c = idx & 7;
            const size_t g = abase + (size_t)(r0 + r) * 64 + c * 8;
            *(uint4*)(smc + F_QHI + r * FLDB + c * 16) = *(const uint4*)(ahi + g);
            *(uint4*)(smc + F_QLO + r * FLDB + c * 16) = *(const uint4*)(alo + g);
        }
    }

    const int am_ = lane & 15;
    const int ak_ = (lane >> 4) * 8;
    const int bn_ = (lane & 7) + ((lane >> 4) << 3);
    const int bk_ = ((lane >> 3) & 1) * 8;
    const int vk_ = lane & 15;
    const int vn_ = (lane >> 4) << 3;
    const int grp = lane >> 2;
    const int qd  = lane & 3;

    float O[2][8][4];
    #pragma unroll
    for (int mt = 0; mt < 2; mt++)
        #pragma unroll
        for (int n8 = 0; n8 < 8; n8++)
            #pragma unroll
            for (int e = 0; e < 4; e++) O[mt][n8][e] = 0.f;

    for (int t = 0; t < 16; t++) {
        __syncthreads();   // all warps done reading buffer (t-1); REDS(t-1) complete
        if (t > 0 && tid < 64) {
            l_s[tid] = l_s[tid] * sc_s[tid]
                     + REDS[tid * 4 + 0] + REDS[tid * 4 + 1]
                     + REDS[tid * 4 + 2] + REDS[tid * 4 + 3];
        }
        // issue K tile t+1 into other buffer
        if (t + 1 < 16) {
            const uint32_t kb = sb + F_KB + ((t + 1) & 1) * 18432;
            #pragma unroll
            for (int j = 0; j < 2; j++) {
                const int r = kr[j];
                const size_t g = abase + (size_t)((t + 1) * 64 + r) * 64 + kc_ * 8;
                cpasync16(kb + r * FLDB + kc_ * 16, ahi + g);
                cpasync16(kb + 9216 + r * FLDB + kc_ * 16, alo + g);
            }
            cpasync_commit();
            cpasync_wait<1>();
        } else {
            cpasync_wait<0>();
        }
        __syncthreads();   // K tile t visible

        const uint32_t kb = sb + F_KB + (t & 1) * 18432;
        const uint32_t kHI = kb, kLO = kb + 9216;

        // ---- GEMM1: S = Q K^T (3-term split) ----
        float S[2][2][4];
        #pragma unroll
        for (int mt = 0; mt < 2; mt++)
            #pragma unroll
            for (int nt = 0; nt < 2; nt++)
                #pragma unroll
                for (int e = 0; e < 4; e++) S[mt][nt][e] = 0.f;
        #pragma unroll
        for (int ks = 0; ks < 4; ks++) {
            const int kc = ks * 16;
            uint32_t a[2][4], bh[2][2], bl[2][2];
            #pragma unroll
            for (int mt = 0; mt < 2; mt++)
                ldsm4(a[mt], sb + F_QHI + (wm * 32 + mt * 16 + am_) * FLDB + (kc + ak_) * 2);
            {
                uint32_t r4[4];
                ldsm4(r4, kHI + (wn * 16 + bn_) * FLDB + (kc + bk_) * 2);
                bh[0][0] = r4[0]; bh[0][1] = r4[1]; bh[1][0] = r4[2]; bh[1][1] = r4[3];
            }
            #pragma unroll
            for (int mt = 0; mt < 2; mt++)
                #pragma unroll
                for (int nt = 0; nt < 2; nt++) mma16816(S[mt][nt], a[mt], bh[nt]);
            {
                uint32_t r4[4];
                ldsm4(r4, kLO + (wn * 16 + bn_) * FLDB + (kc + bk_) * 2);
                bl[0][0] = r4[0]; bl[0][1] = r4[1]; bl[1][0] = r4[2]; bl[1][1] = r4[3];
            }
            #pragma unroll
            for (int mt = 0; mt < 2; mt++)
                #pragma unroll
                for (int nt = 0; nt < 2; nt++) mma16816(S[mt][nt], a[mt], bl[nt]);
            #pragma unroll
            for (int mt = 0; mt < 2; mt++)
                ldsm4(a[mt], sb + F_QLO + (wm * 32 + mt * 16 + am_) * FLDB + (kc + ak_) * 2);
            #pragma unroll
            for (int mt = 0; mt < 2; mt++)
                #pragma unroll
                for (int nt = 0; nt < 2; nt++) mma16816(S[mt][nt], a[mt], bh[nt]);
        }

        // ---- local row max -> cross-warp reduce ----
        #pragma unroll
        for (int mt = 0; mt < 2; mt++) {
            float la = fmaxf(fmaxf(S[mt][0][0], S[mt][0][1]), fmaxf(S[mt][1][0], S[mt][1][1]));
            float lb = fmaxf(fmaxf(S[mt][0][2], S[mt][0][3]), fmaxf(S[mt][1][2], S[mt][1][3]));
            la = fmaxf(la, __shfl_xor_sync(0xffffffffu, la, 1));
            la = fmaxf(la, __shfl_xor_sync(0xffffffffu, la, 2));
            lb = fmaxf(lb, __shfl_xor_sync(0xffffffffu, lb, 1));
            lb = fmaxf(lb, __shfl_xor_sync(0xffffffffu, lb, 2));
            if (qd == 0) {
                const int r1 = wm * 32 + mt * 16 + grp;
                REDM[r1 * 4 + wn] = la;
                REDM[(r1 + 8) * 4 + wn] = lb;
            }
        }
        __syncthreads();
        if (tid < 64) {
            float mt_ = fmaxf(fmaxf(REDM[tid * 4], REDM[tid * 4 + 1]),
                              fmaxf(REDM[tid * 4 + 2], REDM[tid * 4 + 3]));
            const float mo = m_s[tid];
            const float mn = fmaxf(mo, mt_);
            sc_s[tid] = __expf(mo - mn);
            mn_s[tid] = mn;
            m_s[tid] = mn;
        }
        __syncthreads();

        // ---- P = exp(S-m), row sums, pack A-frags, rescale O ----
        uint32_t aPh[2][4], aPl[2][4];
        #pragma unroll
        for (int mt = 0; mt < 2; mt++) {
            const int r1 = wm * 32 + mt * 16 + grp;
            const float mna = mn_s[r1];
            const float mnb = mn_s[r1 + 8];
            float P[2][4];
            #pragma unroll
            for (int nt = 0; nt < 2; nt++) {
                P[nt][0] = __expf(S[mt][nt][0] - mna);
                P[nt][1] = __expf(S[mt][nt][1] - mna);
                P[nt][2] = __expf(S[mt][nt][2] - mnb);
                P[nt][3] = __expf(S[mt][nt][3] - mnb);
            }
            float ra = P[0][0] + P[0][1] + P[1][0] + P[1][1];
            float rb = P[0][2] + P[0][3] + P[1][2] + P[1][3];
            ra += __shfl_xor_sync(0xffffffffu, ra, 1);
            ra += __shfl_xor_sync(0xffffffffu, ra, 2);
            rb += __shfl_xor_sync(0xffffffffu, rb, 1);
            rb += __shfl_xor_sync(0xffffffffu, rb, 2);
            if (qd == 0) {
                REDS[r1 * 4 + wn] = ra;
                REDS[(r1 + 8) * 4 + wn] = rb;
            }
            aPh[mt][0] = packbf2(P[0][0], P[0][1]);
            aPh[mt][1] = packbf2(P[0][2], P[0][3]);
            aPh[mt][2] = packbf2(P[1][0], P[1][1]);
            aPh[mt][3] = packbf2(P[1][2], P[1][3]);
            float l00 = P[0][0] - __bfloat162float(__float2bfloat16(P[0][0]));
            float l01 = P[0][1] - __bfloat162float(__float2bfloat16(P[0][1]));
            float l02 = P[0][2] - __bfloat162float(__float2bfloat16(P[0][2]));
            float l03 = P[0][3] - __bfloat162float(__float2bfloat16(P[0][3]));
            float l10 = P[1][0] - __bfloat162float(__float2bfloat16(P[1][0]));
            float l11 = P[1][1] - __bfloat162float(__float2bfloat16(P[1][1]));
            float l12 = P[1][2] - __bfloat162float(__float2bfloat16(P[1][2]));
            float l13 = P[1][3] - __bfloat162float(__float2bfloat16(P[1][3]));
            aPl[mt][0] = packbf2(l00, l01);
            aPl[mt][1] = packbf2(l02, l03);
            aPl[mt][2] = packbf2(l10, l11);
            aPl[mt][3] = packbf2(l12, l13);
            const float sa = sc_s[r1];
            const float sbx = sc_s[r1 + 8];
            #pragma unroll
            for (int n8 = 0; n8 < 8; n8++) {
                O[mt][n8][0] *= sa; O[mt][n8][1] *= sa;
                O[mt][n8][2] *= sbx; O[mt][n8][3] *= sbx;
            }
        }

        // ---- GEMM2: O += P V (3-term split); V via trans-ldsm, k-slice = wn*16 ----
        #pragma unroll
        for (int g = 0; g < 4; g++) {
            const int n0 = g * 16;
            uint32_t vh[4], vl[4];
            ldsm4t(vh, kHI + (wn * 16 + vk_) * FLDB + (n0 + vn_) * 2);
            ldsm4t(vl, kLO + (wn * 16 + vk_) * FLDB + (n0 + vn_) * 2);
            uint32_t b0h[2] = { vh[0], vh[1] }, b1h[2] = { vh[2], vh[3] };
            uint32_t b0l[2] = { vl[0], vl[1] }, b1l[2] = { vl[2], vl[3] };
            #pragma unroll
            for (int mt = 0; mt < 2; mt++) {
                mma16816(O[mt][2 * g + 0], aPh[mt], b0h);
                mma16816(O[mt][2 * g + 1], aPh[mt], b1h);
                mma16816(O[mt][2 * g + 0], aPh[mt], b0l);
                mma16816(O[mt][2 * g + 1], aPh[mt], b1l);
                mma16816(O[mt][2 * g + 0], aPl[mt], b0h);
                mma16816(O[mt][2 * g + 1], aPl[mt], b1h);
            }
        }
    }
    __syncthreads();
    if (tid < 64) {
        l_s[tid] = l_s[tid] * sc_s[tid]
                 + REDS[tid * 4 + 0] + REDS[tid * 4 + 1]
                 + REDS[tid * 4 + 2] + REDS[tid * 4 + 3];
    }

    // ---- reduce O across wn warps into OSUM (overlay on Q region) ----
    float* Os = (float*)(smc + 0);          // [64][66]
    for (int i = tid; i < 64 * 66; i += 256) Os[i] = 0.f;
    __syncthreads();
    #pragma unroll 1
    for (int p = 0; p < 4; p++) {
        if (wn == p) {
            #pragma unroll
            for (int mt = 0; mt < 2; mt++) {
                const int r1 = wm * 32 + mt * 16 + grp;
                #pragma unroll
                for (int n8 = 0; n8 < 8; n8++) {
                    const int c = n8 * 8 + qd * 2;
                    Os[r1 * 66 + c]       += O[mt][n8][0];
                    Os[r1 * 66 + c + 1]   += O[mt][n8][1];
                    Os[(r1 + 8) * 66 + c]     += O[mt][n8][2];
                    Os[(r1 + 8) * 66 + c + 1] += O[mt][n8][3];
                }
            }
        }
        __syncthreads();
    }

    // ---- final: fv = (Ahi+Alo) + O/l, softmax over 64 ----
    const int txx = tid & 15;
    const int tyy = tid >> 4;
    float fv[4][4];
    #pragma unroll
    for (int i = 0; i < 4; i++) {
        const int rr = tyy * 4 + i;
        const float linv = 1.f / l_s[rr];
        const size_t goff = abase + (size_t)(r0 + rr) * 64 + txx * 4;
        uint2 uh = *(const uint2*)(ahi + goff);
        uint2 ul = *(const uint2*)(alo + goff);
        __nv_bfloat162 h0 = *(__nv_bfloat162*)&uh.x;
        __nv_bfloat162 h1 = *(__nv_bfloat162*)&uh.y;
        __nv_bfloat162 l0 = *(__nv_bfloat162*)&ul.x;
        __nv_bfloat162 l1 = *(__nv_bfloat162*)&ul.y;
        fv[i][0] = __bfloat162float(h0.x) + __bfloat162float(l0.x) + Os[rr * 66 + txx * 4 + 0] * linv;
        fv[i][1] = __bfloat162float(h0.y) + __bfloat162float(l0.y) + Os[rr * 66 + txx * 4 + 1] * linv;
        fv[i][2] = __bfloat162float(h1.x) + __bfloat162float(l1.x) + Os[rr * 66 + txx * 4 + 2] * linv;
        fv[i][3] = __bfloat162float(h1.y) + __bfloat162float(l1.y) + Os[rr * 66 + txx * 4 + 3] * linv;
    }
    #pragma unroll
    for (int i = 0; i < 4; i++) {
        float lm = fmaxf(fmaxf(fv[i][0], fv[i][1]), fmaxf(fv[i][2], fv[i][3]));
        REDF[(tyy * 4 + i) * 16 + txx] = lm;
    }
    __syncthreads();
    if (tid < 64) {
        float mt_ = REDF[tid * 16];
        #pragma unroll
        for (int j = 1; j < 16; j++) mt_ = fmaxf(mt_, REDF[tid * 16 + j]);
        mn_s[tid] = mt_;
    }
    __syncthreads();
    #pragma unroll
    for (int i = 0; i < 4; i++) {
        const int rr = tyy * 4 + i;
        const float mn = mn_s[rr];
        float rs = 0.f;
        #pragma unroll
        for (int j = 0; j < 4; j++) { fv[i][j] = __expf(fv[i][j] - mn); rs += fv[i][j]; }
        REDF[rr * 16 + txx] = rs;
    }
    __syncthreads();
    if (tid < 64) {
        float su = REDF[tid * 16];
        #pragma unroll
        for (int j = 1; j < 16; j++) su += REDF[tid * 16 + j];
        l_s[tid] = 1.f / su;
    }
    __syncthreads();
    float* Ps = (float*)(smc + F_KB);       // [64][68] overlay on K buf0
    #pragma unroll
    for (int i = 0; i < 4; i++) {
        const int rr = tyy * 4 + i;
        const float inv = l_s[rr];
        *(float4*)&Ps[rr * 68 + txx * 4] =
            make_float4(fv[i][0] * inv, fv[i][1] * inv, fv[i][2] * inv, fv[i][3] * inv);
    }
    __syncthreads();

    // ---- out GEMM: out[64][256] = P_final[64][64] x vp[64][256] ----
    float acc[4][16];
    #pragma unroll
    for (int i = 0; i < 4; i++)
        #pragma unroll
        for (int j = 0; j < 16; j++) acc[i][j] = 0.f;
    #pragma unroll 2
    for (int m = 0; m < 64; m++) {
        float pr[4];
        #pragma unroll
        for (int i = 0; i < 4; i++) pr[i] = Ps[(tyy * 4 + i) * 68 + m];
        const float4* vr = (const float4*)(vp + m * 256 + txx * 16);
        float4 v0 = vr[0], v1 = vr[1], v2 = vr[2], v3 = vr[3];
        const float vw[16] = {v0.x, v0.y, v0.z, v0.w, v1.x, v1.y, v1.z, v1.w,
                              v2.x, v2.y, v2.z, v2.w, v3.x, v3.y, v3.z, v3.w};
        #pragma unroll
        for (int i = 0; i < 4; i++)
            #pragma unroll
            for (int j = 0; j < 16; j++) acc[i][j] += pr[i] * vw[j];
    }

    // ---- staged transposed bf16 hi/lo store ----
    const int ph = b >> 3, pw = b & 7;
    const int pixbase = ph * 32 * WW + pw * 32;
    float* stg = (float*)(smc + 0);         // [64][65] overlay (Os dead)
    #pragma unroll 1
    for (int g = 0; g < 4; g++) {
        __syncthreads();
        if ((txx >> 2) == g) {
            const int txl = txx & 3;
            #pragma unroll
            for (int i = 0; i < 4; i++)
                #pragma unroll
                for (int j = 0; j < 16; j++)
                    stg[(tyy * 4 + i) * 65 + txl * 16 + j] = acc[i][j];
        }
        __syncthreads();
        const int rl = tid >> 2;
        const int cc0 = (tid & 3) * 16;
        const int n = r0 + rl;
        const int pix = pixbase + (n >> 5) * WW + (n & 31);
        #pragma unroll
        for (int k2 = 0; k2 < 16; k2++) {
            float v = stg[rl * 65 + cc0 + k2];
            __nv_bfloat16 h = __float2bfloat16(v);
            const size_t off = (size_t)pix * HALF + g * 64 + cc0 + k2;
            pthi[off] = h;
            ptlo[off] = __float2bfloat16(v - __bfloat162float(h));
        }
    }
}

// ==================== launch ====================
extern "C" void kernel_launch(void* const* d_in, const int* in_sizes, int n_in,
                              void* d_out, int out_size)
{
    const float* x   = (const float*)d_in[0];
    const float* q_w = (const float*)d_in[1];
    const float* q_g = (const float*)d_in[2];
    const float* q_b = (const float*)d_in[3];
    const float* q_m = (const float*)d_in[4];
    const float* q_v = (const float*)d_in[5];
    const float* k_w = (const float*)d_in[6];
    const float* k_g = (const float*)d_in[7];
    const float* k_b = (const float*)d_in[8];
    const float* k_m = (const float*)d_in[9];
    const float* k_v = (const float*)d_in[10];
    const float* v_w = (const float*)d_in[11];
    const float* v_g = (const float*)d_in[12];
    const float* v_b = (const float*)d_in[13];
    const float* v_m = (const float*)d_in[14];
    const float* v_v = (const float*)d_in[15];
    const float* o_w = (const float*)d_in[16];
    const float* o_g = (const float*)d_in[17];
    const float* o_b = (const float*)d_in[18];
    const float* o_m = (const float*)d_in[19];
    const float* o_v = (const float*)d_in[20];
    float* out = (float*)d_out;

    __nv_bfloat16 *xthi, *xtlo, *pthi, *ptlo, *ahi, *alo;
    __nv_bfloat16 (*whi)[CIN * HALF], (*wlo)[CIN * HALF];
    float *gq, *gkp, *gvp;
    cudaGetSymbolAddress((void**)&xthi, g_xthi);
    cudaGetSymbolAddress((void**)&xtlo, g_xtlo);
    cudaGetSymbolAddress((void**)&pthi, g_pthi);
    cudaGetSymbolAddress((void**)&ptlo, g_ptlo);
    cudaGetSymbolAddress((void**)&ahi, g_ahi);
    cudaGetSymbolAddress((void**)&alo, g_alo);
    cudaGetSymbolAddress((void**)&whi, g_whi);
    cudaGetSymbolAddress((void**)&wlo, g_wlo);
    cudaGetSymbolAddress((void**)&gq, g_q);
    cudaGetSymbolAddress((void**)&gkp, g_kp);
    cudaGetSymbolAddress((void**)&gvp, g_vp);

    const float qscale = 0.044194173824159216f;   // 512^-0.5

    // conversions
    conv_w4_kernel<<<dim3(512, 4), 256>>>(q_w, k_w, v_w, o_w, (__nv_bfloat16*)whi, (__nv_bfloat16*)wlo);
    conv_x_kernel<<<dim3(NPIX / 32, CIN / 32), dim3(32, 8)>>>(x, xthi, xtlo);
    zero_pool_kernel<<<64, 256>>>(gkp, gvp);

    // projections on HMMA (cp.async double-buffered)
    cudaFuncSetAttribute(proj_mma<CIN, 0>, cudaFuncAttributeMaxDynamicSharedMemorySize, PROJ_SMEM);
    cudaFuncSetAttribute(proj_mma<CIN, 1>, cudaFuncAttributeMaxDynamicSharedMemorySize, PROJ_SMEM);
    cudaFuncSetAttribute(proj_mma<CIN, 2>, cudaFuncAttributeMaxDynamicSharedMemorySize, PROJ_SMEM);
    cudaFuncSetAttribute(proj_mma<HALF, 3>, cudaFuncAttributeMaxDynamicSharedMemorySize, PROJ_SMEM);

    proj_mma<CIN, 0><<<dim3(NPIX / 128, HALF / 128), 256, PROJ_SMEM>>>(
        whi[0], wlo[0], xthi, xtlo, q_g, q_b, q_m, q_v, qscale, gq, nullptr);
    proj_mma<CIN, 1><<<dim3(NPIX / 128, HALF / 128), 256, PROJ_SMEM>>>(
        whi[1], wlo[1], xthi, xtlo, k_g, k_b, k_m, k_v, 1.f, gkp, nullptr);
    proj_mma<CIN, 2><<<dim3(NPIX / 128, HALF / 128), 256, PROJ_SMEM>>>(
        whi[2], wlo[2], xthi, xtlo, v_g, v_b, v_m, v_v, 1.f, gvp, nullptr);

    // attn = q x kp per patch (bf16 hi/lo)
    attn_kernel<<<dim3(8, NUM), 256>>>(gq, gkp, ahi, alo);

    // flash v3 (cp.async double-buffered K tiles)
    cudaFuncSetAttribute(flash3_kernel, cudaFuncAttributeMaxDynamicSharedMemorySize, F_TOTAL);
    flash3_kernel<<<dim3(16, NUM), 256, F_TOTAL>>>(ahi, alo, gvp, pthi, ptlo);

    // o projection + residual -> d_out
    proj_mma<HALF, 3><<<dim3(NPIX / 128, CIN / 128), 256, PROJ_SMEM>>>(
        whi[3], wlo[3], pthi, ptlo, o_g, o_b, o_m, o_v, 1.f, out, x);
}

// round 12
// speedup vs baseline: 24.2379x; 1.0708x over previous
#include <cuda_runtime.h>
#include <cuda_bf16.h>
#include <cstdint>
#include <math.h>

#define HH 256
#define WW 256
#define NPIX 65536          // H*W
#define CIN 512
#define HALF 256
#define PSZ 32
#define NH 8
#define NUM 64              // patches
#define EPS 1e-5f

// ==================== mma.sync / ldmatrix / cp.async helpers ====================
__device__ __forceinline__ uint32_t smem_to_u32(const void* smem_ptr) {
    uint32_t addr;
    asm("{ .reg .u64 tmp; cvta.to.shared.u64 tmp, %1; cvt.u32.u64 %0, tmp; }"
        : "=r"(addr) : "l"(smem_ptr));
    return addr;
}
__device__ __forceinline__ void ldsm4(uint32_t* r, uint32_t addr) {
    asm volatile("ldmatrix.sync.aligned.m8n8.x4.shared.b16 {%0,%1,%2,%3}, [%4];"
        : "=r"(r[0]), "=r"(r[1]), "=r"(r[2]), "=r"(r[3]) : "r"(addr));
}
__device__ __forceinline__ void ldsm4t(uint32_t* r, uint32_t addr) {
    asm volatile("ldmatrix.sync.aligned.m8n8.x4.trans.shared.b16 {%0,%1,%2,%3}, [%4];"
        : "=r"(r[0]), "=r"(r[1]), "=r"(r[2]), "=r"(r[3]) : "r"(addr));
}
__device__ __forceinline__ void mma16816(float* c, const uint32_t* a, const uint32_t* b) {
    asm volatile(
        "mma.sync.aligned.m16n8k16.row.col.f32.bf16.bf16.f32 "
        "{%0,%1,%2,%3}, {%4,%5,%6,%7}, {%8,%9}, {%0,%1,%2,%3};"
        : "+f"(c[0]), "+f"(c[1]), "+f"(c[2]), "+f"(c[3])
        : "r"(a[0]), "r"(a[1]), "r"(a[2]), "r"(a[3]), "r"(b[0]), "r"(b[1]));
}
__device__ __forceinline__ uint32_t packbf2(float lo, float hi) {
    __nv_bfloat162 h = __floats2bfloat162_rn(lo, hi);
    return *(uint32_t*)&h;
}
__device__ __forceinline__ void cpasync16(uint32_t s, const void* g) {
    asm volatile("cp.async.cg.shared.global [%0], [%1], 16;" :: "r"(s), "l"(g) : "memory");
}
__device__ __forceinline__ void cpasync_commit() {
    asm volatile("cp.async.commit_group;" ::: "memory");
}
template <int N>
__device__ __forceinline__ void cpasync_wait() {
    asm volatile("cp.async.wait_group %0;" :: "n"(N) : "memory");
}

// ==================== static scratch ====================
__device__ __nv_bfloat16 g_xthi[(size_t)NPIX * CIN];   // x transposed hi, [pix][512]
__device__ __nv_bfloat16 g_xtlo[(size_t)NPIX * CIN];   // x transposed lo
__device__ __nv_bfloat16 g_qthi[(size_t)NPIX * HALF];  // q transposed hi, [pix][256]
__device__ __nv_bfloat16 g_qtlo[(size_t)NPIX * HALF];
__device__ __nv_bfloat16 g_pthi[(size_t)NPIX * HALF];  // attn-out transposed hi, [pix][256]
__device__ __nv_bfloat16 g_ptlo[(size_t)NPIX * HALF];
__device__ __nv_bfloat16 g_whi[4][CIN * HALF];         // q,k,v,o weights hi
__device__ __nv_bfloat16 g_wlo[4][CIN * HALF];
__device__ __nv_bfloat16 g_ahi[(size_t)NUM * 1024 * 64];   // attn bf16 hi
__device__ __nv_bfloat16 g_alo[(size_t)NUM * 1024 * 64];   // attn bf16 lo
__device__ float g_kp[HALF * NUM];                     // pooled k [c][patch] fp32
__device__ float g_vp[NUM * HALF];                     // pooled v [patch][c] fp32
__device__ __nv_bfloat16 g_kpbh[NUM * HALF];           // kp bf16 hi, [patch][c]
__device__ __nv_bfloat16 g_kpbl[NUM * HALF];           // kp bf16 lo

// ==================== conversion kernels ====================
__global__ void conv_w4_kernel(const float* __restrict__ w0, const float* __restrict__ w1,
                               const float* __restrict__ w2, const float* __restrict__ w3,
                               __nv_bfloat16* __restrict__ hi, __nv_bfloat16* __restrict__ lo)
{
    const int wsel = blockIdx.y;
    const float* w = (wsel == 0) ? w0 : (wsel == 1) ? w1 : (wsel == 2) ? w2 : w3;
    int i = blockIdx.x * 256 + threadIdx.x;
    float v = w[i];
    __nv_bfloat16 h = __float2bfloat16(v);
    const size_t off = (size_t)wsel * (CIN * HALF) + i;
    hi[off] = h;
    lo[off] = __float2bfloat16(v - __bfloat162float(h));
}

// x [512][NPIX] fp32 -> XT [NPIX][512] bf16 hi/lo  (32x32 tile transpose)
__global__ void conv_x_kernel(const float* __restrict__ x,
                              __nv_bfloat16* __restrict__ hi,
                              __nv_bfloat16* __restrict__ lo)
{
    __shared__ float t[32][33];
    const int p0 = blockIdx.x * 32;
    const int k0 = blockIdx.y * 32;
    const int tx = threadIdx.x, ty = threadIdx.y;   // (32, 8)
    #pragma unroll
    for (int i = 0; i < 4; i++) {
        int kl = ty + i * 8;
        t[kl][tx] = x[(size_t)(k0 + kl) * NPIX + p0 + tx];
    }
    __syncthreads();
    #pragma unroll
    for (int i = 0; i < 4; i++) {
        int pl = ty + i * 8;
        float v = t[tx][pl];
        __nv_bfloat16 h = __float2bfloat16(v);
        size_t off = (size_t)(p0 + pl) * CIN + k0 + tx;
        hi[off] = h;
        lo[off] = __float2bfloat16(v - __bfloat162float(h));
    }
}

__global__ void zero_pool_kernel(float* kp, float* vp)
{
    int i = blockIdx.x * 256 + threadIdx.x;   // grid 64 -> 16384
    kp[i] = 0.f;
    vp[i] = 0.f;
}

// kp [c][patch] fp32 -> [patch][c] bf16 hi/lo
__global__ void kconv_kernel(const float* __restrict__ kp,
                             __nv_bfloat16* __restrict__ kph, __nv_bfloat16* __restrict__ kpl)
{
    int i = blockIdx.x * 256 + threadIdx.x;   // grid 64 -> 16384
    const int patch = i >> 8;
    const int c = i & 255;
    float v = kp[c * NUM + patch];
    __nv_bfloat16 h = __float2bfloat16(v);
    kph[patch * HALF + c] = h;
    kpl[patch * HALF + c] = __float2bfloat16(v - __bfloat162float(h));
}

// ==================== fused q/k/v HMMA projection (grid.y = 6) ====================
#define LDKB2 80                      // 32 bf16 = 64B + 16B pad
#define TILE2 (128 * LDKB2)           // 10240
#define BUFSET (4 * TILE2)            // 40960
#define PROJ_SMEM (2 * BUFSET)        // 81920

struct QKVParams {
    const __nv_bfloat16* whi[3];
    const __nv_bfloat16* wlo[3];
    const float* gg[3];
    const float* bb[3];
    const float* mm[3];
    const float* vv[3];
};

__global__ void __launch_bounds__(256, 2)
proj_qkv(QKVParams p,
         const __nv_bfloat16* __restrict__ Bhi, const __nv_bfloat16* __restrict__ Blo,
         __nv_bfloat16* __restrict__ qhi, __nv_bfloat16* __restrict__ qlo,
         float* __restrict__ kpo, float* __restrict__ vpo, float qscale)
{
    extern __shared__ char smc[];
    const uint32_t sb = smem_to_u32(smc);

    const int tid = threadIdx.x;
    const int wid = tid >> 5;
    const int lane = tid & 31;
    const int wm = wid & 1;
    const int wn = wid >> 1;
    const int wsel = blockIdx.y >> 1;     // 0=q 1=k 2=v
    const int bmh = blockIdx.y & 1;       // 0..1 out-ch tile
    const int pixbase = blockIdx.x * 128;

    const __nv_bfloat16* Ahi = p.whi[wsel];
    const __nv_bfloat16* Alo = p.wlo[wsel];

    float acc[4][4][4];
    #pragma unroll
    for (int mt = 0; mt < 4; mt++)
        #pragma unroll
        for (int nt = 0; nt < 4; nt++)
            #pragma unroll
            for (int e = 0; e < 4; e++) acc[mt][nt][e] = 0.f;

    const int am_ = lane & 15;
    const int ak_ = (lane >> 4) * 8;
    const int bn_ = (lane & 7) + ((lane >> 4) << 3);
    const int bk_ = ((lane >> 3) & 1) * 8;

    const int lr[2] = { (tid + 0) >> 2, (tid + 256) >> 2 };
    const int lc = tid & 3;

    const int NCH = CIN / 32;   // 16

    {
        const uint32_t bufb = sb;
        #pragma unroll
        for (int j = 0; j < 2; j++) {
            const int r = lr[j];
            const size_t arow = (size_t)(bmh * 128 + r) * CIN + lc * 8;
            const size_t brow = (size_t)(pixbase + r) * CIN + lc * 8;
            cpasync16(bufb + 0 * TILE2 + r * LDKB2 + lc * 16, Ahi + arow);
            cpasync16(bufb + 1 * TILE2 + r * LDKB2 + lc * 16, Alo + arow);
            cpasync16(bufb + 2 * TILE2 + r * LDKB2 + lc * 16, Bhi + brow);
            cpasync16(bufb + 3 * TILE2 + r * LDKB2 + lc * 16, Blo + brow);
        }
        cpasync_commit();
    }

    for (int ch = 0; ch < NCH; ch++) {
        if (ch + 1 < NCH) {
            const uint32_t bufb = sb + ((ch + 1) & 1) * BUFSET;
            const int kc1 = (ch + 1) * 32;
            #pragma unroll
            for (int j = 0; j < 2; j++) {
                const int r = lr[j];
                const size_t arow = (size_t)(bmh * 128 + r) * CIN + kc1 + lc * 8;
                const size_t brow = (size_t)(pixbase + r) * CIN + kc1 + lc * 8;
                cpasync16(bufb + 0 * TILE2 + r * LDKB2 + lc * 16, Ahi + arow);
                cpasync16(bufb + 1 * TILE2 + r * LDKB2 + lc * 16, Alo + arow);
                cpasync16(bufb + 2 * TILE2 + r * LDKB2 + lc * 16, Bhi + brow);
                cpasync16(bufb + 3 * TILE2 + r * LDKB2 + lc * 16, Blo + brow);
            }
            cpasync_commit();
            cpasync_wait<1>();
        } else {
            cpasync_wait<0>();
        }
        __syncthreads();

        const uint32_t cb = sb + (ch & 1) * BUFSET;
        const uint32_t bAh = cb, bAl = cb + TILE2, bBh = cb + 2 * TILE2, bBl = cb + 3 * TILE2;
        #pragma unroll
        for (int ks = 0; ks < 2; ks++) {
            const int kc = ks * 16;
            uint32_t a[4][4], bh[4][2], bl[4][2];
            #pragma unroll
            for (int mt = 0; mt < 4; mt++)
                ldsm4(a[mt], bAh + (wm * 64 + mt * 16 + am_) * LDKB2 + (kc + ak_) * 2);
            #pragma unroll
            for (int pr = 0; pr < 2; pr++) {
                uint32_t r4[4];
                ldsm4(r4, bBh + (wn * 32 + pr * 16 + bn_) * LDKB2 + (kc + bk_) * 2);
                bh[2 * pr][0] = r4[0]; bh[2 * pr][1] = r4[1];
                bh[2 * pr + 1][0] = r4[2]; bh[2 * pr + 1][1] = r4[3];
            }
            #pragma unroll
            for (int mt = 0; mt < 4; mt++)
                #pragma unroll
                for (int nt = 0; nt < 4; nt++) mma16816(acc[mt][nt], a[mt], bh[nt]);
            #pragma unroll
            for (int pr = 0; pr < 2; pr++) {
                uint32_t r4[4];
                ldsm4(r4, bBl + (wn * 32 + pr * 16 + bn_) * LDKB2 + (kc + bk_) * 2);
                bl[2 * pr][0] = r4[0]; bl[2 * pr][1] = r4[1];
                bl[2 * pr + 1][0] = r4[2]; bl[2 * pr + 1][1] = r4[3];
            }
            #pragma unroll
            for (int mt = 0; mt < 4; mt++)
                #pragma unroll
                for (int nt = 0; nt < 4; nt++) mma16816(acc[mt][nt], a[mt], bl[nt]);
            #pragma unroll
            for (int mt = 0; mt < 4; mt++)
                ldsm4(a[mt], bAl + (wm * 64 + mt * 16 + am_) * LDKB2 + (kc + ak_) * 2);
            #pragma unroll
            for (int mt = 0; mt < 4; mt++)
                #pragma unroll
                for (int nt = 0; nt < 4; nt++) mma16816(acc[mt][nt], a[mt], bh[nt]);
        }
        __syncthreads();
    }

    // ==================== epilogues ====================
    if (wsel >= 1) {
        // fused BN + ReLU + 32-pixel pooling; each warp's 32 cols = one patch
        const int x0 = (pixbase & 255) + wn * 32;
        const int y0 = pixbase >> 8;
        const int patch = ((y0 >> 5) << 3) + (x0 >> 5);
        const float inv = 1.f / 1024.f;
        const float* gg = p.gg[wsel];
        const float* bb = p.bb[wsel];
        const float* mm = p.mm[wsel];
        const float* vv = p.vv[wsel];
        float* outp = (wsel == 1) ? kpo : vpo;
        #pragma unroll
        for (int mt = 0; mt < 4; mt++) {
            #pragma unroll
            for (int hf = 0; hf < 2; hf++) {
                const int o = bmh * 128 + wm * 64 + mt * 16 + (lane >> 2) + hf * 8;
                const float s_r = gg[o] * rsqrtf(vv[o] + EPS);
                const float t_r = bb[o] - mm[o] * s_r;
                float s = 0.f;
                #pragma unroll
                for (int nt = 0; nt < 4; nt++) {
                    s += fmaxf(acc[mt][nt][2 * hf + 0] * s_r + t_r, 0.f);
                    s += fmaxf(acc[mt][nt][2 * hf + 1] * s_r + t_r, 0.f);
                }
                s += __shfl_xor_sync(0xffffffffu, s, 1);
                s += __shfl_xor_sync(0xffffffffu, s, 2);
                if ((lane & 3) == 0) {
                    if (wsel == 1) atomicAdd(outp + o * NUM + patch, s * inv);
                    else           atomicAdd(outp + patch * HALF + o, s * inv);
                }
            }
        }
    } else {
        // q: BN + ReLU + qscale, emit bf16 hi/lo [pix][256]
        float* stage = (float*)smc;                  // 128 x 131 fp32 = 67072
        float* scb = (float*)(smc + 68608);
        float* bob = (float*)(smc + 69632);
        if (tid < 128) {
            const int o = bmh * 128 + tid;
            const float s_r = p.gg[0][o] * rsqrtf(p.vv[0][o] + EPS);
            scb[tid] = s_r;
            bob[tid] = p.bb[0][o] - p.mm[0][o] * s_r;
        }
        __syncthreads();
        #pragma unroll
        for (int mt = 0; mt < 4; mt++) {
            const int r_lo = wm * 64 + mt * 16 + (lane >> 2);
            #pragma unroll
            for (int nt = 0; nt < 4; nt++) {
                const int c = wn * 32 + nt * 8 + (lane & 3) * 2;
                stage[r_lo * 131 + c]     = fmaxf(acc[mt][nt][0] * scb[r_lo] + bob[r_lo], 0.f) * qscale;
                stage[r_lo * 131 + c + 1] = fmaxf(acc[mt][nt][1] * scb[r_lo] + bob[r_lo], 0.f) * qscale;
                stage[(r_lo + 8) * 131 + c]     = fmaxf(acc[mt][nt][2] * scb[r_lo + 8] + bob[r_lo + 8], 0.f) * qscale;
                stage[(r_lo + 8) * 131 + c + 1] = fmaxf(acc[mt][nt][3] * scb[r_lo + 8] + bob[r_lo + 8], 0.f) * qscale;
            }
        }
        __syncthreads();
        for (int i = tid; i < 128 * 64; i += 256) {
            const int pixl = i >> 6;
            const int cp = (i & 63) * 2;
            float v0 = stage[cp * 131 + pixl];
            float v1 = stage[(cp + 1) * 131 + pixl];
            __nv_bfloat16 h0 = __float2bfloat16(v0);
            __nv_bfloat16 h1 = __float2bfloat16(v1);
            const size_t off = (size_t)(pixbase + pixl) * HALF + bmh * 128 + cp;
            *(uint32_t*)(qhi + off) = packbf2(v0, v1);
            *(uint32_t*)(qlo + off) = packbf2(v0 - __bfloat162float(h0), v1 - __bfloat162float(h1));
        }
    }
}

// ==================== HMMA o-projection (MODE 3: image out + residual) ====================
template <int KDIM>
__global__ void __launch_bounds__(256, 2)
proj_o(const __nv_bfloat16* __restrict__ Ahi, const __nv_bfloat16* __restrict__ Alo,
       const __nv_bfloat16* __restrict__ Bhi, const __nv_bfloat16* __restrict__ Blo,
       const float* __restrict__ gg, const float* __restrict__ bb,
       const float* __restrict__ mm, const float* __restrict__ vv,
       float* __restrict__ outp, const float* __restrict__ resid)
{
    extern __shared__ char smc[];
    const uint32_t sb = smem_to_u32(smc);

    const int tid = threadIdx.x;
    const int wid = tid >> 5;
    const int lane = tid & 31;
    const int wm = wid & 1;
    const int wn = wid >> 1;
    const int bm = blockIdx.y;
    const int pixbase = blockIdx.x * 128;

    float acc[4][4][4];
    #pragma unroll
    for (int mt = 0; mt < 4; mt++)
        #pragma unroll
        for (int nt = 0; nt < 4; nt++)
            #pragma unroll
            for (int e = 0; e < 4; e++) acc[mt][nt][e] = 0.f;

    const int am_ = lane & 15;
    const int ak_ = (lane >> 4) * 8;
    const int bn_ = (lane & 7) + ((lane >> 4) << 3);
    const int bk_ = ((lane >> 3) & 1) * 8;

    const int lr[2] = { (tid + 0) >> 2, (tid + 256) >> 2 };
    const int lc = tid & 3;

    const int NCH = KDIM / 32;

    {
        const uint32_t bufb = sb;
        #pragma unroll
        for (int j = 0; j < 2; j++) {
            const int r = lr[j];
            const size_t arow = (size_t)(bm * 128 + r) * KDIM + lc * 8;
            const size_t brow = (size_t)(pixbase + r) * KDIM + lc * 8;
            cpasync16(bufb + 0 * TILE2 + r * LDKB2 + lc * 16, Ahi + arow);
            cpasync16(bufb + 1 * TILE2 + r * LDKB2 + lc * 16, Alo + arow);
            cpasync16(bufb + 2 * TILE2 + r * LDKB2 + lc * 16, Bhi + brow);
            cpasync16(bufb + 3 * TILE2 + r * LDKB2 + lc * 16, Blo + brow);
        }
        cpasync_commit();
    }

    for (int ch = 0; ch < NCH; ch++) {
        if (ch + 1 < NCH) {
            const uint32_t bufb = sb + ((ch + 1) & 1) * BUFSET;
            const int kc1 = (ch + 1) * 32;
            #pragma unroll
            for (int j = 0; j < 2; j++) {
                const int r = lr[j];
                const size_t arow = (size_t)(bm * 128 + r) * KDIM + kc1 + lc * 8;
                const size_t brow = (size_t)(pixbase + r) * KDIM + kc1 + lc * 8;
                cpasync16(bufb + 0 * TILE2 + r * LDKB2 + lc * 16, Ahi + arow);
                cpasync16(bufb + 1 * TILE2 + r * LDKB2 + lc * 16, Alo + arow);
                cpasync16(bufb + 2 * TILE2 + r * LDKB2 + lc * 16, Bhi + brow);
                cpasync16(bufb + 3 * TILE2 + r * LDKB2 + lc * 16, Blo + brow);
            }
            cpasync_commit();
            cpasync_wait<1>();
        } else {
            cpasync_wait<0>();
        }
        __syncthreads();

        const uint32_t cb = sb + (ch & 1) * BUFSET;
        const uint32_t bAh = cb, bAl = cb + TILE2, bBh = cb + 2 * TILE2, bBl = cb + 3 * TILE2;
        #pragma unroll
        for (int ks = 0; ks < 2; ks++) {
            const int kc = ks * 16;
            uint32_t a[4][4], bh[4][2], bl[4][2];
            #pragma unroll
            for (int mt = 0; mt < 4; mt++)
                ldsm4(a[mt], bAh + (wm * 64 + mt * 16 + am_) * LDKB2 + (kc + ak_) * 2);
            #pragma unroll
            for (int pr = 0; pr < 2; pr++) {
                uint32_t r4[4];
                ldsm4(r4, bBh + (wn * 32 + pr * 16 + bn_) * LDKB2 + (kc + bk_) * 2);
                bh[2 * pr][0] = r4[0]; bh[2 * pr][1] = r4[1];
                bh[2 * pr + 1][0] = r4[2]; bh[2 * pr + 1][1] = r4[3];
            }
            #pragma unroll
            for (int mt = 0; mt < 4; mt++)
                #pragma unroll
                for (int nt = 0; nt < 4; nt++) mma16816(acc[mt][nt], a[mt], bh[nt]);
            #pragma unroll
            for (int pr = 0; pr < 2; pr++) {
                uint32_t r4[4];
                ldsm4(r4, bBl + (wn * 32 + pr * 16 + bn_) * LDKB2 + (kc + bk_) * 2);
                bl[2 * pr][0] = r4[0]; bl[2 * pr][1] = r4[1];
                bl[2 * pr + 1][0] = r4[2]; bl[2 * pr + 1][1] = r4[3];
            }
            #pragma unroll
            for (int mt = 0; mt < 4; mt++)
                #pragma unroll
                for (int nt = 0; nt < 4; nt++) mma16816(acc[mt][nt], a[mt], bl[nt]);
            #pragma unroll
            for (int mt = 0; mt < 4; mt++)
                ldsm4(a[mt], bAl + (wm * 64 + mt * 16 + am_) * LDKB2 + (kc + ak_) * 2);
            #pragma unroll
            for (int mt = 0; mt < 4; mt++)
                #pragma unroll
                for (int nt = 0; nt < 4; nt++) mma16816(acc[mt][nt], a[mt], bh[nt]);
        }
        __syncthreads();
    }

    float* stage = (float*)smc;
    float* scb = (float*)(smc + 68608);
    float* bob = (float*)(smc + 69632);
    if (tid < 128) {
        const int o = bm * 128 + tid;
        const float s_r = gg[o] * rsqrtf(vv[o] + EPS);
        scb[tid] = s_r;
        bob[tid] = bb[o] - mm[o] * s_r;
    }
    __syncthreads();
    #pragma unroll
    for (int mt = 0; mt < 4; mt++) {
        const int r_lo = wm * 64 + mt * 16 + (lane >> 2);
        #pragma unroll
        for (int nt = 0; nt < 4; nt++) {
            const int c = wn * 32 + nt * 8 + (lane & 3) * 2;
            stage[r_lo * 130 + c]     = fmaxf(acc[mt][nt][0] * scb[r_lo] + bob[r_lo], 0.f);
            stage[r_lo * 130 + c + 1] = fmaxf(acc[mt][nt][1] * scb[r_lo] + bob[r_lo], 0.f);
            stage[(r_lo + 8) * 130 + c]     = fmaxf(acc[mt][nt][2] * scb[r_lo + 8] + bob[r_lo + 8], 0.f);
            stage[(r_lo + 8) * 130 + c + 1] = fmaxf(acc[mt][nt][3] * scb[r_lo + 8] + bob[r_lo + 8], 0.f);
        }
    }
    __syncthreads();
    for (int i = tid; i < 128 * 128; i += 256) {
        const int r = i >> 7;
        const int c = i & 127;
        const size_t go = (size_t)(bm * 128 + r) * NPIX + pixbase + c;
        outp[go] = stage[r * 130 + c] + resid[go];
    }
}

// ==================== attn via mma.sync: A = q(pix rows) x kp^T per patch ====================
// grid (8 rowblocks, 64 patches). 256 threads = 8 warps, each 16 rows x 64 patch-cols.
#define AT_KPH 0
#define AT_KPSTR 528
#define AT_KPL (64 * AT_KPSTR)          // 33792
#define AT_QB  (2 * 64 * AT_KPSTR)      // 67584; two buffers of 2*10240
#define AT_QBSZ (2 * 128 * LDKB2)       // 20480
#define AT_SMEM (AT_QB + 2 * AT_QBSZ)   // 108544
__global__ void __launch_bounds__(256, 2)
attn_mma(const __nv_bfloat16* __restrict__ qhi, const __nv_bfloat16* __restrict__ qlo,
         const __nv_bfloat16* __restrict__ kph, const __nv_bfloat16* __restrict__ kpl,
         __nv_bfloat16* __restrict__ ahi, __nv_bfloat16* __restrict__ alo)
{
    extern __shared__ char smc[];
    const uint32_t sb = smem_to_u32(smc);

    const int rowblk = blockIdx.x;
    const int b = blockIdx.y;
    const int tid = threadIdx.x;
    const int wid = tid >> 5;
    const int lane = tid & 31;
    const int ph = b >> 3, pw = b & 7;
    const int pixbase = ph * 32 * WW + pw * 32;

    // load kp tiles [64][256] hi/lo with row stride 528B
    #pragma unroll
    for (int j = 0; j < 8; j++) {
        const int idx = tid + j * 256;       // 0..2047
        const int r = idx >> 5;
        const int c16 = idx & 31;
        *(uint4*)(smc + AT_KPH + r * AT_KPSTR + c16 * 16) = *(const uint4*)(kph + r * HALF + c16 * 8);
        *(uint4*)(smc + AT_KPL + r * AT_KPSTR + c16 * 16) = *(const uint4*)(kpl + r * HALF + c16 * 8);
    }

    // Q chunk loader indices (512 16B chunks per tensor per chunk, 2 per thread)
    const int qr[2] = { (tid + 0) >> 2, (tid + 256) >> 2 };
    const int qc = tid & 3;
    // pix for each loader row
    int qpix[2];
    #pragma unroll
    for (int j = 0; j < 2; j++) {
        const int n = rowblk * 128 + qr[j];
        qpix[j] = pixbase + (n >> 5) * WW + (n & 31);
    }

    // prologue chunk 0
    {
        const uint32_t qb = sb + AT_QB;
        #pragma unroll
        for (int j = 0; j < 2; j++) {
            const size_t g = (size_t)qpix[j] * HALF + qc * 8;
            cpasync16(qb + qr[j] * LDKB2 + qc * 16, qhi + g);
            cpasync16(qb + 128 * LDKB2 + qr[j] * LDKB2 + qc * 16, qlo + g);
        }
        cpasync_commit();
    }
    __syncthreads();   // kp visible

    const int am_ = lane & 15;
    const int ak_ = (lane >> 4) * 8;
    const int bn_ = (lane & 7) + ((lane >> 4) << 3);
    const int bk_ = ((lane >> 3) & 1) * 8;
    const int grp = lane >> 2;
    const int qd = lane & 3;

    float S[8][4];
    #pragma unroll
    for (int nt = 0; nt < 8; nt++)
        #pragma unroll
        for (int e = 0; e < 4; e++) S[nt][e] = 0.f;

    const int NCH = HALF / 32;   // 8
    for (int ch = 0; ch < NCH; ch++) {
        if (ch + 1 < NCH) {
            const uint32_t qb = sb + AT_QB + ((ch + 1) & 1) * AT_QBSZ;
            const int kc1 = (ch + 1) * 32;
            #pragma unroll
            for (int j = 0; j < 2; j++) {
                const size_t g = (size_t)qpix[j] * HALF + kc1 + qc * 8;
                cpasync16(qb + qr[j] * LDKB2 + qc * 16, qhi + g);
                cpasync16(qb + 128 * LDKB2 + qr[j] * LDKB2 + qc * 16, qlo + g);
            }
            cpasync_commit();
            cpasync_wait<1>();
        } else {
            cpasync_wait<0>();
        }
        __syncthreads();

        const uint32_t qb = sb + AT_QB + (ch & 1) * AT_QBSZ;
        const uint32_t qHI = qb, qLO = qb + 128 * LDKB2;
        #pragma unroll
        for (int ks = 0; ks < 2; ks++) {
            const int kc = ks * 16;
            const int kb = (ch * 32 + kc) * 2;   // byte offset in kp row
            uint32_t a[4], bh[8][2], bl[8][2];
            ldsm4(a, qHI + (wid * 16 + am_) * LDKB2 + (kc + ak_) * 2);
            #pragma unroll
            for (int pr = 0; pr < 4; pr++) {
                uint32_t r4[4];
                ldsm4(r4, sb + AT_KPH + (pr * 16 + bn_) * AT_KPSTR + kb + bk_ * 2);
                bh[2 * pr][0] = r4[0]; bh[2 * pr][1] = r4[1];
                bh[2 * pr + 1][0] = r4[2]; bh[2 * pr + 1][1] = r4[3];
            }
            #pragma unroll
            for (int nt = 0; nt < 8; nt++) mma16816(S[nt], a, bh[nt]);
            #pragma unroll
            for (int pr = 0; pr < 4; pr++) {
                uint32_t r4[4];
                ldsm4(r4, sb + AT_KPL + (pr * 16 + bn_) * AT_KPSTR + kb + bk_ * 2);
                bl[2 * pr][0] = r4[0]; bl[2 * pr][1] = r4[1];
                bl[2 * pr + 1][0] = r4[2]; bl[2 * pr + 1][1] = r4[3];
            }
            #pragma unroll
            for (int nt = 0; nt < 8; nt++) mma16816(S[nt], a, bl[nt]);
            ldsm4(a, qLO + (wid * 16 + am_) * LDKB2 + (kc + ak_) * 2);
            #pragma unroll
            for (int nt = 0; nt < 8; nt++) mma16816(S[nt], a, bh[nt]);
        }
        __syncthreads();
    }

    // store A bf16 hi/lo: [b][n][64]
    const int r1 = wid * 16 + grp;
    #pragma unroll
    for (int nt = 0; nt < 8; nt++) {
        const int col = nt * 8 + qd * 2;
        {
            const int n = rowblk * 128 + r1;
            const size_t off = ((size_t)b * 1024 + n) * 64 + col;
            float v0 = S[nt][0], v1 = S[nt][1];
            __nv_bfloat16 h0 = __float2bfloat16(v0);
            __nv_bfloat16 h1 = __float2bfloat16(v1);
            *(uint32_t*)(ahi + off) = packbf2(v0, v1);
            *(uint32_t*)(alo + off) = packbf2(v0 - __bfloat162float(h0), v1 - __bfloat162float(h1));
        }
        {
            const int n = rowblk * 128 + r1 + 8;
            const size_t off = ((size_t)b * 1024 + n) * 64 + col;
            float v0 = S[nt][2], v1 = S[nt][3];
            __nv_bfloat16 h0 = __float2bfloat16(v0);
            __nv_bfloat16 h1 = __float2bfloat16(v1);
            *(uint32_t*)(ahi + off) = packbf2(v0, v1);
            *(uint32_t*)(alo + off) = packbf2(v0 - __bfloat162float(h0), v1 - __bfloat162float(h1));
        }
    }
}

// ==================== flash v3: mma.sync nested-softmax attention ====================
#define FLDB 144                 // bf16 tile stride bytes
#define F_QHI 0
#define F_QLO 9216
#define F_KB   18432             // K buffers: base + buf*18432; KHI at +0, KLO at +9216
#define F_REDM 55296             // float[64][4]
#define F_REDS 56320             // float[64][4]
#define F_MS   57344             // float[64]
#define F_LS   57600
#define F_SCS  57856
#define F_MNS  58112
#define F_REDF 58368             // float[64][16]
#define F_TOTAL 62464
__global__ void __launch_bounds__(256, 2)
flash3_kernel(const __nv_bfloat16* __restrict__ ahi, const __nv_bfloat16* __restrict__ alo,
              const float* __restrict__ vp,
              __nv_bfloat16* __restrict__ pthi, __nv_bfloat16* __restrict__ ptlo)
{
    extern __shared__ char smc[];
    const uint32_t sb = smem_to_u32(smc);
    float* REDM = (float*)(smc + F_REDM);
    float* REDS = (float*)(smc + F_REDS);
    float* m_s  = (float*)(smc + F_MS);
    float* l_s  = (float*)(smc + F_LS);
    float* sc_s = (float*)(smc + F_SCS);
    float* mn_s = (float*)(smc + F_MNS);
    float* REDF = (float*)(smc + F_REDF);

    const int rblk = blockIdx.x;    // 0..15
    const int b = blockIdx.y;       // patch
    const int tid = threadIdx.x;
    const int lane = tid & 31;
    const int wid = tid >> 5;
    const int wm = wid >> 2;        // 0..1
    const int wn = wid & 3;         // 0..3
    const int r0 = rblk * 64;
    const size_t abase = (size_t)b * 1024 * 64;

    if (tid < 64) { m_s[tid] = -1e30f; l_s[tid] = 0.f; }

    const int kr[2] = { (tid + 0) >> 3, (tid + 256) >> 3 };
    const int kc_ = tid & 7;

    {
        const uint32_t kb = sb + F_KB;
        #pragma unroll
        for (int j = 0; j < 2; j++) {
            const int r = kr[j];
            const size_t g = abase + (size_t)r * 64 + kc_ * 8;
            cpasync16(kb + r * FLDB + kc_ * 16, ahi + g);
            cpasync16(kb + 9216 + r * FLDB + kc_ * 16, alo + g);
        }
        cpasync_commit();
    }

    {
        #pragma unroll
        for (int i = 0; i < 2; i++) {
            const int idx = tid + i * 256;
            const int r = idx >> 3;
            const int c = idx & 7;
            const size_t g = abase + (size_t)(r0 + r) * 64 + c * 8;
            *(uint4*)(smc + F_QHI + r * FLDB + c * 16) = *(const uint4*)(ahi + g);
            *(uint4*)(smc + F_QLO + r * FLDB + c * 16) = *(const uint4*)(alo + g);
        }
    }

    const int am_ = lane & 15;
    const int ak_ = (lane >> 4) * 8;
    const int bn_ = (lane & 7) + ((lane >> 4) << 3);
    const int bk_ = ((lane >> 3) & 1) * 8;
    const int vk_ = lane & 15;
    const int vn_ = (lane >> 4) << 3;
    const int grp = lane >> 2;
    const int qd  = lane & 3;

    float O[2][8][4];
    #pragma unroll
    for (int mt = 0; mt < 2; mt++)
        #pragma unroll
        for (int n8 = 0; n8 < 8; n8++)
            #pragma unroll
            for (int e = 0; e < 4; e++) O[mt][n8][e] = 0.f;

    for (int t = 0; t < 16; t++) {
        __syncthreads();
        if (t > 0 && tid < 64) {
            l_s[tid] = l_s[tid] * sc_s[tid]
                     + REDS[tid * 4 + 0] + REDS[tid * 4 + 1]
                     + REDS[tid * 4 + 2] + REDS[tid * 4 + 3];
        }
        if (t + 1 < 16) {
            const uint32_t kb = sb + F_KB + ((t + 1) & 1) * 18432;
            #pragma unroll
            for (int j = 0; j < 2; j++) {
                const int r = kr[j];
                const size_t g = abase + (size_t)((t + 1) * 64 + r) * 64 + kc_ * 8;
                cpasync16(kb + r * FLDB + kc_ * 16, ahi + g);
                cpasync16(kb + 9216 + r * FLDB + kc_ * 16, alo + g);
            }
            cpasync_commit();
            cpasync_wait<1>();
        } else {
            cpasync_wait<0>();
        }
        __syncthreads();

        const uint32_t kb = sb + F_KB + (t & 1) * 18432;
        const uint32_t kHI = kb, kLO = kb + 9216;

        float S[2][2][4];
        #pragma unroll
        for (int mt = 0; mt < 2; mt++)
            #pragma unroll
            for (int nt = 0; nt < 2; nt++)
                #pragma unroll
                for (int e = 0; e < 4; e++) S[mt][nt][e] = 0.f;
        #pragma unroll
        for (int ks = 0; ks < 4; ks++) {
            const int kc = ks * 16;
            uint32_t a[2][4], bh[2][2], bl[2][2];
            #pragma unroll
            for (int mt = 0; mt < 2; mt++)
                ldsm4(a[mt], sb + F_QHI + (wm * 32 + mt * 16 + am_) * FLDB + (kc + ak_) * 2);
            {
                uint32_t r4[4];
                ldsm4(r4, kHI + (wn * 16 + bn_) * FLDB + (kc + bk_) * 2);
                bh[0][0] = r4[0]; bh[0][1] = r4[1]; bh[1][0] = r4[2]; bh[1][1] = r4[3];
            }
            #pragma unroll
            for (int mt = 0; mt < 2; mt++)
                #pragma unroll
                for (int nt = 0; nt < 2; nt++) mma16816(S[mt][nt], a[mt], bh[nt]);
            {
                uint32_t r4[4];
                ldsm4(r4, kLO + (wn * 16 + bn_) * FLDB + (kc + bk_) * 2);
                bl[0][0] = r4[0]; bl[0][1] = r4[1]; bl[1][0] = r4[2]; bl[1][1] = r4[3];
            }
            #pragma unroll
            for (int mt = 0; mt < 2; mt++)
                #pragma unroll
                for (int nt = 0; nt < 2; nt++) mma16816(S[mt][nt], a[mt], bl[nt]);
            #pragma unroll
            for (int mt = 0; mt < 2; mt++)
                ldsm4(a[mt], sb + F_QLO + (wm * 32 + mt * 16 + am_) * FLDB + (kc + ak_) * 2);
            #pragma unroll
            for (int mt = 0; mt < 2; mt++)
                #pragma unroll
                for (int nt = 0; nt < 2; nt++) mma16816(S[mt][nt], a[mt], bh[nt]);
        }

        #pragma unroll
        for (int mt = 0; mt < 2; mt++) {
            float la = fmaxf(fmaxf(S[mt][0][0], S[mt][0][1]), fmaxf(S[mt][1][0], S[mt][1][1]));
            float lb = fmaxf(fmaxf(S[mt][0][2], S[mt][0][3]), fmaxf(S[mt][1][2], S[mt][1][3]));
            la = fmaxf(la, __shfl_xor_sync(0xffffffffu, la, 1));
            la = fmaxf(la, __shfl_xor_sync(0xffffffffu, la, 2));
            lb = fmaxf(lb, __shfl_xor_sync(0xffffffffu, lb, 1));
            lb = fmaxf(lb, __shfl_xor_sync(0xffffffffu, lb, 2));
            if (qd == 0) {
                const int r1 = wm * 32 + mt * 16 + grp;
                REDM[r1 * 4 + wn] = la;
                REDM[(r1 + 8) * 4 + wn] = lb;
            }
        }
        __syncthreads();
        if (tid < 64) {
            float mt_ = fmaxf(fmaxf(REDM[tid * 4], REDM[tid * 4 + 1]),
                              fmaxf(REDM[tid * 4 + 2], REDM[tid * 4 + 3]));
            const float mo = m_s[tid];
            const float mn = fmaxf(mo, mt_);
            sc_s[tid] = __expf(mo - mn);
            mn_s[tid] = mn;
            m_s[tid] = mn;
        }
        __syncthreads();

        uint32_t aPh[2][4], aPl[2][4];
        #pragma unroll
        for (int mt = 0; mt < 2; mt++) {
            const int r1 = wm * 32 + mt * 16 + grp;
            const float mna = mn_s[r1];
            const float mnb = mn_s[r1 + 8];
            float P[2][4];
            #pragma unroll
            for (int nt = 0; nt < 2; nt++) {
                P[nt][0] = __expf(S[mt][nt][0] - mna);
                P[nt][1] = __expf(S[mt][nt][1] - mna);
                P[nt][2] = __expf(S[mt][nt][2] - mnb);
                P[nt][3] = __expf(S[mt][nt][3] - mnb);
            }
            float ra = P[0][0] + P[0][1] + P[1][0] + P[1][1];
            float rb = P[0][2] + P[0][3] + P[1][2] + P[1][3];
            ra += __shfl_xor_sync(0xffffffffu, ra, 1);
            ra += __shfl_xor_sync(0xffffffffu, ra, 2);
            rb += __shfl_xor_sync(0xffffffffu, rb, 1);
            rb += __shfl_xor_sync(0xffffffffu, rb, 2);
            if (qd == 0) {
                REDS[r1 * 4 + wn] = ra;
                REDS[(r1 + 8) * 4 + wn] = rb;
            }
            aPh[mt][0] = packbf2(P[0][0], P[0][1]);
            aPh[mt][1] = packbf2(P[0][2], P[0][3]);
            aPh[mt][2] = packbf2(P[1][0], P[1][1]);
            aPh[mt][3] = packbf2(P[1][2], P[1][3]);
            float l00 = P[0][0] - __bfloat162float(__float2bfloat16(P[0][0]));
            float l01 = P[0][1] - __bfloat162float(__float2bfloat16(P[0][1]));
            float l02 = P[0][2] - __bfloat162float(__float2bfloat16(P[0][2]));
            float l03 = P[0][3] - __bfloat162float(__float2bfloat16(P[0][3]));
            float l10 = P[1][0] - __bfloat162float(__float2bfloat16(P[1][0]));
            float l11 = P[1][1] - __bfloat162float(__float2bfloat16(P[1][1]));
            float l12 = P[1][2] - __bfloat162float(__float2bfloat16(P[1][2]));
            float l13 = P[1][3] - __bfloat162float(__float2bfloat16(P[1][3]));
            aPl[mt][0] = packbf2(l00, l01);
            aPl[mt][1] = packbf2(l02, l03);
            aPl[mt][2] = packbf2(l10, l11);
            aPl[mt][3] = packbf2(l12, l13);
            const float sa = sc_s[r1];
            const float sbx = sc_s[r1 + 8];
            #pragma unroll
            for (int n8 = 0; n8 < 8; n8++) {
                O[mt][n8][0] *= sa; O[mt][n8][1] *= sa;
                O[mt][n8][2] *= sbx; O[mt][n8][3] *= sbx;
            }
        }

        #pragma unroll
        for (int g = 0; g < 4; g++) {
            const int n0 = g * 16;
            uint32_t vh[4], vl[4];
            ldsm4t(vh, kHI + (wn * 16 + vk_) * FLDB + (n0 + vn_) * 2);
            ldsm4t(vl, kLO + (wn * 16 + vk_) * FLDB + (n0 + vn_) * 2);
            uint32_t b0h[2] = { vh[0], vh[1] }, b1h[2] = { vh[2], vh[3] };
            uint32_t b0l[2] = { vl[0], vl[1] }, b1l[2] = { vl[2], vl[3] };
            #pragma unroll
            for (int mt = 0; mt < 2; mt++) {
                mma16816(O[mt][2 * g + 0], aPh[mt], b0h);
                mma16816(O[mt][2 * g + 1], aPh[mt], b1h);
                mma16816(O[mt][2 * g + 0], aPh[mt], b0l);
                mma16816(O[mt][2 * g + 1], aPh[mt], b1l);
                mma16816(O[mt][2 * g + 0], aPl[mt], b0h);
                mma16816(O[mt][2 * g + 1], aPl[mt], b1h);
            }
        }
    }
    __syncthreads();
    if (tid < 64) {
        l_s[tid] = l_s[tid] * sc_s[tid]
                 + REDS[tid * 4 + 0] + REDS[tid * 4 + 1]
                 + REDS[tid * 4 + 2] + REDS[tid * 4 + 3];
    }

    float* Os = (float*)(smc + 0);          // [64][66]
    for (int i = tid; i < 64 * 66; i += 256) Os[i] = 0.f;
    __syncthreads();
    #pragma unroll 1
    for (int p = 0; p < 4; p++) {
        if (wn == p) {
            #pragma unroll
            for (int mt = 0; mt < 2; mt++) {
                const int r1 = wm * 32 + mt * 16 + grp;
                #pragma unroll
                for (int n8 = 0; n8 < 8; n8++) {
                    const int c = n8 * 8 + qd * 2;
                    Os[r1 * 66 + c]       += O[mt][n8][0];
                    Os[r1 * 66 + c + 1]   += O[mt][n8][1];
                    Os[(r1 + 8) * 66 + c]     += O[mt][n8][2];
                    Os[(r1 + 8) * 66 + c + 1] += O[mt][n8][3];
                }
            }
        }
        __syncthreads();
    }

    const int txx = tid & 15;
    const int tyy = tid >> 4;
    float fv[4][4];
    #pragma unroll
    for (int i = 0; i < 4; i++) {
        const int rr = tyy * 4 + i;
        const float linv = 1.f / l_s[rr];
        const size_t goff = abase + (size_t)(r0 + rr) * 64 + txx * 4;
        uint2 uh = *(const uint2*)(ahi + goff);
        uint2 ul = *(const uint2*)(alo + goff);
        __nv_bfloat162 h0 = *(__nv_bfloat162*)&uh.x;
        __nv_bfloat162 h1 = *(__nv_bfloat162*)&uh.y;
        __nv_bfloat162 l0 = *(__nv_bfloat162*)&ul.x;
        __nv_bfloat162 l1 = *(__nv_bfloat162*)&ul.y;
        fv[i][0] = __bfloat162float(h0.x) + __bfloat162float(l0.x) + Os[rr * 66 + txx * 4 + 0] * linv;
        fv[i][1] = __bfloat162float(h0.y) + __bfloat162float(l0.y) + Os[rr * 66 + txx * 4 + 1] * linv;
        fv[i][2] = __bfloat162float(h1.x) + __bfloat162float(l1.x) + Os[rr * 66 + txx * 4 + 2] * linv;
        fv[i][3] = __bfloat162float(h1.y) + __bfloat162float(l1.y) + Os[rr * 66 + txx * 4 + 3] * linv;
    }
    #pragma unroll
    for (int i = 0; i < 4; i++) {
        float lm = fmaxf(fmaxf(fv[i][0], fv[i][1]), fmaxf(fv[i][2], fv[i][3]));
        REDF[(tyy * 4 + i) * 16 + txx] = lm;
    }
    __syncthreads();
    if (tid < 64) {
        float mt_ = REDF[tid * 16];
        #pragma unroll
        for (int j = 1; j < 16; j++) mt_ = fmaxf(mt_, REDF[tid * 16 + j]);
        mn_s[tid] = mt_;
    }
    __syncthreads();
    #pragma unroll
    for (int i = 0; i < 4; i++) {
        const int rr = tyy * 4 + i;
        const float mn = mn_s[rr];
        float rs = 0.f;
        #pragma unroll
        for (int j = 0; j < 4; j++) { fv[i][j] = __expf(fv[i][j] - mn); rs += fv[i][j]; }
        REDF[rr * 16 + txx] = rs;
    }
    __syncthreads();
    if (tid < 64) {
        float su = REDF[tid * 16];
        #pragma unroll
        for (int j = 1; j < 16; j++) su += REDF[tid * 16 + j];
        l_s[tid] = 1.f / su;
    }
    __syncthreads();
    float* Ps = (float*)(smc + F_KB);       // [64][68] overlay on K buf0
    #pragma unroll
    for (int i = 0; i < 4; i++) {
        const int rr = tyy * 4 + i;
        const float inv = l_s[rr];
        *(float4*)&Ps[rr * 68 + txx * 4] =
            make_float4(fv[i][0] * inv, fv[i][1] * inv, fv[i][2] * inv, fv[i][3] * inv);
    }
    __syncthreads();

    float acc[4][16];
    #pragma unroll
    for (int i = 0; i < 4; i++)
        #pragma unroll
        for (int j = 0; j < 16; j++) acc[i][j] = 0.f;
    #pragma unroll 2
    for (int m = 0; m < 64; m++) {
        float pr[4];
        #pragma unroll
        for (int i = 0; i < 4; i++) pr[i] = Ps[(tyy * 4 + i) * 68 + m];
        const float4* vr = (const float4*)(vp + m * 256 + txx * 16);
        float4 v0 = vr[0], v1 = vr[1], v2 = vr[2], v3 = vr[3];
        const float vw[16] = {v0.x, v0.y, v0.z, v0.w, v1.x, v1.y, v1.z, v1.w,
                              v2.x, v2.y, v2.z, v2.w, v3.x, v3.y, v3.z, v3.w};
        #pragma unroll
        for (int i = 0; i < 4; i++)
            #pragma unroll
            for (int j = 0; j < 16; j++) acc[i][j] += pr[i] * vw[j];
    }

    const int ph = b >> 3, pw = b & 7;
    const int pixbase = ph * 32 * WW + pw * 32;
    float* stg = (float*)(smc + 0);
    #pragma unroll 1
    for (int g = 0; g < 4; g++) {
        __syncthreads();
        if ((txx >> 2) == g) {
            const int txl = txx & 3;
            #pragma unroll
            for (int i = 0; i < 4; i++)
                #pragma unroll
                for (int j = 0; j < 16; j++)
                    stg[(tyy * 4 + i) * 65 + txl * 16 + j] = acc[i][j];
        }
        __syncthreads();
        const int rl = tid >> 2;
        const int cc0 = (tid & 3) * 16;
        const int n = r0 + rl;
        const int pix = pixbase + (n >> 5) * WW + (n & 31);
        #pragma unroll
        for (int k2 = 0; k2 < 16; k2++) {
            float v = stg[rl * 65 + cc0 + k2];
            __nv_bfloat16 h = __float2bfloat16(v);
            const size_t off = (size_t)pix * HALF + g * 64 + cc0 + k2;
            pthi[off] = h;
            ptlo[off] = __float2bfloat16(v - __bfloat162float(h));
        }
    }
}

// ==================== launch ====================
extern "C" void kernel_launch(void* const* d_in, const int* in_sizes, int n_in,
                              void* d_out, int out_size)
{
    const float* x   = (const float*)d_in[0];
    const float* q_w = (const float*)d_in[1];
    const float* q_g = (const float*)d_in[2];
    const float* q_b = (const float*)d_in[3];
    const float* q_m = (const float*)d_in[4];
    const float* q_v = (const float*)d_in[5];
    const float* k_w = (const float*)d_in[6];
    const float* k_g = (const float*)d_in[7];
    const float* k_b = (const float*)d_in[8];
    const float* k_m = (const float*)d_in[9];
    const float* k_v = (const float*)d_in[10];
    const float* v_w = (const float*)d_in[11];
    const float* v_g = (const float*)d_in[12];
    const float* v_b = (const float*)d_in[13];
    const float* v_m = (const float*)d_in[14];
    const float* v_v = (const float*)d_in[15];
    const float* o_w = (const float*)d_in[16];
    const float* o_g = (const float*)d_in[17];
    const float* o_b = (const float*)d_in[18];
    const float* o_m = (const float*)d_in[19];
    const float* o_v = (const float*)d_in[20];
    float* out = (float*)d_out;

    __nv_bfloat16 *xthi, *xtlo, *qthi, *qtlo, *pthi, *ptlo, *ahi, *alo, *kpbh, *kpbl;
    __nv_bfloat16 (*whi)[CIN * HALF], (*wlo)[CIN * HALF];
    float *gkp, *gvp;
    cudaGetSymbolAddress((void**)&xthi, g_xthi);
    cudaGetSymbolAddress((void**)&xtlo, g_xtlo);
    cudaGetSymbolAddress((void**)&qthi, g_qthi);
    cudaGetSymbolAddress((void**)&qtlo, g_qtlo);
    cudaGetSymbolAddress((void**)&pthi, g_pthi);
    cudaGetSymbolAddress((void**)&ptlo, g_ptlo);
    cudaGetSymbolAddress((void**)&ahi, g_ahi);
    cudaGetSymbolAddress((void**)&alo, g_alo);
    cudaGetSymbolAddress((void**)&kpbh, g_kpbh);
    cudaGetSymbolAddress((void**)&kpbl, g_kpbl);
    cudaGetSymbolAddress((void**)&whi, g_whi);
    cudaGetSymbolAddress((void**)&wlo, g_wlo);
    cudaGetSymbolAddress((void**)&gkp, g_kp);
    cudaGetSymbolAddress((void**)&gvp, g_vp);

    const float qscale = 0.044194173824159216f;   // 512^-0.5

    // conversions
    conv_w4_kernel<<<dim3(512, 4), 256>>>(q_w, k_w, v_w, o_w, (__nv_bfloat16*)whi, (__nv_bfloat16*)wlo);
    conv_x_kernel<<<dim3(NPIX / 32, CIN / 32), dim3(32, 8)>>>(x, xthi, xtlo);
    zero_pool_kernel<<<64, 256>>>(gkp, gvp);

    // fused q/k/v projections
    QKVParams p;
    p.whi[0] = whi[0]; p.whi[1] = whi[1]; p.whi[2] = whi[2];
    p.wlo[0] = wlo[0]; p.wlo[1] = wlo[1]; p.wlo[2] = wlo[2];
    p.gg[0] = q_g; p.gg[1] = k_g; p.gg[2] = v_g;
    p.bb[0] = q_b; p.bb[1] = k_b; p.bb[2] = v_b;
    p.mm[0] = q_m; p.mm[1] = k_m; p.mm[2] = v_m;
    p.vv[0] = q_v; p.vv[1] = k_v; p.vv[2] = v_v;

    cudaFuncSetAttribute(proj_qkv, cudaFuncAttributeMaxDynamicSharedMemorySize, PROJ_SMEM);
    proj_qkv<<<dim3(NPIX / 128, 6), 256, PROJ_SMEM>>>(
        p, xthi, xtlo, qthi, qtlo, gkp, gvp, qscale);

    // kp -> bf16 [patch][c]
    kconv_kernel<<<64, 256>>>(gkp, kpbh, kpbl);

    // attn via mma.sync
    cudaFuncSetAttribute(attn_mma, cudaFuncAttributeMaxDynamicSharedMemorySize, AT_SMEM);
    attn_mma<<<dim3(8, NUM), 256, AT_SMEM>>>(qthi, qtlo, kpbh, kpbl, ahi, alo);

    // flash v3
    cudaFuncSetAttribute(flash3_kernel, cudaFuncAttributeMaxDynamicSharedMemorySize, F_TOTAL);
    flash3_kernel<<<dim3(16, NUM), 256, F_TOTAL>>>(ahi, alo, gvp, pthi, ptlo);

    // o projection + residual -> d_out
    cudaFuncSetAttribute(proj_o<HALF>, cudaFuncAttributeMaxDynamicSharedMemorySize, PROJ_SMEM);
    proj_o<HALF><<<dim3(NPIX / 128, CIN / 128), 256, PROJ_SMEM>>>(
        whi[3], wlo[3], pthi, ptlo, o_g, o_b, o_m, o_v, out, x);
}